// round 8
// baseline (speedup 1.0000x reference)
#include <cuda_runtime.h>
#include <math.h>
#include <stdint.h>

#define CDIV(a,b) (((a)+(b)-1)/(b))

static const int B  = 32;
static const int C  = 256;
static const int NZ = 225;   // 15*15
static const int NX = 961;   // 31*31
static const int KDIM = 2304; // C*9

// ---------------- scratch (device globals; no cudaMalloc allowed) ----------
__device__ float g_attnA[32 * 256 * 256];
__device__ float g_attnB[32 * 256 * 256];
__device__ float g_featZ[32 * 256 * 225];
__device__ float g_featX[32 * 256 * 961];
__device__ float g_off  [32 * 18  * 961];
__device__ float g_col  [2304 * 32 * 1024];   // padded im2col (302 MB)
__device__ float g_wr   [256 * 2304];         // tf32-rounded weights
__device__ float g_hi   [32 * 256 * 976];     // tf32 split hi, K padded
__device__ float g_lo   [32 * 256 * 976];     // tf32 split lo, K padded

// ======================= PTX helpers =======================================
__device__ __forceinline__ uint32_t smem_u32(const void* p) {
    uint32_t a;
    asm("{ .reg .u64 t; cvta.to.shared.u64 t, %1; cvt.u32.u64 %0, t; }" : "=r"(a) : "l"(p));
    return a;
}
__device__ __forceinline__ void cpa16(uint32_t dst, const void* src) {
    asm volatile("cp.async.cg.shared.global [%0], [%1], 16;" :: "r"(dst), "l"(src));
}
__device__ __forceinline__ float round_tf32(float v) {
    uint32_t r;
    asm("cvt.rna.tf32.f32 %0, %1;" : "=r"(r) : "f"(v));
    return __uint_as_float(r);
}
__device__ __forceinline__ void mma_tf32(float& c0, float& c1, float& c2, float& c3,
                                         uint32_t a0, uint32_t a1, uint32_t a2, uint32_t a3,
                                         uint32_t b0, uint32_t b1) {
    asm volatile(
        "mma.sync.aligned.m16n8k8.row.col.f32.tf32.tf32.f32 "
        "{%0,%1,%2,%3},{%4,%5,%6,%7},{%8,%9},{%0,%1,%2,%3};"
        : "+f"(c0), "+f"(c1), "+f"(c2), "+f"(c3)
        : "r"(a0), "r"(a1), "r"(a2), "r"(a3), "r"(b0), "r"(b1));
}

// ---------------------------------------------------------------------------
// split input into tf32 hi/lo pair, K padded to Kpad with zeros
// ---------------------------------------------------------------------------
__global__ __launch_bounds__(256) void splitf_kernel(const float* __restrict__ in,
                                                     float* __restrict__ hi,
                                                     float* __restrict__ lo,
                                                     int K, int Kpad, int total) {
    int i = blockIdx.x * 256 + threadIdx.x;
    if (i >= total) return;
    int bc = i / Kpad, k = i - bc * Kpad;
    float v = (k < K) ? in[(size_t)bc * K + k] : 0.f;
    float h = round_tf32(v);
    hi[i] = h;
    lo[i] = round_tf32(v - h);
}

// ---------------------------------------------------------------------------
// gram via 3xTF32: E[b] = F[b] * F[b]^T, K pre-padded (mult of 8)
// CTA 128x128, BK=8, cp.async double-buffered, 8 warps (2M x 4N)
// ---------------------------------------------------------------------------
__global__ __launch_bounds__(256) void gram_mma3_kernel(const float* __restrict__ hi,
                                                        const float* __restrict__ lo,
                                                        float* __restrict__ E, int Kpad) {
    __shared__ float Ah[2][1536], Al[2][1536], Bh[2][1536], Bl[2][1536];
    int b = blockIdx.z;
    int c0 = blockIdx.y * 128, d0 = blockIdx.x * 128;
    const size_t fb = (size_t)b * C * Kpad;
    int tid = threadIdx.x;
    int wid = tid >> 5, lane = tid & 31;
    int g = lane >> 2, t = lane & 3;
    int warpM = wid >> 2, warpN = wid & 3;

    uint32_t ahU = smem_u32(&Ah[0][0]);
    uint32_t alU = smem_u32(&Al[0][0]);
    uint32_t bhU = smem_u32(&Bh[0][0]);
    uint32_t blU = smem_u32(&Bl[0][0]);

    int lrow = tid >> 1, lhalf = tid & 1;
    auto load_stage = [&](int stg, int k0) {
        uint32_t doff = stg * 6144 + (lrow * 12 + lhalf * 4) * 4;
        const size_t sA = fb + (size_t)(c0 + lrow) * Kpad + k0 + lhalf * 4;
        const size_t sB = fb + (size_t)(d0 + lrow) * Kpad + k0 + lhalf * 4;
        cpa16(ahU + doff, hi + sA);
        cpa16(alU + doff, lo + sA);
        cpa16(bhU + doff, hi + sB);
        cpa16(blU + doff, lo + sB);
    };

    float acc[4][4][4];
#pragma unroll
    for (int i = 0; i < 4; i++)
#pragma unroll
        for (int j = 0; j < 4; j++)
#pragma unroll
            for (int r = 0; r < 4; r++) acc[i][j][r] = 0.f;

    const int ITERS = Kpad / 8;
    load_stage(0, 0);
    asm volatile("cp.async.commit_group;" ::: "memory");

    for (int it = 0; it < ITERS; it++) {
        int cur = it & 1;
        if (it + 1 < ITERS) load_stage(cur ^ 1, (it + 1) * 8);
        asm volatile("cp.async.commit_group;" ::: "memory");
        asm volatile("cp.async.wait_group 1;" ::: "memory");
        __syncthreads();

        const float* A0h = &Ah[cur][0];
        const float* A0l = &Al[cur][0];
        const float* B0h = &Bh[cur][0];
        const float* B0l = &Bl[cur][0];

        uint32_t ah[4][4], al[4][4];
#pragma unroll
        for (int mt = 0; mt < 4; mt++) {
            int m = warpM * 64 + mt * 16 + g;
            ah[mt][0] = __float_as_uint(A0h[m * 12 + t]);
            ah[mt][1] = __float_as_uint(A0h[(m + 8) * 12 + t]);
            ah[mt][2] = __float_as_uint(A0h[m * 12 + t + 4]);
            ah[mt][3] = __float_as_uint(A0h[(m + 8) * 12 + t + 4]);
            al[mt][0] = __float_as_uint(A0l[m * 12 + t]);
            al[mt][1] = __float_as_uint(A0l[(m + 8) * 12 + t]);
            al[mt][2] = __float_as_uint(A0l[m * 12 + t + 4]);
            al[mt][3] = __float_as_uint(A0l[(m + 8) * 12 + t + 4]);
        }
        uint32_t bh[4][2], bl[4][2];
#pragma unroll
        for (int nt = 0; nt < 4; nt++) {
            int n = warpN * 32 + nt * 8 + g;
            bh[nt][0] = __float_as_uint(B0h[n * 12 + t]);
            bh[nt][1] = __float_as_uint(B0h[n * 12 + t + 4]);
            bl[nt][0] = __float_as_uint(B0l[n * 12 + t]);
            bl[nt][1] = __float_as_uint(B0l[n * 12 + t + 4]);
        }
#pragma unroll
        for (int mt = 0; mt < 4; mt++)
#pragma unroll
            for (int nt = 0; nt < 4; nt++) {
                mma_tf32(acc[mt][nt][0], acc[mt][nt][1], acc[mt][nt][2], acc[mt][nt][3],
                         ah[mt][0], ah[mt][1], ah[mt][2], ah[mt][3],
                         bh[nt][0], bh[nt][1]);
                mma_tf32(acc[mt][nt][0], acc[mt][nt][1], acc[mt][nt][2], acc[mt][nt][3],
                         ah[mt][0], ah[mt][1], ah[mt][2], ah[mt][3],
                         bl[nt][0], bl[nt][1]);
                mma_tf32(acc[mt][nt][0], acc[mt][nt][1], acc[mt][nt][2], acc[mt][nt][3],
                         al[mt][0], al[mt][1], al[mt][2], al[mt][3],
                         bh[nt][0], bh[nt][1]);
            }
        __syncthreads();
    }

    float* Eb = E + (size_t)b * C * C;
#pragma unroll
    for (int mt = 0; mt < 4; mt++) {
        int m = c0 + warpM * 64 + mt * 16 + g;
#pragma unroll
        for (int nt = 0; nt < 4; nt++) {
            int n = d0 + warpN * 32 + nt * 8 + t * 2;
            Eb[(size_t)m * C + n]           = acc[mt][nt][0];
            Eb[(size_t)m * C + n + 1]       = acc[mt][nt][1];
            Eb[(size_t)(m + 8) * C + n]     = acc[mt][nt][2];
            Eb[(size_t)(m + 8) * C + n + 1] = acc[mt][nt][3];
        }
    }
}

// ---------------------------------------------------------------------------
// softmax of (rowmax - e) == exp(rowmin - e)/sum  (shuffle reductions)
// ---------------------------------------------------------------------------
__global__ __launch_bounds__(256) void attn_softmax_kernel(float* __restrict__ E) {
    int row = blockIdx.x;
    float* e = E + (size_t)row * 256;
    int t = threadIdx.x;
    int warp = t >> 5, lane = t & 31;
    __shared__ float sm[16];
    float v = e[t];
    float m = v;
#pragma unroll
    for (int s = 16; s > 0; s >>= 1) m = fminf(m, __shfl_xor_sync(0xffffffffu, m, s));
    if (lane == 0) sm[warp] = m;
    __syncthreads();
    float emin = fminf(fminf(fminf(sm[0], sm[1]), fminf(sm[2], sm[3])),
                       fminf(fminf(sm[4], sm[5]), fminf(sm[6], sm[7])));
    float p = expf(emin - v);
    float sum = p;
#pragma unroll
    for (int s = 16; s > 0; s >>= 1) sum += __shfl_xor_sync(0xffffffffu, sum, s);
    if (lane == 0) sm[8 + warp] = sum;
    __syncthreads();
    float tot = (sm[8] + sm[9]) + (sm[10] + sm[11]) + (sm[12] + sm[13]) + (sm[14] + sm[15]);
    e[t] = p / tot;
}

// ---------------------------------------------------------------------------
// cam_use via tf32 MMA: O[b] = gamma * A[b] @ F[b] + F[b]
// CTA 128x128, BK=8, A via cp.async double-buffer, B via guarded LDG+STS
// ---------------------------------------------------------------------------
__global__ __launch_bounds__(256) void camuse_mma_kernel(const float* __restrict__ A,
                                                         const float* __restrict__ F,
                                                         float* __restrict__ O, int N,
                                                         const float* __restrict__ gamma) {
    __shared__ float sA[2][1536];    // 128 x 8 (stride 12)
    __shared__ float sB[2][1088];    // 8 x 128 (stride 136)
    int b = blockIdx.z;
    int m0 = blockIdx.y * 128, n0 = blockIdx.x * 128;
    const float* Ab = A + (size_t)b * C * C;
    const float* Fb = F + (size_t)b * C * N;
    int tid = threadIdx.x;
    int wid = tid >> 5, lane = tid & 31;
    int g = lane >> 2, t = lane & 3;
    int warpM = wid >> 2, warpN = wid & 3;

    uint32_t sAu = smem_u32(&sA[0][0]);
    int lrow = tid >> 1, lhalf = tid & 1;

    auto load_stage = [&](int stg, int k0) {
        cpa16(sAu + stg * 6144 + (lrow * 12 + lhalf * 4) * 4,
              Ab + (size_t)(m0 + lrow) * C + k0 + lhalf * 4);
#pragma unroll
        for (int i = 0; i < 4; i++) {
            int idx = tid + i * 256;
            int r = idx >> 7, cc = idx & 127;
            int n = n0 + cc;
            sB[stg][r * 136 + cc] = (n < N) ? round_tf32(Fb[(size_t)(k0 + r) * N + n]) : 0.f;
        }
    };

    float acc[4][4][4];
#pragma unroll
    for (int i = 0; i < 4; i++)
#pragma unroll
        for (int j = 0; j < 4; j++)
#pragma unroll
            for (int r = 0; r < 4; r++) acc[i][j][r] = 0.f;

    const int ITERS = C / 8;   // 32
    load_stage(0, 0);
    asm volatile("cp.async.commit_group;" ::: "memory");

    for (int it = 0; it < ITERS; it++) {
        int cur = it & 1;
        if (it + 1 < ITERS) load_stage(cur ^ 1, (it + 1) * 8);
        asm volatile("cp.async.commit_group;" ::: "memory");
        asm volatile("cp.async.wait_group 1;" ::: "memory");
        __syncthreads();

        const float* A0 = &sA[cur][0];
        const float* B0 = &sB[cur][0];
        uint32_t af[4][4];
#pragma unroll
        for (int mt = 0; mt < 4; mt++) {
            int m = warpM * 64 + mt * 16 + g;
            af[mt][0] = __float_as_uint(A0[m * 12 + t]);
            af[mt][1] = __float_as_uint(A0[(m + 8) * 12 + t]);
            af[mt][2] = __float_as_uint(A0[m * 12 + t + 4]);
            af[mt][3] = __float_as_uint(A0[(m + 8) * 12 + t + 4]);
        }
        uint32_t bf[4][2];
#pragma unroll
        for (int nt = 0; nt < 4; nt++) {
            int n = warpN * 32 + nt * 8 + g;
            bf[nt][0] = __float_as_uint(B0[t * 136 + n]);
            bf[nt][1] = __float_as_uint(B0[(t + 4) * 136 + n]);
        }
#pragma unroll
        for (int mt = 0; mt < 4; mt++)
#pragma unroll
            for (int nt = 0; nt < 4; nt++)
                mma_tf32(acc[mt][nt][0], acc[mt][nt][1], acc[mt][nt][2], acc[mt][nt][3],
                         af[mt][0], af[mt][1], af[mt][2], af[mt][3],
                         bf[nt][0], bf[nt][1]);
        __syncthreads();
    }

    float gm = gamma[0];
#pragma unroll
    for (int mt = 0; mt < 4; mt++) {
        int m = m0 + warpM * 64 + mt * 16 + g;
#pragma unroll
        for (int nt = 0; nt < 4; nt++) {
            int n = n0 + warpN * 32 + nt * 8 + t * 2;
            if (n < N) {
                O[((size_t)b * C + m) * N + n] = gm * acc[mt][nt][0] + Fb[(size_t)m * N + n];
                O[((size_t)b * C + m + 8) * N + n] = gm * acc[mt][nt][2] + Fb[(size_t)(m + 8) * N + n];
                if (n + 1 < N) {
                    O[((size_t)b * C + m) * N + n + 1] = gm * acc[mt][nt][1] + Fb[(size_t)m * N + n + 1];
                    O[((size_t)b * C + m + 8) * N + n + 1] = gm * acc[mt][nt][3] + Fb[(size_t)(m + 8) * N + n + 1];
                }
            }
        }
    }
}

// ---------------------------------------------------------------------------
// offset conv: 3x3, C -> 18, pad 1.  3 channels per block.
// grid (ntile, 6, B), 128 threads
// ---------------------------------------------------------------------------
__global__ __launch_bounds__(128) void offconv3_kernel(const float* __restrict__ feat,
                                                       const float* __restrict__ woff,
                                                       const float* __restrict__ boff,
                                                       float* __restrict__ off,
                                                       int H, int W) {
    __shared__ float sw[3 * 2304];
    int chb = blockIdx.y * 3, b = blockIdx.z;
    for (int i = threadIdx.x; i < 3 * 2304; i += 128) {
        int j = i / 2304, r = i - j * 2304;
        sw[i] = woff[(size_t)(chb + j) * 2304 + r];
    }
    __syncthreads();
    int N = H * W;
    int n = blockIdx.x * 128 + threadIdx.x;
    if (n >= N) return;
    int h = n / W, w = n % W;
    const float* fb = feat + (size_t)b * C * N;
    float a0 = 0.f, a1 = 0.f, a2 = 0.f;
    for (int c = 0; c < C; c++) {
        const float* fc = fb + (size_t)c * N;
        const float* w0 = sw + c * 9;
#pragma unroll
        for (int ky = 0; ky < 3; ky++) {
            int y = h + ky - 1;
            if ((unsigned)y >= (unsigned)H) continue;
            const float* fr = fc + y * W;
#pragma unroll
            for (int kx = 0; kx < 3; kx++) {
                int x = w + kx - 1;
                if ((unsigned)x < (unsigned)W) {
                    float f = fr[x];
                    int tap = ky * 3 + kx;
                    a0 += w0[tap] * f;
                    a1 += w0[2304 + tap] * f;
                    a2 += w0[4608 + tap] * f;
                }
            }
        }
    }
    off[((size_t)b * 18 + chb + 0) * N + n] = a0 + boff[chb + 0];
    off[((size_t)b * 18 + chb + 1) * N + n] = a1 + boff[chb + 1];
    off[((size_t)b * 18 + chb + 2) * N + n] = a2 + boff[chb + 2];
}

// ---------------------------------------------------------------------------
// bilinear deform sampling -> padded im2col, 4 pixels/thread, float4 stores
// col[(c*9+k)][b*Npad + n]
// ---------------------------------------------------------------------------
__global__ __launch_bounds__(128) void sample4_kernel(const float* __restrict__ feat,
                                                      const float* __restrict__ off,
                                                      float* __restrict__ col,
                                                      int H, int W, int Npad, int NtotPad) {
    int N = H * W;
    int b = blockIdx.z, k = blockIdx.y;
    int n0 = (blockIdx.x * 128 + threadIdx.x) * 4;
    if (n0 >= N) return;
    int vn = N - n0; if (vn > 4) vn = 4;
    int ky = k / 3, kx = k % 3;

    float w00[4], w01[4], w10[4], w11[4];
    int i00[4], i01[4], i10[4], i11[4];
    const float* offy = off + ((size_t)b * 18 + 2 * k) * N;
    const float* offx = off + ((size_t)b * 18 + 2 * k + 1) * N;
    float Hm1 = (float)(H - 1), Wm1 = (float)(W - 1);
#pragma unroll
    for (int j = 0; j < 4; j++) {
        int n = n0 + j;
        int nn = (j < vn) ? n : n0;
        int h = nn / W, w = nn % W;
        float py = (float)(h + ky - 1) + offy[nn];
        float px = (float)(w + kx - 1) + offx[nn];
        float y0f = floorf(py), x0f = floorf(px);
        float ly = py - y0f, lx = px - x0f;
        float vy0 = (y0f >= 0.f && y0f <= Hm1) ? (1.f - ly) : 0.f;
        float vy1 = (y0f + 1.f >= 0.f && y0f + 1.f <= Hm1) ? ly : 0.f;
        float vx0 = (x0f >= 0.f && x0f <= Wm1) ? (1.f - lx) : 0.f;
        float vx1 = (x0f + 1.f >= 0.f && x0f + 1.f <= Wm1) ? lx : 0.f;
        int y0 = (int)fminf(fmaxf(y0f, 0.f), Hm1);
        int y1 = (int)fminf(fmaxf(y0f + 1.f, 0.f), Hm1);
        int x0 = (int)fminf(fmaxf(x0f, 0.f), Wm1);
        int x1 = (int)fminf(fmaxf(x0f + 1.f, 0.f), Wm1);
        i00[j] = y0 * W + x0; i01[j] = y0 * W + x1;
        i10[j] = y1 * W + x0; i11[j] = y1 * W + x1;
        w00[j] = vy0 * vx0; w01[j] = vy0 * vx1;
        w10[j] = vy1 * vx0; w11[j] = vy1 * vx1;
    }

    const float* fb = feat + (size_t)b * C * N;
    float* cp = col + (size_t)k * NtotPad + (size_t)b * Npad + n0;
    const size_t cstride = (size_t)9 * NtotPad;
    if (vn == 4) {
        for (int c = 0; c < C; c++) {
            const float* fc = fb + (size_t)c * N;
            float4 v;
            v.x = round_tf32(w00[0]*fc[i00[0]] + w01[0]*fc[i01[0]] + w10[0]*fc[i10[0]] + w11[0]*fc[i11[0]]);
            v.y = round_tf32(w00[1]*fc[i00[1]] + w01[1]*fc[i01[1]] + w10[1]*fc[i10[1]] + w11[1]*fc[i11[1]]);
            v.z = round_tf32(w00[2]*fc[i00[2]] + w01[2]*fc[i01[2]] + w10[2]*fc[i10[2]] + w11[2]*fc[i11[2]]);
            v.w = round_tf32(w00[3]*fc[i00[3]] + w01[3]*fc[i01[3]] + w10[3]*fc[i10[3]] + w11[3]*fc[i11[3]]);
            *(float4*)(cp + (size_t)c * cstride) = v;
        }
    } else {
        for (int c = 0; c < C; c++) {
            const float* fc = fb + (size_t)c * N;
            float* o = cp + (size_t)c * cstride;
            for (int j = 0; j < vn; j++)
                o[j] = round_tf32(w00[j]*fc[i00[j]] + w01[j]*fc[i01[j]] +
                                  w10[j]*fc[i10[j]] + w11[j]*fc[i11[j]]);
        }
    }
}

// ---------------------------------------------------------------------------
// round W to tf32 once per scale
// ---------------------------------------------------------------------------
__global__ __launch_bounds__(256) void wround_kernel(const float* __restrict__ in,
                                                     float* __restrict__ out, int n) {
    int i = blockIdx.x * 256 + threadIdx.x;
    if (i < n) out[i] = round_tf32(in[i]);
}

// ---------------------------------------------------------------------------
// tf32 mma.sync GEMM:  out = W[256 x 2304] @ col[2304 x NtotPad]
// CTA 128x128, BK=16, 8 warps (2M x 4N), warp tile 64x32, double-buffer cp.async
// grid (2, NTOT/128): m on x so sibling m-tiles share the col tile via L2
// ---------------------------------------------------------------------------
#define A_STRIDE 20
#define B_STRIDE 136

__global__ __launch_bounds__(256) void dconv_mma_kernel(const float* __restrict__ Wm,
                                                        const float* __restrict__ Bc,
                                                        float* __restrict__ out,
                                                        int Nsp, int NtotPad, int shift) {
    __shared__ float sA[2][128 * A_STRIDE];
    __shared__ float sB[2][16 * B_STRIDE];

    int tid = threadIdx.x;
    int wid = tid >> 5, lane = tid & 31;
    int g = lane >> 2, t = lane & 3;
    int warpM = wid >> 2;
    int warpN = wid & 3;

    int m0 = blockIdx.x * 128;
    int n0 = blockIdx.y * 128;
    int bb = n0 >> shift;
    int nl0 = n0 & ((1 << shift) - 1);

    uint32_t sAu = smem_u32(&sA[0][0]);
    uint32_t sBu = smem_u32(&sB[0][0]);

    auto load_stage = [&](int stg, int k0) {
        uint32_t aBase = sAu + stg * (128 * A_STRIDE * 4);
        uint32_t bBase = sBu + stg * (16 * B_STRIDE * 4);
#pragma unroll
        for (int i = 0; i < 2; i++) {
            int q = tid + i * 256;
            int row = q >> 2, c16 = q & 3;
            cpa16(aBase + (row * A_STRIDE + c16 * 4) * 4,
                  Wm + (size_t)(m0 + row) * KDIM + k0 + c16 * 4);
        }
#pragma unroll
        for (int i = 0; i < 2; i++) {
            int q = tid + i * 256;
            int row = q >> 5, c = q & 31;
            cpa16(bBase + (row * B_STRIDE + c * 4) * 4,
                  Bc + (size_t)(k0 + row) * NtotPad + n0 + c * 4);
        }
    };

    float acc[4][4][4];
#pragma unroll
    for (int i = 0; i < 4; i++)
#pragma unroll
        for (int j = 0; j < 4; j++)
#pragma unroll
            for (int r = 0; r < 4; r++) acc[i][j][r] = 0.f;

    const int ITERS = KDIM / 16;   // 144
    load_stage(0, 0);
    asm volatile("cp.async.commit_group;" ::: "memory");

    for (int it = 0; it < ITERS; ++it) {
        int cur = it & 1;
        if (it + 1 < ITERS) load_stage(cur ^ 1, (it + 1) * 16);
        asm volatile("cp.async.commit_group;" ::: "memory");
        asm volatile("cp.async.wait_group 1;" ::: "memory");
        __syncthreads();

        const float* A0 = &sA[cur][0];
        const float* B0 = &sB[cur][0];
#pragma unroll
        for (int ks = 0; ks < 2; ks++) {
            int kb = ks * 8;
            uint32_t af[4][4];
#pragma unroll
            for (int mt = 0; mt < 4; mt++) {
                int m = warpM * 64 + mt * 16 + g;
                af[mt][0] = __float_as_uint(A0[m * A_STRIDE + kb + t]);
                af[mt][1] = __float_as_uint(A0[(m + 8) * A_STRIDE + kb + t]);
                af[mt][2] = __float_as_uint(A0[m * A_STRIDE + kb + t + 4]);
                af[mt][3] = __float_as_uint(A0[(m + 8) * A_STRIDE + kb + t + 4]);
            }
            uint32_t bf[4][2];
#pragma unroll
            for (int nt = 0; nt < 4; nt++) {
                int n = warpN * 32 + nt * 8 + g;
                bf[nt][0] = __float_as_uint(B0[(kb + t) * B_STRIDE + n]);
                bf[nt][1] = __float_as_uint(B0[(kb + t + 4) * B_STRIDE + n]);
            }
#pragma unroll
            for (int mt = 0; mt < 4; mt++)
#pragma unroll
                for (int nt = 0; nt < 4; nt++)
                    mma_tf32(acc[mt][nt][0], acc[mt][nt][1], acc[mt][nt][2], acc[mt][nt][3],
                             af[mt][0], af[mt][1], af[mt][2], af[mt][3],
                             bf[nt][0], bf[nt][1]);
        }
        __syncthreads();
    }

#pragma unroll
    for (int mt = 0; mt < 4; mt++) {
        int m = m0 + warpM * 64 + mt * 16 + g;
        float* r0 = out + ((size_t)bb * C + m) * Nsp;
        float* r1 = out + ((size_t)bb * C + m + 8) * Nsp;
#pragma unroll
        for (int nt = 0; nt < 4; nt++) {
            int n = nl0 + warpN * 32 + nt * 8 + t * 2;
            if (n < Nsp) {
                r0[n] = acc[mt][nt][0];
                r1[n] = acc[mt][nt][2];
                if (n + 1 < Nsp) {
                    r0[n + 1] = acc[mt][nt][1];
                    r1[n + 1] = acc[mt][nt][3];
                }
            }
        }
    }
}

// ---------------------------------------------------------------------------
extern "C" void kernel_launch(void* const* d_in, const int* in_sizes, int n_in,
                              void* d_out, int out_size) {
    const float *Z[3], *X[3], *OW[3], *OB[3], *DW[3], *G[3];
    int nz = 0, nx = 0, nw = 0, nb = 0, nd = 0, ng = 0;
    for (int i = 0; i < n_in; i++) {
        switch (in_sizes[i]) {
            case 1843200: Z[nz++]  = (const float*)d_in[i]; break;
            case 7872512: X[nx++]  = (const float*)d_in[i]; break;
            case 41472:   OW[nw++] = (const float*)d_in[i]; break;
            case 18:      OB[nb++] = (const float*)d_in[i]; break;
            case 589824:  DW[nd++] = (const float*)d_in[i]; break;
            case 1:       G[ng++]  = (const float*)d_in[i]; break;
            default: break;
        }
    }

    float *attnA, *attnB, *featZ, *featX, *offb, *colb, *wrb, *hib, *lob;
    cudaGetSymbolAddress((void**)&attnA, g_attnA);
    cudaGetSymbolAddress((void**)&attnB, g_attnB);
    cudaGetSymbolAddress((void**)&featZ, g_featZ);
    cudaGetSymbolAddress((void**)&featX, g_featX);
    cudaGetSymbolAddress((void**)&offb,  g_off);
    cudaGetSymbolAddress((void**)&colb,  g_col);
    cudaGetSymbolAddress((void**)&wrb,   g_wr);
    cudaGetSymbolAddress((void**)&hib,   g_hi);
    cudaGetSymbolAddress((void**)&lob,   g_lo);

    float* outZ = (float*)d_out;
    float* outX = outZ + (size_t)3 * B * C * NZ;

    const int NPAD_Z = 256,  SH_Z = 8;
    const int NPAD_X = 1024, SH_X = 10;
    const int NTOT_Z = B * NPAD_Z;   // 8192
    const int NTOT_X = B * NPAD_X;   // 32768
    const int KP_Z = 240;
    const int KP_X = 976;
    const int TOT_Z = B * C * KP_Z;
    const int TOT_X = B * C * KP_X;

    for (int i = 0; i < 3; i++) {
        // --- channel attention (gram via pipelined 3xTF32) ---
        splitf_kernel<<<CDIV(TOT_Z, 256), 256>>>(Z[i], hib, lob, NZ, KP_Z, TOT_Z);
        gram_mma3_kernel<<<dim3(2, 2, B), 256>>>(hib, lob, attnA, KP_Z);
        attn_softmax_kernel<<<B * C, 256>>>(attnA);
        splitf_kernel<<<CDIV(TOT_X, 256), 256>>>(X[i], hib, lob, NX, KP_X, TOT_X);
        gram_mma3_kernel<<<dim3(2, 2, B), 256>>>(hib, lob, attnB, KP_X);
        attn_softmax_kernel<<<B * C, 256>>>(attnB);

        // --- cam_use (cross attention) via pipelined tf32 MMA ---
        camuse_mma_kernel<<<dim3(2, 2, B), 256>>>(attnB, Z[i], featZ, NZ, G[i]);
        camuse_mma_kernel<<<dim3(8, 2, B), 256>>>(attnA, X[i], featX, NX, G[i]);

        wround_kernel<<<CDIV(256 * KDIM, 256), 256>>>(DW[i], wrb, 256 * KDIM);

        // --- z branch ---
        offconv3_kernel<<<dim3(CDIV(NZ, 128), 6, B), 128>>>(featZ, OW[i], OB[i], offb, 15, 15);
        sample4_kernel<<<dim3(CDIV(NZ, 512), 9, B), 128>>>(featZ, offb, colb, 15, 15, NPAD_Z, NTOT_Z);
        dconv_mma_kernel<<<dim3(2, NTOT_Z / 128), 256>>>(wrb, colb,
                                                         outZ + (size_t)i * B * C * NZ,
                                                         NZ, NTOT_Z, SH_Z);
        // --- x branch ---
        offconv3_kernel<<<dim3(CDIV(NX, 128), 6, B), 128>>>(featX, OW[i], OB[i], offb, 31, 31);
        sample4_kernel<<<dim3(CDIV(NX, 512), 9, B), 128>>>(featX, offb, colb, 31, 31, NPAD_X, NTOT_X);
        dconv_mma_kernel<<<dim3(2, NTOT_X / 128), 256>>>(wrb, colb,
                                                         outX + (size_t)i * B * C * NX,
                                                         NX, NTOT_X, SH_X);
    }
    (void)out_size;
}

// round 9
// speedup vs baseline: 1.2854x; 1.2854x over previous
#include <cuda_runtime.h>
#include <math.h>
#include <stdint.h>

#define CDIV(a,b) (((a)+(b)-1)/(b))

static const int B  = 32;
static const int C  = 256;
static const int NZ = 225;   // 15*15
static const int NX = 961;   // 31*31
static const int KDIM = 2304; // C*9

// ---------------- scratch (device globals; no cudaMalloc allowed) ----------
__device__ float g_attnA[32 * 256 * 256];
__device__ float g_attnB[32 * 256 * 256];
__device__ float g_featZ[32 * 256 * 225];
__device__ float g_featX[32 * 256 * 961];
__device__ float g_off  [32 * 18  * 961];
__device__ float g_col  [2304 * 32 * 1024];   // padded im2col (302 MB)
__device__ float g_wr   [256 * 2304];         // tf32-rounded weights
__device__ float g_hi   [32 * 256 * 976];     // tf32 split hi, K padded
__device__ float g_lo   [32 * 256 * 976];     // tf32 split lo, K padded

// ======================= PTX helpers =======================================
__device__ __forceinline__ uint32_t smem_u32(const void* p) {
    uint32_t a;
    asm("{ .reg .u64 t; cvta.to.shared.u64 t, %1; cvt.u32.u64 %0, t; }" : "=r"(a) : "l"(p));
    return a;
}
__device__ __forceinline__ void cpa16(uint32_t dst, const void* src) {
    asm volatile("cp.async.cg.shared.global [%0], [%1], 16;" :: "r"(dst), "l"(src));
}
__device__ __forceinline__ float round_tf32(float v) {
    uint32_t r;
    asm("cvt.rna.tf32.f32 %0, %1;" : "=r"(r) : "f"(v));
    return __uint_as_float(r);
}
__device__ __forceinline__ void mma_tf32(float& c0, float& c1, float& c2, float& c3,
                                         uint32_t a0, uint32_t a1, uint32_t a2, uint32_t a3,
                                         uint32_t b0, uint32_t b1) {
    asm volatile(
        "mma.sync.aligned.m16n8k8.row.col.f32.tf32.tf32.f32 "
        "{%0,%1,%2,%3},{%4,%5,%6,%7},{%8,%9},{%0,%1,%2,%3};"
        : "+f"(c0), "+f"(c1), "+f"(c2), "+f"(c3)
        : "r"(a0), "r"(a1), "r"(a2), "r"(a3), "r"(b0), "r"(b1));
}

// ---------------------------------------------------------------------------
// split input into tf32 hi/lo pair, K padded to Kpad with zeros
// ---------------------------------------------------------------------------
__global__ __launch_bounds__(256) void splitf_kernel(const float* __restrict__ in,
                                                     float* __restrict__ hi,
                                                     float* __restrict__ lo,
                                                     int K, int Kpad, int total) {
    int i = blockIdx.x * 256 + threadIdx.x;
    if (i >= total) return;
    int bc = i / Kpad, k = i - bc * Kpad;
    float v = (k < K) ? in[(size_t)bc * K + k] : 0.f;
    float h = round_tf32(v);
    hi[i] = h;
    lo[i] = round_tf32(v - h);
}

// ---------------------------------------------------------------------------
// gram via 3xTF32: E[b] = F[b] * F[b]^T, K pre-padded (mult of 8)
// CTA 128x128, BK=8, cp.async double-buffered, 8 warps (2M x 4N)
// ---------------------------------------------------------------------------
__global__ __launch_bounds__(256) void gram_mma3_kernel(const float* __restrict__ hi,
                                                        const float* __restrict__ lo,
                                                        float* __restrict__ E, int Kpad) {
    __shared__ float Ah[2][1536], Al[2][1536], Bh[2][1536], Bl[2][1536];
    int b = blockIdx.z;
    int c0 = blockIdx.y * 128, d0 = blockIdx.x * 128;
    const size_t fb = (size_t)b * C * Kpad;
    int tid = threadIdx.x;
    int wid = tid >> 5, lane = tid & 31;
    int g = lane >> 2, t = lane & 3;
    int warpM = wid >> 2, warpN = wid & 3;

    uint32_t ahU = smem_u32(&Ah[0][0]);
    uint32_t alU = smem_u32(&Al[0][0]);
    uint32_t bhU = smem_u32(&Bh[0][0]);
    uint32_t blU = smem_u32(&Bl[0][0]);

    int lrow = tid >> 1, lhalf = tid & 1;
    auto load_stage = [&](int stg, int k0) {
        uint32_t doff = stg * 6144 + (lrow * 12 + lhalf * 4) * 4;
        const size_t sA = fb + (size_t)(c0 + lrow) * Kpad + k0 + lhalf * 4;
        const size_t sB = fb + (size_t)(d0 + lrow) * Kpad + k0 + lhalf * 4;
        cpa16(ahU + doff, hi + sA);
        cpa16(alU + doff, lo + sA);
        cpa16(bhU + doff, hi + sB);
        cpa16(blU + doff, lo + sB);
    };

    float acc[4][4][4];
#pragma unroll
    for (int i = 0; i < 4; i++)
#pragma unroll
        for (int j = 0; j < 4; j++)
#pragma unroll
            for (int r = 0; r < 4; r++) acc[i][j][r] = 0.f;

    const int ITERS = Kpad / 8;
    load_stage(0, 0);
    asm volatile("cp.async.commit_group;" ::: "memory");

    for (int it = 0; it < ITERS; it++) {
        int cur = it & 1;
        if (it + 1 < ITERS) load_stage(cur ^ 1, (it + 1) * 8);
        asm volatile("cp.async.commit_group;" ::: "memory");
        asm volatile("cp.async.wait_group 1;" ::: "memory");
        __syncthreads();

        const float* A0h = &Ah[cur][0];
        const float* A0l = &Al[cur][0];
        const float* B0h = &Bh[cur][0];
        const float* B0l = &Bl[cur][0];

        uint32_t ah[4][4], al[4][4];
#pragma unroll
        for (int mt = 0; mt < 4; mt++) {
            int m = warpM * 64 + mt * 16 + g;
            ah[mt][0] = __float_as_uint(A0h[m * 12 + t]);
            ah[mt][1] = __float_as_uint(A0h[(m + 8) * 12 + t]);
            ah[mt][2] = __float_as_uint(A0h[m * 12 + t + 4]);
            ah[mt][3] = __float_as_uint(A0h[(m + 8) * 12 + t + 4]);
            al[mt][0] = __float_as_uint(A0l[m * 12 + t]);
            al[mt][1] = __float_as_uint(A0l[(m + 8) * 12 + t]);
            al[mt][2] = __float_as_uint(A0l[m * 12 + t + 4]);
            al[mt][3] = __float_as_uint(A0l[(m + 8) * 12 + t + 4]);
        }
        uint32_t bh[4][2], bl[4][2];
#pragma unroll
        for (int nt = 0; nt < 4; nt++) {
            int n = warpN * 32 + nt * 8 + g;
            bh[nt][0] = __float_as_uint(B0h[n * 12 + t]);
            bh[nt][1] = __float_as_uint(B0h[n * 12 + t + 4]);
            bl[nt][0] = __float_as_uint(B0l[n * 12 + t]);
            bl[nt][1] = __float_as_uint(B0l[n * 12 + t + 4]);
        }
#pragma unroll
        for (int mt = 0; mt < 4; mt++)
#pragma unroll
            for (int nt = 0; nt < 4; nt++) {
                mma_tf32(acc[mt][nt][0], acc[mt][nt][1], acc[mt][nt][2], acc[mt][nt][3],
                         ah[mt][0], ah[mt][1], ah[mt][2], ah[mt][3],
                         bh[nt][0], bh[nt][1]);
                mma_tf32(acc[mt][nt][0], acc[mt][nt][1], acc[mt][nt][2], acc[mt][nt][3],
                         ah[mt][0], ah[mt][1], ah[mt][2], ah[mt][3],
                         bl[nt][0], bl[nt][1]);
                mma_tf32(acc[mt][nt][0], acc[mt][nt][1], acc[mt][nt][2], acc[mt][nt][3],
                         al[mt][0], al[mt][1], al[mt][2], al[mt][3],
                         bh[nt][0], bh[nt][1]);
            }
        __syncthreads();
    }

    float* Eb = E + (size_t)b * C * C;
#pragma unroll
    for (int mt = 0; mt < 4; mt++) {
        int m = c0 + warpM * 64 + mt * 16 + g;
#pragma unroll
        for (int nt = 0; nt < 4; nt++) {
            int n = d0 + warpN * 32 + nt * 8 + t * 2;
            Eb[(size_t)m * C + n]           = acc[mt][nt][0];
            Eb[(size_t)m * C + n + 1]       = acc[mt][nt][1];
            Eb[(size_t)(m + 8) * C + n]     = acc[mt][nt][2];
            Eb[(size_t)(m + 8) * C + n + 1] = acc[mt][nt][3];
        }
    }
}

// ---------------------------------------------------------------------------
// softmax of (rowmax - e) == exp(rowmin - e)/sum  (shuffle reductions)
// ---------------------------------------------------------------------------
__global__ __launch_bounds__(256) void attn_softmax_kernel(float* __restrict__ E) {
    int row = blockIdx.x;
    float* e = E + (size_t)row * 256;
    int t = threadIdx.x;
    int warp = t >> 5, lane = t & 31;
    __shared__ float sm[16];
    float v = e[t];
    float m = v;
#pragma unroll
    for (int s = 16; s > 0; s >>= 1) m = fminf(m, __shfl_xor_sync(0xffffffffu, m, s));
    if (lane == 0) sm[warp] = m;
    __syncthreads();
    float emin = fminf(fminf(fminf(sm[0], sm[1]), fminf(sm[2], sm[3])),
                       fminf(fminf(sm[4], sm[5]), fminf(sm[6], sm[7])));
    float p = expf(emin - v);
    float sum = p;
#pragma unroll
    for (int s = 16; s > 0; s >>= 1) sum += __shfl_xor_sync(0xffffffffu, sum, s);
    if (lane == 0) sm[8 + warp] = sum;
    __syncthreads();
    float tot = (sm[8] + sm[9]) + (sm[10] + sm[11]) + (sm[12] + sm[13]) + (sm[14] + sm[15]);
    e[t] = p / tot;
}

// ---------------------------------------------------------------------------
// cam_use via tf32 MMA: O[b] = gamma * A[b] @ F[b] + F[b]
// CTA 128x128, BK=8, A via cp.async double-buffer, B via guarded LDG+STS
// ---------------------------------------------------------------------------
__global__ __launch_bounds__(256) void camuse_mma_kernel(const float* __restrict__ A,
                                                         const float* __restrict__ F,
                                                         float* __restrict__ O, int N,
                                                         const float* __restrict__ gamma) {
    __shared__ float sA[2][1536];    // 128 x 8 (stride 12)
    __shared__ float sB[2][1088];    // 8 x 128 (stride 136)
    int b = blockIdx.z;
    int m0 = blockIdx.y * 128, n0 = blockIdx.x * 128;
    const float* Ab = A + (size_t)b * C * C;
    const float* Fb = F + (size_t)b * C * N;
    int tid = threadIdx.x;
    int wid = tid >> 5, lane = tid & 31;
    int g = lane >> 2, t = lane & 3;
    int warpM = wid >> 2, warpN = wid & 3;

    uint32_t sAu = smem_u32(&sA[0][0]);
    int lrow = tid >> 1, lhalf = tid & 1;

    auto load_stage = [&](int stg, int k0) {
        cpa16(sAu + stg * 6144 + (lrow * 12 + lhalf * 4) * 4,
              Ab + (size_t)(m0 + lrow) * C + k0 + lhalf * 4);
#pragma unroll
        for (int i = 0; i < 4; i++) {
            int idx = tid + i * 256;
            int r = idx >> 7, cc = idx & 127;
            int n = n0 + cc;
            sB[stg][r * 136 + cc] = (n < N) ? round_tf32(Fb[(size_t)(k0 + r) * N + n]) : 0.f;
        }
    };

    float acc[4][4][4];
#pragma unroll
    for (int i = 0; i < 4; i++)
#pragma unroll
        for (int j = 0; j < 4; j++)
#pragma unroll
            for (int r = 0; r < 4; r++) acc[i][j][r] = 0.f;

    const int ITERS = C / 8;   // 32
    load_stage(0, 0);
    asm volatile("cp.async.commit_group;" ::: "memory");

    for (int it = 0; it < ITERS; it++) {
        int cur = it & 1;
        if (it + 1 < ITERS) load_stage(cur ^ 1, (it + 1) * 8);
        asm volatile("cp.async.commit_group;" ::: "memory");
        asm volatile("cp.async.wait_group 1;" ::: "memory");
        __syncthreads();

        const float* A0 = &sA[cur][0];
        const float* B0 = &sB[cur][0];
        uint32_t af[4][4];
#pragma unroll
        for (int mt = 0; mt < 4; mt++) {
            int m = warpM * 64 + mt * 16 + g;
            af[mt][0] = __float_as_uint(A0[m * 12 + t]);
            af[mt][1] = __float_as_uint(A0[(m + 8) * 12 + t]);
            af[mt][2] = __float_as_uint(A0[m * 12 + t + 4]);
            af[mt][3] = __float_as_uint(A0[(m + 8) * 12 + t + 4]);
        }
        uint32_t bf[4][2];
#pragma unroll
        for (int nt = 0; nt < 4; nt++) {
            int n = warpN * 32 + nt * 8 + g;
            bf[nt][0] = __float_as_uint(B0[t * 136 + n]);
            bf[nt][1] = __float_as_uint(B0[(t + 4) * 136 + n]);
        }
#pragma unroll
        for (int mt = 0; mt < 4; mt++)
#pragma unroll
            for (int nt = 0; nt < 4; nt++)
                mma_tf32(acc[mt][nt][0], acc[mt][nt][1], acc[mt][nt][2], acc[mt][nt][3],
                         af[mt][0], af[mt][1], af[mt][2], af[mt][3],
                         bf[nt][0], bf[nt][1]);
        __syncthreads();
    }

    float gm = gamma[0];
#pragma unroll
    for (int mt = 0; mt < 4; mt++) {
        int m = m0 + warpM * 64 + mt * 16 + g;
#pragma unroll
        for (int nt = 0; nt < 4; nt++) {
            int n = n0 + warpN * 32 + nt * 8 + t * 2;
            if (n < N) {
                O[((size_t)b * C + m) * N + n] = gm * acc[mt][nt][0] + Fb[(size_t)m * N + n];
                O[((size_t)b * C + m + 8) * N + n] = gm * acc[mt][nt][2] + Fb[(size_t)(m + 8) * N + n];
                if (n + 1 < N) {
                    O[((size_t)b * C + m) * N + n + 1] = gm * acc[mt][nt][1] + Fb[(size_t)m * N + n + 1];
                    O[((size_t)b * C + m + 8) * N + n + 1] = gm * acc[mt][nt][3] + Fb[(size_t)(m + 8) * N + n + 1];
                }
            }
        }
    }
}

// ---------------------------------------------------------------------------
// offset conv: 3x3, C -> 18, pad 1.  grid (ntile, 18, B), 128 threads
// (per-channel version — max parallelism; latency-bound gather loop)
// ---------------------------------------------------------------------------
__global__ __launch_bounds__(128) void offconv_kernel(const float* __restrict__ feat,
                                                      const float* __restrict__ woff,
                                                      const float* __restrict__ boff,
                                                      float* __restrict__ off,
                                                      int H, int W) {
    __shared__ float sw[2304];
    int ch = blockIdx.y, b = blockIdx.z;
    const float* wp = woff + (size_t)ch * 2304;
    for (int i = threadIdx.x; i < 2304; i += 128) sw[i] = wp[i];
    __syncthreads();
    int N = H * W;
    int n = blockIdx.x * 128 + threadIdx.x;
    if (n >= N) return;
    int h = n / W, w = n % W;
    const float* fb = feat + (size_t)b * C * N;
    float acc = boff[ch];
    for (int c = 0; c < C; c++) {
        const float* fc = fb + (size_t)c * N;
        const float* swc = sw + c * 9;
#pragma unroll
        for (int ky = 0; ky < 3; ky++) {
            int y = h + ky - 1;
            if ((unsigned)y >= (unsigned)H) continue;
            const float* fr = fc + y * W;
#pragma unroll
            for (int kx = 0; kx < 3; kx++) {
                int x = w + kx - 1;
                if ((unsigned)x < (unsigned)W) acc += swc[ky * 3 + kx] * fr[x];
            }
        }
    }
    off[((size_t)b * 18 + ch) * N + n] = acc;
}

// ---------------------------------------------------------------------------
// bilinear deform sampling -> padded im2col, tf32-rounded values
// channel-split: grid (ntile, 18, B); y = khalf*9? no: y = cslice*9 + k
// each block handles 128 channels -> 2x thread-level parallelism vs R6
// ---------------------------------------------------------------------------
__global__ __launch_bounds__(128) void sample_kernel(const float* __restrict__ feat,
                                                     const float* __restrict__ off,
                                                     float* __restrict__ col,
                                                     int H, int W, int Npad, int NtotPad) {
    int N = H * W;
    int b = blockIdx.z;
    int k = blockIdx.y % 9;
    int c0 = (blockIdx.y / 9) * 128;     // 0 or 128
    int n = blockIdx.x * 128 + threadIdx.x;
    if (n >= N) return;
    int h = n / W, w = n % W;
    int ky = k / 3, kx = k % 3;
    float oy = off[((size_t)b * 18 + 2 * k) * N + n];
    float ox = off[((size_t)b * 18 + 2 * k + 1) * N + n];
    float py = (float)(h + ky - 1) + oy;
    float px = (float)(w + kx - 1) + ox;
    float y0f = floorf(py), x0f = floorf(px);
    float ly = py - y0f, lx = px - x0f;
    float Hm1 = (float)(H - 1), Wm1 = (float)(W - 1);

    float vy0 = (y0f >= 0.f && y0f <= Hm1) ? (1.f - ly) : 0.f;
    float vy1 = (y0f + 1.f >= 0.f && y0f + 1.f <= Hm1) ? ly : 0.f;
    float vx0 = (x0f >= 0.f && x0f <= Wm1) ? (1.f - lx) : 0.f;
    float vx1 = (x0f + 1.f >= 0.f && x0f + 1.f <= Wm1) ? lx : 0.f;
    int y0 = (int)fminf(fmaxf(y0f, 0.f), Hm1);
    int y1 = (int)fminf(fmaxf(y0f + 1.f, 0.f), Hm1);
    int x0 = (int)fminf(fmaxf(x0f, 0.f), Wm1);
    int x1 = (int)fminf(fmaxf(x0f + 1.f, 0.f), Wm1);

    int i00 = y0 * W + x0, i01 = y0 * W + x1, i10 = y1 * W + x0, i11 = y1 * W + x1;
    float w00 = vy0 * vx0, w01 = vy0 * vx1, w10 = vy1 * vx0, w11 = vy1 * vx1;

    const float* fb = feat + ((size_t)b * C + c0) * N;
    float* cp = col + (size_t)(c0 * 9 + k) * NtotPad + (size_t)b * Npad + n;
    const size_t cstride = (size_t)9 * NtotPad;
    for (int c = 0; c < 128; c++) {
        const float* fc = fb + (size_t)c * N;
        float v = w00 * fc[i00] + w01 * fc[i01] + w10 * fc[i10] + w11 * fc[i11];
        cp[(size_t)c * cstride] = round_tf32(v);
    }
}

// ---------------------------------------------------------------------------
// round W to tf32 once per scale
// ---------------------------------------------------------------------------
__global__ __launch_bounds__(256) void wround_kernel(const float* __restrict__ in,
                                                     float* __restrict__ out, int n) {
    int i = blockIdx.x * 256 + threadIdx.x;
    if (i < n) out[i] = round_tf32(in[i]);
}

// ---------------------------------------------------------------------------
// tf32 mma.sync GEMM:  out = W[256 x 2304] @ col[2304 x NtotPad]
// CTA 128x128, BK=16, 8 warps (2M x 4N), warp tile 64x32, double-buffer cp.async
// grid (2, NTOT/128): m on x so sibling m-tiles share the col tile via L2
// ---------------------------------------------------------------------------
#define A_STRIDE 20
#define B_STRIDE 136

__global__ __launch_bounds__(256) void dconv_mma_kernel(const float* __restrict__ Wm,
                                                        const float* __restrict__ Bc,
                                                        float* __restrict__ out,
                                                        int Nsp, int NtotPad, int shift) {
    __shared__ float sA[2][128 * A_STRIDE];
    __shared__ float sB[2][16 * B_STRIDE];

    int tid = threadIdx.x;
    int wid = tid >> 5, lane = tid & 31;
    int g = lane >> 2, t = lane & 3;
    int warpM = wid >> 2;
    int warpN = wid & 3;

    int m0 = blockIdx.x * 128;
    int n0 = blockIdx.y * 128;
    int bb = n0 >> shift;
    int nl0 = n0 & ((1 << shift) - 1);

    uint32_t sAu = smem_u32(&sA[0][0]);
    uint32_t sBu = smem_u32(&sB[0][0]);

    auto load_stage = [&](int stg, int k0) {
        uint32_t aBase = sAu + stg * (128 * A_STRIDE * 4);
        uint32_t bBase = sBu + stg * (16 * B_STRIDE * 4);
#pragma unroll
        for (int i = 0; i < 2; i++) {
            int q = tid + i * 256;
            int row = q >> 2, c16 = q & 3;
            cpa16(aBase + (row * A_STRIDE + c16 * 4) * 4,
                  Wm + (size_t)(m0 + row) * KDIM + k0 + c16 * 4);
        }
#pragma unroll
        for (int i = 0; i < 2; i++) {
            int q = tid + i * 256;
            int row = q >> 5, c = q & 31;
            cpa16(bBase + (row * B_STRIDE + c * 4) * 4,
                  Bc + (size_t)(k0 + row) * NtotPad + n0 + c * 4);
        }
    };

    float acc[4][4][4];
#pragma unroll
    for (int i = 0; i < 4; i++)
#pragma unroll
        for (int j = 0; j < 4; j++)
#pragma unroll
            for (int r = 0; r < 4; r++) acc[i][j][r] = 0.f;

    const int ITERS = KDIM / 16;   // 144
    load_stage(0, 0);
    asm volatile("cp.async.commit_group;" ::: "memory");

    for (int it = 0; it < ITERS; ++it) {
        int cur = it & 1;
        if (it + 1 < ITERS) load_stage(cur ^ 1, (it + 1) * 16);
        asm volatile("cp.async.commit_group;" ::: "memory");
        asm volatile("cp.async.wait_group 1;" ::: "memory");
        __syncthreads();

        const float* A0 = &sA[cur][0];
        const float* B0 = &sB[cur][0];
#pragma unroll
        for (int ks = 0; ks < 2; ks++) {
            int kb = ks * 8;
            uint32_t af[4][4];
#pragma unroll
            for (int mt = 0; mt < 4; mt++) {
                int m = warpM * 64 + mt * 16 + g;
                af[mt][0] = __float_as_uint(A0[m * A_STRIDE + kb + t]);
                af[mt][1] = __float_as_uint(A0[(m + 8) * A_STRIDE + kb + t]);
                af[mt][2] = __float_as_uint(A0[m * A_STRIDE + kb + t + 4]);
                af[mt][3] = __float_as_uint(A0[(m + 8) * A_STRIDE + kb + t + 4]);
            }
            uint32_t bf[4][2];
#pragma unroll
            for (int nt = 0; nt < 4; nt++) {
                int n = warpN * 32 + nt * 8 + g;
                bf[nt][0] = __float_as_uint(B0[(kb + t) * B_STRIDE + n]);
                bf[nt][1] = __float_as_uint(B0[(kb + t + 4) * B_STRIDE + n]);
            }
#pragma unroll
            for (int mt = 0; mt < 4; mt++)
#pragma unroll
                for (int nt = 0; nt < 4; nt++)
                    mma_tf32(acc[mt][nt][0], acc[mt][nt][1], acc[mt][nt][2], acc[mt][nt][3],
                             af[mt][0], af[mt][1], af[mt][2], af[mt][3],
                             bf[nt][0], bf[nt][1]);
        }
        __syncthreads();
    }

#pragma unroll
    for (int mt = 0; mt < 4; mt++) {
        int m = m0 + warpM * 64 + mt * 16 + g;
        float* r0 = out + ((size_t)bb * C + m) * Nsp;
        float* r1 = out + ((size_t)bb * C + m + 8) * Nsp;
#pragma unroll
        for (int nt = 0; nt < 4; nt++) {
            int n = nl0 + warpN * 32 + nt * 8 + t * 2;
            if (n < Nsp) {
                r0[n] = acc[mt][nt][0];
                r1[n] = acc[mt][nt][2];
                if (n + 1 < Nsp) {
                    r0[n + 1] = acc[mt][nt][1];
                    r1[n + 1] = acc[mt][nt][3];
                }
            }
        }
    }
}

// ---------------------------------------------------------------------------
extern "C" void kernel_launch(void* const* d_in, const int* in_sizes, int n_in,
                              void* d_out, int out_size) {
    const float *Z[3], *X[3], *OW[3], *OB[3], *DW[3], *G[3];
    int nz = 0, nx = 0, nw = 0, nb = 0, nd = 0, ng = 0;
    for (int i = 0; i < n_in; i++) {
        switch (in_sizes[i]) {
            case 1843200: Z[nz++]  = (const float*)d_in[i]; break;
            case 7872512: X[nx++]  = (const float*)d_in[i]; break;
            case 41472:   OW[nw++] = (const float*)d_in[i]; break;
            case 18:      OB[nb++] = (const float*)d_in[i]; break;
            case 589824:  DW[nd++] = (const float*)d_in[i]; break;
            case 1:       G[ng++]  = (const float*)d_in[i]; break;
            default: break;
        }
    }

    float *attnA, *attnB, *featZ, *featX, *offb, *colb, *wrb, *hib, *lob;
    cudaGetSymbolAddress((void**)&attnA, g_attnA);
    cudaGetSymbolAddress((void**)&attnB, g_attnB);
    cudaGetSymbolAddress((void**)&featZ, g_featZ);
    cudaGetSymbolAddress((void**)&featX, g_featX);
    cudaGetSymbolAddress((void**)&offb,  g_off);
    cudaGetSymbolAddress((void**)&colb,  g_col);
    cudaGetSymbolAddress((void**)&wrb,   g_wr);
    cudaGetSymbolAddress((void**)&hib,   g_hi);
    cudaGetSymbolAddress((void**)&lob,   g_lo);

    float* outZ = (float*)d_out;
    float* outX = outZ + (size_t)3 * B * C * NZ;

    const int NPAD_Z = 256,  SH_Z = 8;
    const int NPAD_X = 1024, SH_X = 10;
    const int NTOT_Z = B * NPAD_Z;   // 8192
    const int NTOT_X = B * NPAD_X;   // 32768
    const int KP_Z = 240;
    const int KP_X = 976;
    const int TOT_Z = B * C * KP_Z;
    const int TOT_X = B * C * KP_X;

    for (int i = 0; i < 3; i++) {
        // --- channel attention (gram via pipelined 3xTF32) ---
        splitf_kernel<<<CDIV(TOT_Z, 256), 256>>>(Z[i], hib, lob, NZ, KP_Z, TOT_Z);
        gram_mma3_kernel<<<dim3(2, 2, B), 256>>>(hib, lob, attnA, KP_Z);
        attn_softmax_kernel<<<B * C, 256>>>(attnA);
        splitf_kernel<<<CDIV(TOT_X, 256), 256>>>(X[i], hib, lob, NX, KP_X, TOT_X);
        gram_mma3_kernel<<<dim3(2, 2, B), 256>>>(hib, lob, attnB, KP_X);
        attn_softmax_kernel<<<B * C, 256>>>(attnB);

        // --- cam_use (cross attention) via pipelined tf32 MMA ---
        camuse_mma_kernel<<<dim3(2, 2, B), 256>>>(attnB, Z[i], featZ, NZ, G[i]);
        camuse_mma_kernel<<<dim3(8, 2, B), 256>>>(attnA, X[i], featX, NX, G[i]);

        wround_kernel<<<CDIV(256 * KDIM, 256), 256>>>(DW[i], wrb, 256 * KDIM);

        // --- z branch ---
        offconv_kernel<<<dim3(CDIV(NZ, 128), 18, B), 128>>>(featZ, OW[i], OB[i], offb, 15, 15);
        sample_kernel<<<dim3(CDIV(NZ, 128), 18, B), 128>>>(featZ, offb, colb, 15, 15, NPAD_Z, NTOT_Z);
        dconv_mma_kernel<<<dim3(2, NTOT_Z / 128), 256>>>(wrb, colb,
                                                         outZ + (size_t)i * B * C * NZ,
                                                         NZ, NTOT_Z, SH_Z);
        // --- x branch ---
        offconv_kernel<<<dim3(CDIV(NX, 128), 18, B), 128>>>(featX, OW[i], OB[i], offb, 31, 31);
        sample_kernel<<<dim3(CDIV(NX, 128), 18, B), 128>>>(featX, offb, colb, 31, 31, NPAD_X, NTOT_X);
        dconv_mma_kernel<<<dim3(2, NTOT_X / 128), 256>>>(wrb, colb,
                                                         outX + (size_t)i * B * C * NX,
                                                         NX, NTOT_X, SH_X);
    }
    (void)out_size;
}

// round 10
// speedup vs baseline: 1.5440x; 1.2012x over previous
#include <cuda_runtime.h>
#include <math.h>
#include <stdint.h>

#define CDIV(a,b) (((a)+(b)-1)/(b))

static const int B  = 32;
static const int C  = 256;
static const int NZ = 225;   // 15*15
static const int NX = 961;   // 31*31
static const int KDIM = 2304; // C*9

// ---------------- scratch (device globals; no cudaMalloc allowed) ----------
__device__ float g_attnA[32 * 256 * 256];
__device__ float g_attnB[32 * 256 * 256];
__device__ float g_featZ[32 * 256 * 225];
__device__ float g_featX[32 * 256 * 961];
__device__ float g_off4 [8 * 32 * 18 * 961];  // 8 channel-chunk partial planes (17.7 MB)
__device__ float g_col  [2304 * 32 * 1024];   // padded im2col (302 MB)
__device__ float g_wr   [256 * 2304];         // tf32-rounded weights
__device__ float g_hi   [32 * 256 * 976];     // tf32 split hi, K padded
__device__ float g_lo   [32 * 256 * 976];     // tf32 split lo, K padded

// ======================= PTX helpers =======================================
__device__ __forceinline__ uint32_t smem_u32(const void* p) {
    uint32_t a;
    asm("{ .reg .u64 t; cvta.to.shared.u64 t, %1; cvt.u32.u64 %0, t; }" : "=r"(a) : "l"(p));
    return a;
}
__device__ __forceinline__ void cpa16(uint32_t dst, const void* src) {
    asm volatile("cp.async.cg.shared.global [%0], [%1], 16;" :: "r"(dst), "l"(src));
}
__device__ __forceinline__ float round_tf32(float v) {
    uint32_t r;
    asm("cvt.rna.tf32.f32 %0, %1;" : "=r"(r) : "f"(v));
    return __uint_as_float(r);
}
__device__ __forceinline__ void mma_tf32(float& c0, float& c1, float& c2, float& c3,
                                         uint32_t a0, uint32_t a1, uint32_t a2, uint32_t a3,
                                         uint32_t b0, uint32_t b1) {
    asm volatile(
        "mma.sync.aligned.m16n8k8.row.col.f32.tf32.tf32.f32 "
        "{%0,%1,%2,%3},{%4,%5,%6,%7},{%8,%9},{%0,%1,%2,%3};"
        : "+f"(c0), "+f"(c1), "+f"(c2), "+f"(c3)
        : "r"(a0), "r"(a1), "r"(a2), "r"(a3), "r"(b0), "r"(b1));
}

// ---------------------------------------------------------------------------
// split input into tf32 hi/lo pair, K padded to Kpad (2D grid, no div/mod)
// ---------------------------------------------------------------------------
__global__ __launch_bounds__(256) void splitf_kernel(const float* __restrict__ in,
                                                     float* __restrict__ hi,
                                                     float* __restrict__ lo,
                                                     int K, int Kpad) {
    int bc = blockIdx.y;
    int k = blockIdx.x * 256 + threadIdx.x;
    if (k >= Kpad) return;
    float v = (k < K) ? in[(size_t)bc * K + k] : 0.f;
    float h = round_tf32(v);
    size_t o = (size_t)bc * Kpad + k;
    hi[o] = h;
    lo[o] = round_tf32(v - h);
}

// ---------------------------------------------------------------------------
// gram via 3xTF32: E[b] = F[b] * F[b]^T, K pre-padded (mult of 8)
// CTA 128x128, BK=8, cp.async double-buffered, 8 warps (2M x 4N)
// ---------------------------------------------------------------------------
__global__ __launch_bounds__(256) void gram_mma3_kernel(const float* __restrict__ hi,
                                                        const float* __restrict__ lo,
                                                        float* __restrict__ E, int Kpad) {
    __shared__ float Ah[2][1536], Al[2][1536], Bh[2][1536], Bl[2][1536];
    int b = blockIdx.z;
    int c0 = blockIdx.y * 128, d0 = blockIdx.x * 128;
    const size_t fb = (size_t)b * C * Kpad;
    int tid = threadIdx.x;
    int wid = tid >> 5, lane = tid & 31;
    int g = lane >> 2, t = lane & 3;
    int warpM = wid >> 2, warpN = wid & 3;

    uint32_t ahU = smem_u32(&Ah[0][0]);
    uint32_t alU = smem_u32(&Al[0][0]);
    uint32_t bhU = smem_u32(&Bh[0][0]);
    uint32_t blU = smem_u32(&Bl[0][0]);

    int lrow = tid >> 1, lhalf = tid & 1;
    auto load_stage = [&](int stg, int k0) {
        uint32_t doff = stg * 6144 + (lrow * 12 + lhalf * 4) * 4;
        const size_t sA = fb + (size_t)(c0 + lrow) * Kpad + k0 + lhalf * 4;
        const size_t sB = fb + (size_t)(d0 + lrow) * Kpad + k0 + lhalf * 4;
        cpa16(ahU + doff, hi + sA);
        cpa16(alU + doff, lo + sA);
        cpa16(bhU + doff, hi + sB);
        cpa16(blU + doff, lo + sB);
    };

    float acc[4][4][4];
#pragma unroll
    for (int i = 0; i < 4; i++)
#pragma unroll
        for (int j = 0; j < 4; j++)
#pragma unroll
            for (int r = 0; r < 4; r++) acc[i][j][r] = 0.f;

    const int ITERS = Kpad / 8;
    load_stage(0, 0);
    asm volatile("cp.async.commit_group;" ::: "memory");

    for (int it = 0; it < ITERS; it++) {
        int cur = it & 1;
        if (it + 1 < ITERS) load_stage(cur ^ 1, (it + 1) * 8);
        asm volatile("cp.async.commit_group;" ::: "memory");
        asm volatile("cp.async.wait_group 1;" ::: "memory");
        __syncthreads();

        const float* A0h = &Ah[cur][0];
        const float* A0l = &Al[cur][0];
        const float* B0h = &Bh[cur][0];
        const float* B0l = &Bl[cur][0];

        uint32_t ah[4][4], al[4][4];
#pragma unroll
        for (int mt = 0; mt < 4; mt++) {
            int m = warpM * 64 + mt * 16 + g;
            ah[mt][0] = __float_as_uint(A0h[m * 12 + t]);
            ah[mt][1] = __float_as_uint(A0h[(m + 8) * 12 + t]);
            ah[mt][2] = __float_as_uint(A0h[m * 12 + t + 4]);
            ah[mt][3] = __float_as_uint(A0h[(m + 8) * 12 + t + 4]);
            al[mt][0] = __float_as_uint(A0l[m * 12 + t]);
            al[mt][1] = __float_as_uint(A0l[(m + 8) * 12 + t]);
            al[mt][2] = __float_as_uint(A0l[m * 12 + t + 4]);
            al[mt][3] = __float_as_uint(A0l[(m + 8) * 12 + t + 4]);
        }
        uint32_t bh[4][2], bl[4][2];
#pragma unroll
        for (int nt = 0; nt < 4; nt++) {
            int n = warpN * 32 + nt * 8 + g;
            bh[nt][0] = __float_as_uint(B0h[n * 12 + t]);
            bh[nt][1] = __float_as_uint(B0h[n * 12 + t + 4]);
            bl[nt][0] = __float_as_uint(B0l[n * 12 + t]);
            bl[nt][1] = __float_as_uint(B0l[n * 12 + t + 4]);
        }
#pragma unroll
        for (int mt = 0; mt < 4; mt++)
#pragma unroll
            for (int nt = 0; nt < 4; nt++) {
                mma_tf32(acc[mt][nt][0], acc[mt][nt][1], acc[mt][nt][2], acc[mt][nt][3],
                         ah[mt][0], ah[mt][1], ah[mt][2], ah[mt][3],
                         bh[nt][0], bh[nt][1]);
                mma_tf32(acc[mt][nt][0], acc[mt][nt][1], acc[mt][nt][2], acc[mt][nt][3],
                         ah[mt][0], ah[mt][1], ah[mt][2], ah[mt][3],
                         bl[nt][0], bl[nt][1]);
                mma_tf32(acc[mt][nt][0], acc[mt][nt][1], acc[mt][nt][2], acc[mt][nt][3],
                         al[mt][0], al[mt][1], al[mt][2], al[mt][3],
                         bh[nt][0], bh[nt][1]);
            }
        __syncthreads();
    }

    float* Eb = E + (size_t)b * C * C;
#pragma unroll
    for (int mt = 0; mt < 4; mt++) {
        int m = c0 + warpM * 64 + mt * 16 + g;
#pragma unroll
        for (int nt = 0; nt < 4; nt++) {
            int n = d0 + warpN * 32 + nt * 8 + t * 2;
            Eb[(size_t)m * C + n]           = acc[mt][nt][0];
            Eb[(size_t)m * C + n + 1]       = acc[mt][nt][1];
            Eb[(size_t)(m + 8) * C + n]     = acc[mt][nt][2];
            Eb[(size_t)(m + 8) * C + n + 1] = acc[mt][nt][3];
        }
    }
}

// ---------------------------------------------------------------------------
// softmax of (rowmax - e) == exp(rowmin - e)/sum  (shuffle reductions)
// ---------------------------------------------------------------------------
__global__ __launch_bounds__(256) void attn_softmax_kernel(float* __restrict__ E) {
    int row = blockIdx.x;
    float* e = E + (size_t)row * 256;
    int t = threadIdx.x;
    int warp = t >> 5, lane = t & 31;
    __shared__ float sm[16];
    float v = e[t];
    float m = v;
#pragma unroll
    for (int s = 16; s > 0; s >>= 1) m = fminf(m, __shfl_xor_sync(0xffffffffu, m, s));
    if (lane == 0) sm[warp] = m;
    __syncthreads();
    float emin = fminf(fminf(fminf(sm[0], sm[1]), fminf(sm[2], sm[3])),
                       fminf(fminf(sm[4], sm[5]), fminf(sm[6], sm[7])));
    float p = expf(emin - v);
    float sum = p;
#pragma unroll
    for (int s = 16; s > 0; s >>= 1) sum += __shfl_xor_sync(0xffffffffu, sum, s);
    if (lane == 0) sm[8 + warp] = sum;
    __syncthreads();
    float tot = (sm[8] + sm[9]) + (sm[10] + sm[11]) + (sm[12] + sm[13]) + (sm[14] + sm[15]);
    e[t] = p / tot;
}

// ---------------------------------------------------------------------------
// cam_use via tf32 MMA: O[b] = gamma * A[b] @ F[b] + F[b]
// CTA 128x128, BK=8, A via cp.async double-buffer, B via guarded LDG+STS
// ---------------------------------------------------------------------------
__global__ __launch_bounds__(256) void camuse_mma_kernel(const float* __restrict__ A,
                                                         const float* __restrict__ F,
                                                         float* __restrict__ O, int N,
                                                         const float* __restrict__ gamma) {
    __shared__ float sA[2][1536];    // 128 x 8 (stride 12)
    __shared__ float sB[2][1088];    // 8 x 128 (stride 136)
    int b = blockIdx.z;
    int m0 = blockIdx.y * 128, n0 = blockIdx.x * 128;
    const float* Ab = A + (size_t)b * C * C;
    const float* Fb = F + (size_t)b * C * N;
    int tid = threadIdx.x;
    int wid = tid >> 5, lane = tid & 31;
    int g = lane >> 2, t = lane & 3;
    int warpM = wid >> 2, warpN = wid & 3;

    uint32_t sAu = smem_u32(&sA[0][0]);
    int lrow = tid >> 1, lhalf = tid & 1;

    auto load_stage = [&](int stg, int k0) {
        cpa16(sAu + stg * 6144 + (lrow * 12 + lhalf * 4) * 4,
              Ab + (size_t)(m0 + lrow) * C + k0 + lhalf * 4);
#pragma unroll
        for (int i = 0; i < 4; i++) {
            int idx = tid + i * 256;
            int r = idx >> 7, cc = idx & 127;
            int n = n0 + cc;
            sB[stg][r * 136 + cc] = (n < N) ? round_tf32(Fb[(size_t)(k0 + r) * N + n]) : 0.f;
        }
    };

    float acc[4][4][4];
#pragma unroll
    for (int i = 0; i < 4; i++)
#pragma unroll
        for (int j = 0; j < 4; j++)
#pragma unroll
            for (int r = 0; r < 4; r++) acc[i][j][r] = 0.f;

    const int ITERS = C / 8;   // 32
    load_stage(0, 0);
    asm volatile("cp.async.commit_group;" ::: "memory");

    for (int it = 0; it < ITERS; it++) {
        int cur = it & 1;
        if (it + 1 < ITERS) load_stage(cur ^ 1, (it + 1) * 8);
        asm volatile("cp.async.commit_group;" ::: "memory");
        asm volatile("cp.async.wait_group 1;" ::: "memory");
        __syncthreads();

        const float* A0 = &sA[cur][0];
        const float* B0 = &sB[cur][0];
        uint32_t af[4][4];
#pragma unroll
        for (int mt = 0; mt < 4; mt++) {
            int m = warpM * 64 + mt * 16 + g;
            af[mt][0] = __float_as_uint(A0[m * 12 + t]);
            af[mt][1] = __float_as_uint(A0[(m + 8) * 12 + t]);
            af[mt][2] = __float_as_uint(A0[m * 12 + t + 4]);
            af[mt][3] = __float_as_uint(A0[(m + 8) * 12 + t + 4]);
        }
        uint32_t bf[4][2];
#pragma unroll
        for (int nt = 0; nt < 4; nt++) {
            int n = warpN * 32 + nt * 8 + g;
            bf[nt][0] = __float_as_uint(B0[t * 136 + n]);
            bf[nt][1] = __float_as_uint(B0[(t + 4) * 136 + n]);
        }
#pragma unroll
        for (int mt = 0; mt < 4; mt++)
#pragma unroll
            for (int nt = 0; nt < 4; nt++)
                mma_tf32(acc[mt][nt][0], acc[mt][nt][1], acc[mt][nt][2], acc[mt][nt][3],
                         af[mt][0], af[mt][1], af[mt][2], af[mt][3],
                         bf[nt][0], bf[nt][1]);
        __syncthreads();
    }

    float gm = gamma[0];
#pragma unroll
    for (int mt = 0; mt < 4; mt++) {
        int m = m0 + warpM * 64 + mt * 16 + g;
#pragma unroll
        for (int nt = 0; nt < 4; nt++) {
            int n = n0 + warpN * 32 + nt * 8 + t * 2;
            if (n < N) {
                O[((size_t)b * C + m) * N + n] = gm * acc[mt][nt][0] + Fb[(size_t)m * N + n];
                O[((size_t)b * C + m + 8) * N + n] = gm * acc[mt][nt][2] + Fb[(size_t)(m + 8) * N + n];
                if (n + 1 < N) {
                    O[((size_t)b * C + m) * N + n + 1] = gm * acc[mt][nt][1] + Fb[(size_t)m * N + n + 1];
                    O[((size_t)b * C + m + 8) * N + n + 1] = gm * acc[mt][nt][3] + Fb[(size_t)(m + 8) * N + n + 1];
                }
            }
        }
    }
}

// ---------------------------------------------------------------------------
// offset conv, channel-chunked: each block computes ALL 18 outputs over a
// 32-channel slice; partials to off4[chunk][b][18][N].  grid (ntile, 8, B).
// Feature reads now 1x (vs 18x), gathers stay coalesced, 1 px/thread.
// ---------------------------------------------------------------------------
__global__ __launch_bounds__(128) void offconv_chunk_kernel(const float* __restrict__ feat,
                                                            const float* __restrict__ woff,
                                                            float* __restrict__ off4,
                                                            int H, int W) {
    __shared__ float sw[32 * 9 * 20];   // [cc][tap][ch(pad20)] = 23 KB
    int chunk = blockIdx.y, b = blockIdx.z;
    int c0 = chunk * 32;
    for (int i = threadIdx.x; i < 32 * 9 * 18; i += 128) {
        int ch = i % 18;
        int rem = i / 18;
        int tap = rem % 9, cc = rem / 9;
        sw[(cc * 9 + tap) * 20 + ch] = woff[(size_t)ch * 2304 + (c0 + cc) * 9 + tap];
    }
    __syncthreads();
    int N = H * W;
    int n = blockIdx.x * 128 + threadIdx.x;
    if (n >= N) return;
    int h = n / W, w = n % W;
    int idx[9];
#pragma unroll
    for (int tap = 0; tap < 9; tap++) {
        int y = h + tap / 3 - 1, x = w + tap % 3 - 1;
        idx[tap] = ((unsigned)y < (unsigned)H && (unsigned)x < (unsigned)W) ? y * W + x : -1;
    }
    float acc[18];
#pragma unroll
    for (int ch = 0; ch < 18; ch++) acc[ch] = 0.f;

    const float* fb = feat + ((size_t)b * C + c0) * N;
    for (int cc = 0; cc < 32; cc++) {
        const float* fc = fb + (size_t)cc * N;
        float f[9];
#pragma unroll
        for (int tap = 0; tap < 9; tap++) f[tap] = (idx[tap] >= 0) ? fc[idx[tap]] : 0.f;
        const float* wp = sw + cc * 180;
#pragma unroll
        for (int tap = 0; tap < 9; tap++) {
            const float* wt = wp + tap * 20;
            float fv = f[tap];
#pragma unroll
            for (int ch = 0; ch < 18; ch++) acc[ch] += wt[ch] * fv;
        }
    }
    float* op = off4 + (((size_t)chunk * B + b) * 18) * N + n;
#pragma unroll
    for (int ch = 0; ch < 18; ch++) op[(size_t)ch * N] = acc[ch];
}

// ---------------------------------------------------------------------------
// bilinear deform sampling -> padded im2col, tf32-rounded values
// offsets = bias + sum of 8 chunk partials.  channel-split grid y = cslice*9+k
// ---------------------------------------------------------------------------
__global__ __launch_bounds__(128) void sample_kernel(const float* __restrict__ feat,
                                                     const float* __restrict__ off4,
                                                     const float* __restrict__ boff,
                                                     float* __restrict__ col,
                                                     int H, int W, int Npad, int NtotPad) {
    int N = H * W;
    int b = blockIdx.z;
    int k = blockIdx.y % 9;
    int c0 = (blockIdx.y / 9) * 128;     // 0 or 128
    int n = blockIdx.x * 128 + threadIdx.x;
    if (n >= N) return;
    int h = n / W, w = n % W;
    int ky = k / 3, kx = k % 3;

    const size_t cst = (size_t)B * 18 * N;   // chunk stride
    const float* p = off4 + ((size_t)b * 18 + 2 * k) * N + n;
    float oy = __ldg(&boff[2 * k]);
    float ox = __ldg(&boff[2 * k + 1]);
#pragma unroll
    for (int q = 0; q < 8; q++) {
        oy += p[(size_t)q * cst];
        ox += p[(size_t)q * cst + N];
    }

    float py = (float)(h + ky - 1) + oy;
    float px = (float)(w + kx - 1) + ox;
    float y0f = floorf(py), x0f = floorf(px);
    float ly = py - y0f, lx = px - x0f;
    float Hm1 = (float)(H - 1), Wm1 = (float)(W - 1);

    float vy0 = (y0f >= 0.f && y0f <= Hm1) ? (1.f - ly) : 0.f;
    float vy1 = (y0f + 1.f >= 0.f && y0f + 1.f <= Hm1) ? ly : 0.f;
    float vx0 = (x0f >= 0.f && x0f <= Wm1) ? (1.f - lx) : 0.f;
    float vx1 = (x0f + 1.f >= 0.f && x0f + 1.f <= Wm1) ? lx : 0.f;
    int y0 = (int)fminf(fmaxf(y0f, 0.f), Hm1);
    int y1 = (int)fminf(fmaxf(y0f + 1.f, 0.f), Hm1);
    int x0 = (int)fminf(fmaxf(x0f, 0.f), Wm1);
    int x1 = (int)fminf(fmaxf(x0f + 1.f, 0.f), Wm1);

    int i00 = y0 * W + x0, i01 = y0 * W + x1, i10 = y1 * W + x0, i11 = y1 * W + x1;
    float w00 = vy0 * vx0, w01 = vy0 * vx1, w10 = vy1 * vx0, w11 = vy1 * vx1;

    const float* fb = feat + ((size_t)b * C + c0) * N;
    float* cp = col + (size_t)(c0 * 9 + k) * NtotPad + (size_t)b * Npad + n;
    const size_t cstride = (size_t)9 * NtotPad;
    for (int c = 0; c < 128; c++) {
        const float* fc = fb + (size_t)c * N;
        float v = w00 * fc[i00] + w01 * fc[i01] + w10 * fc[i10] + w11 * fc[i11];
        cp[(size_t)c * cstride] = round_tf32(v);
    }
}

// ---------------------------------------------------------------------------
// round W to tf32 once per scale
// ---------------------------------------------------------------------------
__global__ __launch_bounds__(256) void wround_kernel(const float* __restrict__ in,
                                                     float* __restrict__ out, int n) {
    int i = blockIdx.x * 256 + threadIdx.x;
    if (i < n) out[i] = round_tf32(in[i]);
}

// ---------------------------------------------------------------------------
// tf32 mma.sync GEMM:  out = W[256 x 2304] @ col[2304 x NtotPad]
// CTA 128x128, BK=16, 8 warps (2M x 4N), warp tile 64x32, double-buffer cp.async
// grid (2, NTOT/128): m on x so sibling m-tiles share the col tile via L2
// ---------------------------------------------------------------------------
#define A_STRIDE 20
#define B_STRIDE 136

__global__ __launch_bounds__(256) void dconv_mma_kernel(const float* __restrict__ Wm,
                                                        const float* __restrict__ Bc,
                                                        float* __restrict__ out,
                                                        int Nsp, int NtotPad, int shift) {
    __shared__ float sA[2][128 * A_STRIDE];
    __shared__ float sB[2][16 * B_STRIDE];

    int tid = threadIdx.x;
    int wid = tid >> 5, lane = tid & 31;
    int g = lane >> 2, t = lane & 3;
    int warpM = wid >> 2;
    int warpN = wid & 3;

    int m0 = blockIdx.x * 128;
    int n0 = blockIdx.y * 128;
    int bb = n0 >> shift;
    int nl0 = n0 & ((1 << shift) - 1);

    uint32_t sAu = smem_u32(&sA[0][0]);
    uint32_t sBu = smem_u32(&sB[0][0]);

    auto load_stage = [&](int stg, int k0) {
        uint32_t aBase = sAu + stg * (128 * A_STRIDE * 4);
        uint32_t bBase = sBu + stg * (16 * B_STRIDE * 4);
#pragma unroll
        for (int i = 0; i < 2; i++) {
            int q = tid + i * 256;
            int row = q >> 2, c16 = q & 3;
            cpa16(aBase + (row * A_STRIDE + c16 * 4) * 4,
                  Wm + (size_t)(m0 + row) * KDIM + k0 + c16 * 4);
        }
#pragma unroll
        for (int i = 0; i < 2; i++) {
            int q = tid + i * 256;
            int row = q >> 5, c = q & 31;
            cpa16(bBase + (row * B_STRIDE + c * 4) * 4,
                  Bc + (size_t)(k0 + row) * NtotPad + n0 + c * 4);
        }
    };

    float acc[4][4][4];
#pragma unroll
    for (int i = 0; i < 4; i++)
#pragma unroll
        for (int j = 0; j < 4; j++)
#pragma unroll
            for (int r = 0; r < 4; r++) acc[i][j][r] = 0.f;

    const int ITERS = KDIM / 16;   // 144
    load_stage(0, 0);
    asm volatile("cp.async.commit_group;" ::: "memory");

    for (int it = 0; it < ITERS; ++it) {
        int cur = it & 1;
        if (it + 1 < ITERS) load_stage(cur ^ 1, (it + 1) * 16);
        asm volatile("cp.async.commit_group;" ::: "memory");
        asm volatile("cp.async.wait_group 1;" ::: "memory");
        __syncthreads();

        const float* A0 = &sA[cur][0];
        const float* B0 = &sB[cur][0];
#pragma unroll
        for (int ks = 0; ks < 2; ks++) {
            int kb = ks * 8;
            uint32_t af[4][4];
#pragma unroll
            for (int mt = 0; mt < 4; mt++) {
                int m = warpM * 64 + mt * 16 + g;
                af[mt][0] = __float_as_uint(A0[m * A_STRIDE + kb + t]);
                af[mt][1] = __float_as_uint(A0[(m + 8) * A_STRIDE + kb + t]);
                af[mt][2] = __float_as_uint(A0[m * A_STRIDE + kb + t + 4]);
                af[mt][3] = __float_as_uint(A0[(m + 8) * A_STRIDE + kb + t + 4]);
            }
            uint32_t bf[4][2];
#pragma unroll
            for (int nt = 0; nt < 4; nt++) {
                int n = warpN * 32 + nt * 8 + g;
                bf[nt][0] = __float_as_uint(B0[(kb + t) * B_STRIDE + n]);
                bf[nt][1] = __float_as_uint(B0[(kb + t + 4) * B_STRIDE + n]);
            }
#pragma unroll
            for (int mt = 0; mt < 4; mt++)
#pragma unroll
                for (int nt = 0; nt < 4; nt++)
                    mma_tf32(acc[mt][nt][0], acc[mt][nt][1], acc[mt][nt][2], acc[mt][nt][3],
                             af[mt][0], af[mt][1], af[mt][2], af[mt][3],
                             bf[nt][0], bf[nt][1]);
        }
        __syncthreads();
    }

#pragma unroll
    for (int mt = 0; mt < 4; mt++) {
        int m = m0 + warpM * 64 + mt * 16 + g;
        float* r0 = out + ((size_t)bb * C + m) * Nsp;
        float* r1 = out + ((size_t)bb * C + m + 8) * Nsp;
#pragma unroll
        for (int nt = 0; nt < 4; nt++) {
            int n = nl0 + warpN * 32 + nt * 8 + t * 2;
            if (n < Nsp) {
                r0[n] = acc[mt][nt][0];
                r1[n] = acc[mt][nt][2];
                if (n + 1 < Nsp) {
                    r0[n + 1] = acc[mt][nt][1];
                    r1[n + 1] = acc[mt][nt][3];
                }
            }
        }
    }
}

// ---------------------------------------------------------------------------
extern "C" void kernel_launch(void* const* d_in, const int* in_sizes, int n_in,
                              void* d_out, int out_size) {
    const float *Z[3], *X[3], *OW[3], *OB[3], *DW[3], *G[3];
    int nz = 0, nx = 0, nw = 0, nb = 0, nd = 0, ng = 0;
    for (int i = 0; i < n_in; i++) {
        switch (in_sizes[i]) {
            case 1843200: Z[nz++]  = (const float*)d_in[i]; break;
            case 7872512: X[nx++]  = (const float*)d_in[i]; break;
            case 41472:   OW[nw++] = (const float*)d_in[i]; break;
            case 18:      OB[nb++] = (const float*)d_in[i]; break;
            case 589824:  DW[nd++] = (const float*)d_in[i]; break;
            case 1:       G[ng++]  = (const float*)d_in[i]; break;
            default: break;
        }
    }

    float *attnA, *attnB, *featZ, *featX, *off4b, *colb, *wrb, *hib, *lob;
    cudaGetSymbolAddress((void**)&attnA, g_attnA);
    cudaGetSymbolAddress((void**)&attnB, g_attnB);
    cudaGetSymbolAddress((void**)&featZ, g_featZ);
    cudaGetSymbolAddress((void**)&featX, g_featX);
    cudaGetSymbolAddress((void**)&off4b, g_off4);
    cudaGetSymbolAddress((void**)&colb,  g_col);
    cudaGetSymbolAddress((void**)&wrb,   g_wr);
    cudaGetSymbolAddress((void**)&hib,   g_hi);
    cudaGetSymbolAddress((void**)&lob,   g_lo);

    float* outZ = (float*)d_out;
    float* outX = outZ + (size_t)3 * B * C * NZ;

    const int NPAD_Z = 256,  SH_Z = 8;
    const int NPAD_X = 1024, SH_X = 10;
    const int NTOT_Z = B * NPAD_Z;   // 8192
    const int NTOT_X = B * NPAD_X;   // 32768
    const int KP_Z = 240;
    const int KP_X = 976;

    for (int i = 0; i < 3; i++) {
        // --- channel attention (gram via pipelined 3xTF32) ---
        splitf_kernel<<<dim3(CDIV(KP_Z, 256), B * C), 256>>>(Z[i], hib, lob, NZ, KP_Z);
        gram_mma3_kernel<<<dim3(2, 2, B), 256>>>(hib, lob, attnA, KP_Z);
        attn_softmax_kernel<<<B * C, 256>>>(attnA);
        splitf_kernel<<<dim3(CDIV(KP_X, 256), B * C), 256>>>(X[i], hib, lob, NX, KP_X);
        gram_mma3_kernel<<<dim3(2, 2, B), 256>>>(hib, lob, attnB, KP_X);
        attn_softmax_kernel<<<B * C, 256>>>(attnB);

        // --- cam_use (cross attention) via pipelined tf32 MMA ---
        camuse_mma_kernel<<<dim3(2, 2, B), 256>>>(attnB, Z[i], featZ, NZ, G[i]);
        camuse_mma_kernel<<<dim3(8, 2, B), 256>>>(attnA, X[i], featX, NX, G[i]);

        wround_kernel<<<CDIV(256 * KDIM, 256), 256>>>(DW[i], wrb, 256 * KDIM);

        // --- z branch ---
        offconv_chunk_kernel<<<dim3(CDIV(NZ, 128), 8, B), 128>>>(featZ, OW[i], off4b, 15, 15);
        sample_kernel<<<dim3(CDIV(NZ, 128), 18, B), 128>>>(featZ, off4b, OB[i], colb,
                                                           15, 15, NPAD_Z, NTOT_Z);
        dconv_mma_kernel<<<dim3(2, NTOT_Z / 128), 256>>>(wrb, colb,
                                                         outZ + (size_t)i * B * C * NZ,
                                                         NZ, NTOT_Z, SH_Z);
        // --- x branch ---
        offconv_chunk_kernel<<<dim3(CDIV(NX, 128), 8, B), 128>>>(featX, OW[i], off4b, 31, 31);
        sample_kernel<<<dim3(CDIV(NX, 128), 18, B), 128>>>(featX, off4b, OB[i], colb,
                                                           31, 31, NPAD_X, NTOT_X);
        dconv_mma_kernel<<<dim3(2, NTOT_X / 128), 256>>>(wrb, colb,
                                                         outX + (size_t)i * B * C * NX,
                                                         NX, NTOT_X, SH_X);
    }
    (void)out_size;
}

// round 11
// speedup vs baseline: 1.6572x; 1.0733x over previous
#include <cuda_runtime.h>
#include <math.h>
#include <stdint.h>

#define CDIV(a,b) (((a)+(b)-1)/(b))

static const int B  = 32;
static const int C  = 256;
static const int NZ = 225;   // 15*15
static const int NX = 961;   // 31*31
static const int KDIM = 2304; // C*9

static const int KPX = 976;          // x K padded
static const int KPZ = 240;          // z K padded
static const int NPAD_Z = 256,  SH_Z = 8;
static const int NPAD_X = 1024, SH_X = 10;
static const int ZCOLS = 32 * 256;   // 8192 (z region width)
static const int XCOLS = 32 * 1024;  // 32768
static const int NTOTP = ZCOLS + XCOLS;  // 40960 combined col width

// ---------------- scratch (device globals; no cudaMalloc allowed) ----------
__device__ float g_attnA[32 * 256 * 256];        // z gram/attn
__device__ float g_attnB[32 * 256 * 256];        // x gram/attn
__device__ float g_featZ[32 * 256 * 225];
__device__ float g_featX[32 * 256 * 961];
__device__ float g_off4x[8 * 32 * 18 * 961];     // x offconv partials
__device__ float g_off4z[8 * 32 * 18 * 225];     // z offconv partials
__device__ float g_col  [2304 * 40960];          // merged im2col (377 MB)
__device__ float g_wr   [256 * 2304];
__device__ float g_hix  [32 * 256 * 976];
__device__ float g_lox  [32 * 256 * 976];
__device__ float g_hiz  [32 * 256 * 240];
__device__ float g_loz  [32 * 256 * 240];

// ======================= PTX helpers =======================================
__device__ __forceinline__ uint32_t smem_u32(const void* p) {
    uint32_t a;
    asm("{ .reg .u64 t; cvta.to.shared.u64 t, %1; cvt.u32.u64 %0, t; }" : "=r"(a) : "l"(p));
    return a;
}
__device__ __forceinline__ void cpa16(uint32_t dst, const void* src) {
    asm volatile("cp.async.cg.shared.global [%0], [%1], 16;" :: "r"(dst), "l"(src));
}
__device__ __forceinline__ float round_tf32(float v) {
    uint32_t r;
    asm("cvt.rna.tf32.f32 %0, %1;" : "=r"(r) : "f"(v));
    return __uint_as_float(r);
}
__device__ __forceinline__ void mma_tf32(float& c0, float& c1, float& c2, float& c3,
                                         uint32_t a0, uint32_t a1, uint32_t a2, uint32_t a3,
                                         uint32_t b0, uint32_t b1) {
    asm volatile(
        "mma.sync.aligned.m16n8k8.row.col.f32.tf32.tf32.f32 "
        "{%0,%1,%2,%3},{%4,%5,%6,%7},{%8,%9},{%0,%1,%2,%3};"
        : "+f"(c0), "+f"(c1), "+f"(c2), "+f"(c3)
        : "r"(a0), "r"(a1), "r"(a2), "r"(a3), "r"(b0), "r"(b1));
}

// ---------------------------------------------------------------------------
// merged tf32 split: grid (4, 2*B*C); y < B*C -> x branch, else z
// ---------------------------------------------------------------------------
__global__ __launch_bounds__(256) void splitf_kernel(const float* __restrict__ inX,
                                                     const float* __restrict__ inZ,
                                                     float* __restrict__ hiX,
                                                     float* __restrict__ loX,
                                                     float* __restrict__ hiZ,
                                                     float* __restrict__ loZ) {
    int y = blockIdx.y;
    const float* in; float* hi; float* lo; int K, Kpad, bc;
    if (y < B * C) { in = inX; hi = hiX; lo = loX; K = NX; Kpad = KPX; bc = y; }
    else           { in = inZ; hi = hiZ; lo = loZ; K = NZ; Kpad = KPZ; bc = y - B * C; }
    int k = blockIdx.x * 256 + threadIdx.x;
    if (k >= Kpad) return;
    float v = (k < K) ? in[(size_t)bc * K + k] : 0.f;
    float h = round_tf32(v);
    size_t o = (size_t)bc * Kpad + k;
    hi[o] = h;
    lo[o] = round_tf32(v - h);
}

// ---------------------------------------------------------------------------
// merged gram via 3xTF32: grid (2,2,64); z-dim < 32 -> x, else z
// ---------------------------------------------------------------------------
__global__ __launch_bounds__(256) void gram_mma3_kernel(const float* __restrict__ hiX,
                                                        const float* __restrict__ loX,
                                                        const float* __restrict__ hiZ,
                                                        const float* __restrict__ loZ,
                                                        float* __restrict__ Ex,
                                                        float* __restrict__ Ez) {
    __shared__ float Ah[2][1536], Al[2][1536], Bh[2][1536], Bl[2][1536];
    const float* hi; const float* lo; float* E; int Kpad, b;
    if (blockIdx.z < 32) { hi = hiX; lo = loX; E = Ex; Kpad = KPX; b = blockIdx.z; }
    else                 { hi = hiZ; lo = loZ; E = Ez; Kpad = KPZ; b = blockIdx.z - 32; }
    int c0 = blockIdx.y * 128, d0 = blockIdx.x * 128;
    const size_t fb = (size_t)b * C * Kpad;
    int tid = threadIdx.x;
    int wid = tid >> 5, lane = tid & 31;
    int g = lane >> 2, t = lane & 3;
    int warpM = wid >> 2, warpN = wid & 3;

    uint32_t ahU = smem_u32(&Ah[0][0]);
    uint32_t alU = smem_u32(&Al[0][0]);
    uint32_t bhU = smem_u32(&Bh[0][0]);
    uint32_t blU = smem_u32(&Bl[0][0]);

    int lrow = tid >> 1, lhalf = tid & 1;
    auto load_stage = [&](int stg, int k0) {
        uint32_t doff = stg * 6144 + (lrow * 12 + lhalf * 4) * 4;
        const size_t sA = fb + (size_t)(c0 + lrow) * Kpad + k0 + lhalf * 4;
        const size_t sB = fb + (size_t)(d0 + lrow) * Kpad + k0 + lhalf * 4;
        cpa16(ahU + doff, hi + sA);
        cpa16(alU + doff, lo + sA);
        cpa16(bhU + doff, hi + sB);
        cpa16(blU + doff, lo + sB);
    };

    float acc[4][4][4];
#pragma unroll
    for (int i = 0; i < 4; i++)
#pragma unroll
        for (int j = 0; j < 4; j++)
#pragma unroll
            for (int r = 0; r < 4; r++) acc[i][j][r] = 0.f;

    const int ITERS = Kpad / 8;
    load_stage(0, 0);
    asm volatile("cp.async.commit_group;" ::: "memory");

    for (int it = 0; it < ITERS; it++) {
        int cur = it & 1;
        if (it + 1 < ITERS) load_stage(cur ^ 1, (it + 1) * 8);
        asm volatile("cp.async.commit_group;" ::: "memory");
        asm volatile("cp.async.wait_group 1;" ::: "memory");
        __syncthreads();

        const float* A0h = &Ah[cur][0];
        const float* A0l = &Al[cur][0];
        const float* B0h = &Bh[cur][0];
        const float* B0l = &Bl[cur][0];

        uint32_t ah[4][4], al[4][4];
#pragma unroll
        for (int mt = 0; mt < 4; mt++) {
            int m = warpM * 64 + mt * 16 + g;
            ah[mt][0] = __float_as_uint(A0h[m * 12 + t]);
            ah[mt][1] = __float_as_uint(A0h[(m + 8) * 12 + t]);
            ah[mt][2] = __float_as_uint(A0h[m * 12 + t + 4]);
            ah[mt][3] = __float_as_uint(A0h[(m + 8) * 12 + t + 4]);
            al[mt][0] = __float_as_uint(A0l[m * 12 + t]);
            al[mt][1] = __float_as_uint(A0l[(m + 8) * 12 + t]);
            al[mt][2] = __float_as_uint(A0l[m * 12 + t + 4]);
            al[mt][3] = __float_as_uint(A0l[(m + 8) * 12 + t + 4]);
        }
        uint32_t bh[4][2], bl[4][2];
#pragma unroll
        for (int nt = 0; nt < 4; nt++) {
            int n = warpN * 32 + nt * 8 + g;
            bh[nt][0] = __float_as_uint(B0h[n * 12 + t]);
            bh[nt][1] = __float_as_uint(B0h[n * 12 + t + 4]);
            bl[nt][0] = __float_as_uint(B0l[n * 12 + t]);
            bl[nt][1] = __float_as_uint(B0l[n * 12 + t + 4]);
        }
#pragma unroll
        for (int mt = 0; mt < 4; mt++)
#pragma unroll
            for (int nt = 0; nt < 4; nt++) {
                mma_tf32(acc[mt][nt][0], acc[mt][nt][1], acc[mt][nt][2], acc[mt][nt][3],
                         ah[mt][0], ah[mt][1], ah[mt][2], ah[mt][3],
                         bh[nt][0], bh[nt][1]);
                mma_tf32(acc[mt][nt][0], acc[mt][nt][1], acc[mt][nt][2], acc[mt][nt][3],
                         ah[mt][0], ah[mt][1], ah[mt][2], ah[mt][3],
                         bl[nt][0], bl[nt][1]);
                mma_tf32(acc[mt][nt][0], acc[mt][nt][1], acc[mt][nt][2], acc[mt][nt][3],
                         al[mt][0], al[mt][1], al[mt][2], al[mt][3],
                         bh[nt][0], bh[nt][1]);
            }
        __syncthreads();
    }

    float* Eb = E + (size_t)b * C * C;
#pragma unroll
    for (int mt = 0; mt < 4; mt++) {
        int m = c0 + warpM * 64 + mt * 16 + g;
#pragma unroll
        for (int nt = 0; nt < 4; nt++) {
            int n = d0 + warpN * 32 + nt * 8 + t * 2;
            Eb[(size_t)m * C + n]           = acc[mt][nt][0];
            Eb[(size_t)m * C + n + 1]       = acc[mt][nt][1];
            Eb[(size_t)(m + 8) * C + n]     = acc[mt][nt][2];
            Eb[(size_t)(m + 8) * C + n + 1] = acc[mt][nt][3];
        }
    }
}

// ---------------------------------------------------------------------------
// merged softmax: grid 2*B*C; row < B*C -> Ex else Ez
// ---------------------------------------------------------------------------
__global__ __launch_bounds__(256) void attn_softmax_kernel(float* __restrict__ Ex,
                                                           float* __restrict__ Ez) {
    int row = blockIdx.x;
    float* e = (row < B * C) ? Ex + (size_t)row * 256
                             : Ez + (size_t)(row - B * C) * 256;
    int t = threadIdx.x;
    int warp = t >> 5, lane = t & 31;
    __shared__ float sm[16];
    float v = e[t];
    float m = v;
#pragma unroll
    for (int s = 16; s > 0; s >>= 1) m = fminf(m, __shfl_xor_sync(0xffffffffu, m, s));
    if (lane == 0) sm[warp] = m;
    __syncthreads();
    float emin = fminf(fminf(fminf(sm[0], sm[1]), fminf(sm[2], sm[3])),
                       fminf(fminf(sm[4], sm[5]), fminf(sm[6], sm[7])));
    float p = expf(emin - v);
    float sum = p;
#pragma unroll
    for (int s = 16; s > 0; s >>= 1) sum += __shfl_xor_sync(0xffffffffu, sum, s);
    if (lane == 0) sm[8 + warp] = sum;
    __syncthreads();
    float tot = (sm[8] + sm[9]) + (sm[10] + sm[11]) + (sm[12] + sm[13]) + (sm[14] + sm[15]);
    e[t] = p / tot;
}

// ---------------------------------------------------------------------------
// merged cam_use via tf32 MMA: grid (8,2,64); z<32 -> x branch, else z
// x: A=attnA(z gram), F=X; z: A=attnB(x gram), F=Z  (cross attention)
// ---------------------------------------------------------------------------
__global__ __launch_bounds__(256) void camuse_mma_kernel(const float* __restrict__ attnA,
                                                         const float* __restrict__ attnB,
                                                         const float* __restrict__ Xf,
                                                         const float* __restrict__ Zf,
                                                         float* __restrict__ featX,
                                                         float* __restrict__ featZ,
                                                         const float* __restrict__ gamma) {
    const float* A; const float* F; float* O; int N, b;
    if (blockIdx.z < 32) { A = attnA; F = Xf; O = featX; N = NX; b = blockIdx.z; }
    else {
        if (blockIdx.x >= 2) return;
        A = attnB; F = Zf; O = featZ; N = NZ; b = blockIdx.z - 32;
    }
    __shared__ float sA[2][1536];    // 128 x 8 (stride 12)
    __shared__ float sB[2][1088];    // 8 x 128 (stride 136)
    int m0 = blockIdx.y * 128, n0 = blockIdx.x * 128;
    const float* Ab = A + (size_t)b * C * C;
    const float* Fb = F + (size_t)b * C * N;
    int tid = threadIdx.x;
    int wid = tid >> 5, lane = tid & 31;
    int g = lane >> 2, t = lane & 3;
    int warpM = wid >> 2, warpN = wid & 3;

    uint32_t sAu = smem_u32(&sA[0][0]);
    int lrow = tid >> 1, lhalf = tid & 1;

    auto load_stage = [&](int stg, int k0) {
        cpa16(sAu + stg * 6144 + (lrow * 12 + lhalf * 4) * 4,
              Ab + (size_t)(m0 + lrow) * C + k0 + lhalf * 4);
#pragma unroll
        for (int i = 0; i < 4; i++) {
            int idx = tid + i * 256;
            int r = idx >> 7, cc = idx & 127;
            int n = n0 + cc;
            sB[stg][r * 136 + cc] = (n < N) ? round_tf32(Fb[(size_t)(k0 + r) * N + n]) : 0.f;
        }
    };

    float acc[4][4][4];
#pragma unroll
    for (int i = 0; i < 4; i++)
#pragma unroll
        for (int j = 0; j < 4; j++)
#pragma unroll
            for (int r = 0; r < 4; r++) acc[i][j][r] = 0.f;

    const int ITERS = C / 8;   // 32
    load_stage(0, 0);
    asm volatile("cp.async.commit_group;" ::: "memory");

    for (int it = 0; it < ITERS; it++) {
        int cur = it & 1;
        if (it + 1 < ITERS) load_stage(cur ^ 1, (it + 1) * 8);
        asm volatile("cp.async.commit_group;" ::: "memory");
        asm volatile("cp.async.wait_group 1;" ::: "memory");
        __syncthreads();

        const float* A0 = &sA[cur][0];
        const float* B0 = &sB[cur][0];
        uint32_t af[4][4];
#pragma unroll
        for (int mt = 0; mt < 4; mt++) {
            int m = warpM * 64 + mt * 16 + g;
            af[mt][0] = __float_as_uint(A0[m * 12 + t]);
            af[mt][1] = __float_as_uint(A0[(m + 8) * 12 + t]);
            af[mt][2] = __float_as_uint(A0[m * 12 + t + 4]);
            af[mt][3] = __float_as_uint(A0[(m + 8) * 12 + t + 4]);
        }
        uint32_t bf[4][2];
#pragma unroll
        for (int nt = 0; nt < 4; nt++) {
            int n = warpN * 32 + nt * 8 + g;
            bf[nt][0] = __float_as_uint(B0[t * 136 + n]);
            bf[nt][1] = __float_as_uint(B0[(t + 4) * 136 + n]);
        }
#pragma unroll
        for (int mt = 0; mt < 4; mt++)
#pragma unroll
            for (int nt = 0; nt < 4; nt++)
                mma_tf32(acc[mt][nt][0], acc[mt][nt][1], acc[mt][nt][2], acc[mt][nt][3],
                         af[mt][0], af[mt][1], af[mt][2], af[mt][3],
                         bf[nt][0], bf[nt][1]);
        __syncthreads();
    }

    float gm = gamma[0];
#pragma unroll
    for (int mt = 0; mt < 4; mt++) {
        int m = m0 + warpM * 64 + mt * 16 + g;
#pragma unroll
        for (int nt = 0; nt < 4; nt++) {
            int n = n0 + warpN * 32 + nt * 8 + t * 2;
            if (n < N) {
                O[((size_t)b * C + m) * N + n] = gm * acc[mt][nt][0] + Fb[(size_t)m * N + n];
                O[((size_t)b * C + m + 8) * N + n] = gm * acc[mt][nt][2] + Fb[(size_t)(m + 8) * N + n];
                if (n + 1 < N) {
                    O[((size_t)b * C + m) * N + n + 1] = gm * acc[mt][nt][1] + Fb[(size_t)m * N + n + 1];
                    O[((size_t)b * C + m + 8) * N + n + 1] = gm * acc[mt][nt][3] + Fb[(size_t)(m + 8) * N + n + 1];
                }
            }
        }
    }
}

// ---------------------------------------------------------------------------
// merged offset conv, channel-chunked partials.  grid (8, 8, 64)
// ---------------------------------------------------------------------------
__global__ __launch_bounds__(128) void offconv_chunk_kernel(const float* __restrict__ featX,
                                                            const float* __restrict__ featZ,
                                                            const float* __restrict__ woff,
                                                            float* __restrict__ off4x,
                                                            float* __restrict__ off4z) {
    const float* feat; float* off4; int H, W, b;
    if (blockIdx.z < 32) { feat = featX; off4 = off4x; H = 31; W = 31; b = blockIdx.z; }
    else {
        if (blockIdx.x >= 2) return;
        feat = featZ; off4 = off4z; H = 15; W = 15; b = blockIdx.z - 32;
    }
    __shared__ float sw[32 * 9 * 20];
    int chunk = blockIdx.y;
    int c0 = chunk * 32;
    for (int i = threadIdx.x; i < 32 * 9 * 18; i += 128) {
        int ch = i % 18;
        int rem = i / 18;
        int tap = rem % 9, cc = rem / 9;
        sw[(cc * 9 + tap) * 20 + ch] = woff[(size_t)ch * 2304 + (c0 + cc) * 9 + tap];
    }
    __syncthreads();
    int N = H * W;
    int n = blockIdx.x * 128 + threadIdx.x;
    if (n >= N) return;
    int h = n / W, w = n % W;
    int idx[9];
#pragma unroll
    for (int tap = 0; tap < 9; tap++) {
        int y = h + tap / 3 - 1, x = w + tap % 3 - 1;
        idx[tap] = ((unsigned)y < (unsigned)H && (unsigned)x < (unsigned)W) ? y * W + x : -1;
    }
    float acc[18];
#pragma unroll
    for (int ch = 0; ch < 18; ch++) acc[ch] = 0.f;

    const float* fb = feat + ((size_t)b * C + c0) * N;
    for (int cc = 0; cc < 32; cc++) {
        const float* fc = fb + (size_t)cc * N;
        float f[9];
#pragma unroll
        for (int tap = 0; tap < 9; tap++) f[tap] = (idx[tap] >= 0) ? fc[idx[tap]] : 0.f;
        const float* wp = sw + cc * 180;
#pragma unroll
        for (int tap = 0; tap < 9; tap++) {
            const float* wt = wp + tap * 20;
            float fv = f[tap];
#pragma unroll
            for (int ch = 0; ch < 18; ch++) acc[ch] += wt[ch] * fv;
        }
    }
    float* op = off4 + (((size_t)chunk * B + b) * 18) * N + n;
#pragma unroll
    for (int ch = 0; ch < 18; ch++) op[(size_t)ch * N] = acc[ch];
}

// ---------------------------------------------------------------------------
// merged bilinear sampling -> combined im2col.  grid (8, 18, 64)
// y = cslice*9 + k;  col layout: [kdim][ zcols(8192) | xcols(32768) ]
// ---------------------------------------------------------------------------
__global__ __launch_bounds__(128) void sample_kernel(const float* __restrict__ featX,
                                                     const float* __restrict__ featZ,
                                                     const float* __restrict__ off4x,
                                                     const float* __restrict__ off4z,
                                                     const float* __restrict__ boff,
                                                     float* __restrict__ col) {
    const float* feat; const float* off4; int H, W, b, Npad, base;
    if (blockIdx.z < 32) {
        feat = featX; off4 = off4x; H = 31; W = 31; b = blockIdx.z;
        Npad = NPAD_X; base = ZCOLS;
    } else {
        if (blockIdx.x >= 2) return;
        feat = featZ; off4 = off4z; H = 15; W = 15; b = blockIdx.z - 32;
        Npad = NPAD_Z; base = 0;
    }
    int N = H * W;
    int k = blockIdx.y % 9;
    int c0 = (blockIdx.y / 9) * 128;
    int n = blockIdx.x * 128 + threadIdx.x;
    if (n >= N) return;
    int h = n / W, w = n % W;
    int ky = k / 3, kx = k % 3;

    const size_t cst = (size_t)B * 18 * N;
    const float* p = off4 + ((size_t)b * 18 + 2 * k) * N + n;
    float oy = __ldg(&boff[2 * k]);
    float ox = __ldg(&boff[2 * k + 1]);
#pragma unroll
    for (int q = 0; q < 8; q++) {
        oy += p[(size_t)q * cst];
        ox += p[(size_t)q * cst + N];
    }

    float py = (float)(h + ky - 1) + oy;
    float px = (float)(w + kx - 1) + ox;
    float y0f = floorf(py), x0f = floorf(px);
    float ly = py - y0f, lx = px - x0f;
    float Hm1 = (float)(H - 1), Wm1 = (float)(W - 1);

    float vy0 = (y0f >= 0.f && y0f <= Hm1) ? (1.f - ly) : 0.f;
    float vy1 = (y0f + 1.f >= 0.f && y0f + 1.f <= Hm1) ? ly : 0.f;
    float vx0 = (x0f >= 0.f && x0f <= Wm1) ? (1.f - lx) : 0.f;
    float vx1 = (x0f + 1.f >= 0.f && x0f + 1.f <= Wm1) ? lx : 0.f;
    int y0 = (int)fminf(fmaxf(y0f, 0.f), Hm1);
    int y1 = (int)fminf(fmaxf(y0f + 1.f, 0.f), Hm1);
    int x0 = (int)fminf(fmaxf(x0f, 0.f), Wm1);
    int x1 = (int)fminf(fmaxf(x0f + 1.f, 0.f), Wm1);

    int i00 = y0 * W + x0, i01 = y0 * W + x1, i10 = y1 * W + x0, i11 = y1 * W + x1;
    float w00 = vy0 * vx0, w01 = vy0 * vx1, w10 = vy1 * vx0, w11 = vy1 * vx1;

    const float* fb = feat + ((size_t)b * C + c0) * N;
    float* cp = col + (size_t)(c0 * 9 + k) * NTOTP + base + (size_t)b * Npad + n;
    const size_t cstride = (size_t)9 * NTOTP;
    for (int c = 0; c < 128; c++) {
        const float* fc = fb + (size_t)c * N;
        float v = w00 * fc[i00] + w01 * fc[i01] + w10 * fc[i10] + w11 * fc[i11];
        cp[(size_t)c * cstride] = round_tf32(v);
    }
}

// ---------------------------------------------------------------------------
// round W to tf32 once per scale
// ---------------------------------------------------------------------------
__global__ __launch_bounds__(256) void wround_kernel(const float* __restrict__ in,
                                                     float* __restrict__ out, int n) {
    int i = blockIdx.x * 256 + threadIdx.x;
    if (i < n) out[i] = round_tf32(in[i]);
}

// ---------------------------------------------------------------------------
// merged tf32 mma GEMM: out = W[256x2304] @ col[2304 x 40960]
// grid (2, 320): tiles 0..63 -> z (outZ), 64..319 -> x (outX)
// CTA 128x128, BK=16, 8 warps (2M x 4N), double-buffer cp.async
// ---------------------------------------------------------------------------
#define A_STRIDE 20
#define B_STRIDE 136

__global__ __launch_bounds__(256) void dconv_mma_kernel(const float* __restrict__ Wm,
                                                        const float* __restrict__ Bc,
                                                        float* __restrict__ outZ,
                                                        float* __restrict__ outX) {
    __shared__ float sA[2][128 * A_STRIDE];
    __shared__ float sB[2][16 * B_STRIDE];

    int tid = threadIdx.x;
    int wid = tid >> 5, lane = tid & 31;
    int g = lane >> 2, t = lane & 3;
    int warpM = wid >> 2;
    int warpN = wid & 3;

    int m0 = blockIdx.x * 128;
    int n0 = blockIdx.y * 128;

    float* out; int bb, nl0, Nsp;
    if (n0 < ZCOLS) {
        out = outZ; bb = n0 >> SH_Z; nl0 = n0 & (NPAD_Z - 1); Nsp = NZ;
    } else {
        int nx = n0 - ZCOLS;
        out = outX; bb = nx >> SH_X; nl0 = nx & (NPAD_X - 1); Nsp = NX;
    }

    uint32_t sAu = smem_u32(&sA[0][0]);
    uint32_t sBu = smem_u32(&sB[0][0]);

    auto load_stage = [&](int stg, int k0) {
        uint32_t aBase = sAu + stg * (128 * A_STRIDE * 4);
        uint32_t bBase = sBu + stg * (16 * B_STRIDE * 4);
#pragma unroll
        for (int i = 0; i < 2; i++) {
            int q = tid + i * 256;
            int row = q >> 2, c16 = q & 3;
            cpa16(aBase + (row * A_STRIDE + c16 * 4) * 4,
                  Wm + (size_t)(m0 + row) * KDIM + k0 + c16 * 4);
        }
#pragma unroll
        for (int i = 0; i < 2; i++) {
            int q = tid + i * 256;
            int row = q >> 5, c = q & 31;
            cpa16(bBase + (row * B_STRIDE + c * 4) * 4,
                  Bc + (size_t)(k0 + row) * NTOTP + n0 + c * 4);
        }
    };

    float acc[4][4][4];
#pragma unroll
    for (int i = 0; i < 4; i++)
#pragma unroll
        for (int j = 0; j < 4; j++)
#pragma unroll
            for (int r = 0; r < 4; r++) acc[i][j][r] = 0.f;

    const int ITERS = KDIM / 16;   // 144
    load_stage(0, 0);
    asm volatile("cp.async.commit_group;" ::: "memory");

    for (int it = 0; it < ITERS; ++it) {
        int cur = it & 1;
        if (it + 1 < ITERS) load_stage(cur ^ 1, (it + 1) * 16);
        asm volatile("cp.async.commit_group;" ::: "memory");
        asm volatile("cp.async.wait_group 1;" ::: "memory");
        __syncthreads();

        const float* A0 = &sA[cur][0];
        const float* B0 = &sB[cur][0];
#pragma unroll
        for (int ks = 0; ks < 2; ks++) {
            int kb = ks * 8;
            uint32_t af[4][4];
#pragma unroll
            for (int mt = 0; mt < 4; mt++) {
                int m = warpM * 64 + mt * 16 + g;
                af[mt][0] = __float_as_uint(A0[m * A_STRIDE + kb + t]);
                af[mt][1] = __float_as_uint(A0[(m + 8) * A_STRIDE + kb + t]);
                af[mt][2] = __float_as_uint(A0[m * A_STRIDE + kb + t + 4]);
                af[mt][3] = __float_as_uint(A0[(m + 8) * A_STRIDE + kb + t + 4]);
            }
            uint32_t bf[4][2];
#pragma unroll
            for (int nt = 0; nt < 4; nt++) {
                int n = warpN * 32 + nt * 8 + g;
                bf[nt][0] = __float_as_uint(B0[(kb + t) * B_STRIDE + n]);
                bf[nt][1] = __float_as_uint(B0[(kb + t + 4) * B_STRIDE + n]);
            }
#pragma unroll
            for (int mt = 0; mt < 4; mt++)
#pragma unroll
                for (int nt = 0; nt < 4; nt++)
                    mma_tf32(acc[mt][nt][0], acc[mt][nt][1], acc[mt][nt][2], acc[mt][nt][3],
                             af[mt][0], af[mt][1], af[mt][2], af[mt][3],
                             bf[nt][0], bf[nt][1]);
        }
        __syncthreads();
    }

#pragma unroll
    for (int mt = 0; mt < 4; mt++) {
        int m = m0 + warpM * 64 + mt * 16 + g;
        float* r0 = out + ((size_t)bb * C + m) * Nsp;
        float* r1 = out + ((size_t)bb * C + m + 8) * Nsp;
#pragma unroll
        for (int nt = 0; nt < 4; nt++) {
            int n = nl0 + warpN * 32 + nt * 8 + t * 2;
            if (n < Nsp) {
                r0[n] = acc[mt][nt][0];
                r1[n] = acc[mt][nt][2];
                if (n + 1 < Nsp) {
                    r0[n + 1] = acc[mt][nt][1];
                    r1[n + 1] = acc[mt][nt][3];
                }
            }
        }
    }
}

// ---------------------------------------------------------------------------
extern "C" void kernel_launch(void* const* d_in, const int* in_sizes, int n_in,
                              void* d_out, int out_size) {
    const float *Z[3], *X[3], *OW[3], *OB[3], *DW[3], *G[3];
    int nz = 0, nx = 0, nw = 0, nb = 0, nd = 0, ng = 0;
    for (int i = 0; i < n_in; i++) {
        switch (in_sizes[i]) {
            case 1843200: Z[nz++]  = (const float*)d_in[i]; break;
            case 7872512: X[nx++]  = (const float*)d_in[i]; break;
            case 41472:   OW[nw++] = (const float*)d_in[i]; break;
            case 18:      OB[nb++] = (const float*)d_in[i]; break;
            case 589824:  DW[nd++] = (const float*)d_in[i]; break;
            case 1:       G[ng++]  = (const float*)d_in[i]; break;
            default: break;
        }
    }

    float *attnA, *attnB, *featZ, *featX, *off4x, *off4z, *colb, *wrb;
    float *hix, *lox, *hiz, *loz;
    cudaGetSymbolAddress((void**)&attnA, g_attnA);
    cudaGetSymbolAddress((void**)&attnB, g_attnB);
    cudaGetSymbolAddress((void**)&featZ, g_featZ);
    cudaGetSymbolAddress((void**)&featX, g_featX);
    cudaGetSymbolAddress((void**)&off4x, g_off4x);
    cudaGetSymbolAddress((void**)&off4z, g_off4z);
    cudaGetSymbolAddress((void**)&colb,  g_col);
    cudaGetSymbolAddress((void**)&wrb,   g_wr);
    cudaGetSymbolAddress((void**)&hix,   g_hix);
    cudaGetSymbolAddress((void**)&lox,   g_lox);
    cudaGetSymbolAddress((void**)&hiz,   g_hiz);
    cudaGetSymbolAddress((void**)&loz,   g_loz);

    float* outZ = (float*)d_out;
    float* outX = outZ + (size_t)3 * B * C * NZ;

    for (int i = 0; i < 3; i++) {
        splitf_kernel<<<dim3(CDIV(KPX, 256), 2 * B * C), 256>>>(X[i], Z[i],
                                                                hix, lox, hiz, loz);
        gram_mma3_kernel<<<dim3(2, 2, 64), 256>>>(hix, lox, hiz, loz, attnB, attnA);
        attn_softmax_kernel<<<2 * B * C, 256>>>(attnB, attnA);
        camuse_mma_kernel<<<dim3(8, 2, 64), 256>>>(attnA, attnB, X[i], Z[i],
                                                   featX, featZ, G[i]);
        wround_kernel<<<CDIV(256 * KDIM, 256), 256>>>(DW[i], wrb, 256 * KDIM);
        offconv_chunk_kernel<<<dim3(8, 8, 64), 128>>>(featX, featZ, OW[i], off4x, off4z);
        sample_kernel<<<dim3(8, 18, 64), 128>>>(featX, featZ, off4x, off4z, OB[i], colb);
        dconv_mma_kernel<<<dim3(2, NTOTP / 128), 256>>>(wrb, colb,
                                                        outZ + (size_t)i * B * C * NZ,
                                                        outX + (size_t)i * B * C * NX);
    }
    (void)out_size;
}

// round 13
// speedup vs baseline: 1.7615x; 1.0629x over previous
#include <cuda_runtime.h>
#include <math.h>
#include <stdint.h>

#define CDIV(a,b) (((a)+(b)-1)/(b))

static const int B  = 32;
static const int C  = 256;
static const int NZ = 225;   // 15*15
static const int NX = 961;   // 31*31
static const int KDIM = 2304; // C*9

static const int KPX = 976;          // x K padded
static const int KPZ = 240;          // z K padded
static const int NPAD_Z = 256,  SH_Z = 8;
static const int NPAD_X = 1024, SH_X = 10;
static const int ZCOLS = 32 * 256;   // 8192
static const int XCOLS = 32 * 1024;  // 32768
static const int NTOTP = ZCOLS + XCOLS;  // 40960

// ---------------- scratch (device globals; no cudaMalloc allowed) ----------
__device__ float g_attnA[32 * 256 * 256];        // z gram/attn
__device__ float g_attnB[32 * 256 * 256];        // x gram/attn
__device__ float g_featZ[32 * 256 * 225];
__device__ float g_featX[32 * 256 * 961];
__device__ float g_off4x[8 * 32 * 18 * 961];
__device__ float g_off4z[8 * 32 * 18 * 225];
__device__ float g_col  [2304 * 40960];          // merged im2col (377 MB)
__device__ float g_wr   [256 * 2304];
__device__ float g_hix  [32 * 256 * 976];
__device__ float g_lox  [32 * 256 * 976];
__device__ float g_hiz  [32 * 256 * 240];
__device__ float g_loz  [32 * 256 * 240];

// ======================= PTX helpers =======================================
__device__ __forceinline__ uint32_t smem_u32(const void* p) {
    uint32_t a;
    asm("{ .reg .u64 t; cvta.to.shared.u64 t, %1; cvt.u32.u64 %0, t; }" : "=r"(a) : "l"(p));
    return a;
}
__device__ __forceinline__ void cpa16(uint32_t dst, const void* src) {
    asm volatile("cp.async.cg.shared.global [%0], [%1], 16;" :: "r"(dst), "l"(src));
}
__device__ __forceinline__ void cpa16z(uint32_t dst, const void* src, int bytes) {
    asm volatile("cp.async.cg.shared.global [%0], [%1], 16, %2;"
                 :: "r"(dst), "l"(src), "r"(bytes));
}
__device__ __forceinline__ void cpa_commit() {
    asm volatile("cp.async.commit_group;" ::: "memory");
}
__device__ __forceinline__ void cpa_wait1() {
    asm volatile("cp.async.wait_group 1;" ::: "memory");
}
__device__ __forceinline__ float round_tf32(float v) {
    uint32_t r;
    asm("cvt.rna.tf32.f32 %0, %1;" : "=r"(r) : "f"(v));
    return __uint_as_float(r);
}
__device__ __forceinline__ void mma_tf32(float& c0, float& c1, float& c2, float& c3,
                                         uint32_t a0, uint32_t a1, uint32_t a2, uint32_t a3,
                                         uint32_t b0, uint32_t b1) {
    asm volatile(
        "mma.sync.aligned.m16n8k8.row.col.f32.tf32.tf32.f32 "
        "{%0,%1,%2,%3},{%4,%5,%6,%7},{%8,%9},{%0,%1,%2,%3};"
        : "+f"(c0), "+f"(c1), "+f"(c2), "+f"(c3)
        : "r"(a0), "r"(a1), "r"(a2), "r"(a3), "r"(b0), "r"(b1));
}

// ---------------------------------------------------------------------------
// merged tf32 split: grid (4, 2*B*C); y < B*C -> x branch, else z
// ---------------------------------------------------------------------------
__global__ __launch_bounds__(256) void splitf_kernel(const float* __restrict__ inX,
                                                     const float* __restrict__ inZ,
                                                     float* __restrict__ hiX,
                                                     float* __restrict__ loX,
                                                     float* __restrict__ hiZ,
                                                     float* __restrict__ loZ) {
    int y = blockIdx.y;
    const float* in; float* hi; float* lo; int K, Kpad, bc;
    if (y < B * C) { in = inX; hi = hiX; lo = loX; K = NX; Kpad = KPX; bc = y; }
    else           { in = inZ; hi = hiZ; lo = loZ; K = NZ; Kpad = KPZ; bc = y - B * C; }
    int k = blockIdx.x * 256 + threadIdx.x;
    if (k >= Kpad) return;
    float v = (k < K) ? in[(size_t)bc * K + k] : 0.f;
    float h = round_tf32(v);
    size_t o = (size_t)bc * Kpad + k;
    hi[o] = h;
    lo[o] = round_tf32(v - h);
}

// ---------------------------------------------------------------------------
// merged gram via 3xTF32: grid (2,2,64); 3-stage cp.async ring, 1 barrier/iter
// ---------------------------------------------------------------------------
__global__ __launch_bounds__(256) void gram_mma3_kernel(const float* __restrict__ hiX,
                                                        const float* __restrict__ loX,
                                                        const float* __restrict__ hiZ,
                                                        const float* __restrict__ loZ,
                                                        float* __restrict__ Ex,
                                                        float* __restrict__ Ez) {
    __shared__ float Ah[3][1536], Al[3][1536], Bh[3][1536], Bl[3][1536];
    const float* hi; const float* lo; float* E; int Kpad, b;
    if (blockIdx.z < 32) { hi = hiX; lo = loX; E = Ex; Kpad = KPX; b = blockIdx.z; }
    else                 { hi = hiZ; lo = loZ; E = Ez; Kpad = KPZ; b = blockIdx.z - 32; }
    int c0 = blockIdx.y * 128, d0 = blockIdx.x * 128;
    const size_t fb = (size_t)b * C * Kpad;
    int tid = threadIdx.x;
    int wid = tid >> 5, lane = tid & 31;
    int g = lane >> 2, t = lane & 3;
    int warpM = wid >> 2, warpN = wid & 3;

    uint32_t ahU = smem_u32(&Ah[0][0]);
    uint32_t alU = smem_u32(&Al[0][0]);
    uint32_t bhU = smem_u32(&Bh[0][0]);
    uint32_t blU = smem_u32(&Bl[0][0]);

    int lrow = tid >> 1, lhalf = tid & 1;
    auto load_stage = [&](int stg, int k0) {
        uint32_t doff = stg * 6144 + (lrow * 12 + lhalf * 4) * 4;
        const size_t sA = fb + (size_t)(c0 + lrow) * Kpad + k0 + lhalf * 4;
        const size_t sB = fb + (size_t)(d0 + lrow) * Kpad + k0 + lhalf * 4;
        cpa16(ahU + doff, hi + sA);
        cpa16(alU + doff, lo + sA);
        cpa16(bhU + doff, hi + sB);
        cpa16(blU + doff, lo + sB);
    };

    float acc[4][4][4];
#pragma unroll
    for (int i = 0; i < 4; i++)
#pragma unroll
        for (int j = 0; j < 4; j++)
#pragma unroll
            for (int r = 0; r < 4; r++) acc[i][j][r] = 0.f;

    const int ITERS = Kpad / 8;
    load_stage(0, 0);
    cpa_commit();
    load_stage(1, 8);
    cpa_commit();

    int rc = 0, rw = 2;
    for (int it = 0; it < ITERS; it++) {
        cpa_wait1();
        __syncthreads();

        const float* A0h = &Ah[rc][0];
        const float* A0l = &Al[rc][0];
        const float* B0h = &Bh[rc][0];
        const float* B0l = &Bl[rc][0];

        uint32_t ah[4][4], al[4][4];
#pragma unroll
        for (int mt = 0; mt < 4; mt++) {
            int m = warpM * 64 + mt * 16 + g;
            ah[mt][0] = __float_as_uint(A0h[m * 12 + t]);
            ah[mt][1] = __float_as_uint(A0h[(m + 8) * 12 + t]);
            ah[mt][2] = __float_as_uint(A0h[m * 12 + t + 4]);
            ah[mt][3] = __float_as_uint(A0h[(m + 8) * 12 + t + 4]);
            al[mt][0] = __float_as_uint(A0l[m * 12 + t]);
            al[mt][1] = __float_as_uint(A0l[(m + 8) * 12 + t]);
            al[mt][2] = __float_as_uint(A0l[m * 12 + t + 4]);
            al[mt][3] = __float_as_uint(A0l[(m + 8) * 12 + t + 4]);
        }
        uint32_t bh[4][2], bl[4][2];
#pragma unroll
        for (int nt = 0; nt < 4; nt++) {
            int n = warpN * 32 + nt * 8 + g;
            bh[nt][0] = __float_as_uint(B0h[n * 12 + t]);
            bh[nt][1] = __float_as_uint(B0h[n * 12 + t + 4]);
            bl[nt][0] = __float_as_uint(B0l[n * 12 + t]);
            bl[nt][1] = __float_as_uint(B0l[n * 12 + t + 4]);
        }
#pragma unroll
        for (int mt = 0; mt < 4; mt++)
#pragma unroll
            for (int nt = 0; nt < 4; nt++) {
                mma_tf32(acc[mt][nt][0], acc[mt][nt][1], acc[mt][nt][2], acc[mt][nt][3],
                         ah[mt][0], ah[mt][1], ah[mt][2], ah[mt][3],
                         bh[nt][0], bh[nt][1]);
                mma_tf32(acc[mt][nt][0], acc[mt][nt][1], acc[mt][nt][2], acc[mt][nt][3],
                         ah[mt][0], ah[mt][1], ah[mt][2], ah[mt][3],
                         bl[nt][0], bl[nt][1]);
                mma_tf32(acc[mt][nt][0], acc[mt][nt][1], acc[mt][nt][2], acc[mt][nt][3],
                         al[mt][0], al[mt][1], al[mt][2], al[mt][3],
                         bh[nt][0], bh[nt][1]);
            }

        if (it + 2 < ITERS) load_stage(rw, (it + 2) * 8);
        cpa_commit();
        rc = (rc == 2) ? 0 : rc + 1;
        rw = (rw == 2) ? 0 : rw + 1;
    }

    float* Eb = E + (size_t)b * C * C;
#pragma unroll
    for (int mt = 0; mt < 4; mt++) {
        int m = c0 + warpM * 64 + mt * 16 + g;
#pragma unroll
        for (int nt = 0; nt < 4; nt++) {
            int n = d0 + warpN * 32 + nt * 8 + t * 2;
            Eb[(size_t)m * C + n]           = acc[mt][nt][0];
            Eb[(size_t)m * C + n + 1]       = acc[mt][nt][1];
            Eb[(size_t)(m + 8) * C + n]     = acc[mt][nt][2];
            Eb[(size_t)(m + 8) * C + n + 1] = acc[mt][nt][3];
        }
    }
}

// ---------------------------------------------------------------------------
// merged softmax: grid 2*B*C; row < B*C -> Ex else Ez
// ---------------------------------------------------------------------------
__global__ __launch_bounds__(256) void attn_softmax_kernel(float* __restrict__ Ex,
                                                           float* __restrict__ Ez) {
    int row = blockIdx.x;
    float* e = (row < B * C) ? Ex + (size_t)row * 256
                             : Ez + (size_t)(row - B * C) * 256;
    int t = threadIdx.x;
    int warp = t >> 5, lane = t & 31;
    __shared__ float sm[16];
    float v = e[t];
    float m = v;
#pragma unroll
    for (int s = 16; s > 0; s >>= 1) m = fminf(m, __shfl_xor_sync(0xffffffffu, m, s));
    if (lane == 0) sm[warp] = m;
    __syncthreads();
    float emin = fminf(fminf(fminf(sm[0], sm[1]), fminf(sm[2], sm[3])),
                       fminf(fminf(sm[4], sm[5]), fminf(sm[6], sm[7])));
    float p = expf(emin - v);
    float sum = p;
#pragma unroll
    for (int s = 16; s > 0; s >>= 1) sum += __shfl_xor_sync(0xffffffffu, sum, s);
    if (lane == 0) sm[8 + warp] = sum;
    __syncthreads();
    float tot = (sm[8] + sm[9]) + (sm[10] + sm[11]) + (sm[12] + sm[13]) + (sm[14] + sm[15]);
    e[t] = p / tot;
}

// ---------------------------------------------------------------------------
// merged cam_use via tf32 MMA: grid (8,2,64); 3-stage full cp.async ring.
// B operand async-loaded from the PRE-ROUNDED, PADDED hi arrays (16B-aligned
// rows of Kpad floats; zeros beyond N) — fixes R12's misaligned cp.async.
// ---------------------------------------------------------------------------
__global__ __launch_bounds__(256) void camuse_mma_kernel(const float* __restrict__ attnA,
                                                         const float* __restrict__ attnB,
                                                         const float* __restrict__ hiX,
                                                         const float* __restrict__ hiZ,
                                                         const float* __restrict__ Xf,
                                                         const float* __restrict__ Zf,
                                                         float* __restrict__ featX,
                                                         float* __restrict__ featZ,
                                                         const float* __restrict__ gamma) {
    const float* A; const float* hiF; const float* F; float* O; int N, Kpad, b;
    if (blockIdx.z < 32) {
        A = attnA; hiF = hiX; F = Xf; O = featX; N = NX; Kpad = KPX; b = blockIdx.z;
    } else {
        if (blockIdx.x >= 2) return;
        A = attnB; hiF = hiZ; F = Zf; O = featZ; N = NZ; Kpad = KPZ; b = blockIdx.z - 32;
    }
    __shared__ float sA[3][1536];    // 128 x 8 (stride 12)
    __shared__ float sB[3][1088];    // 8 x 128 (stride 136)
    int m0 = blockIdx.y * 128, n0 = blockIdx.x * 128;
    const float* Ab = A + (size_t)b * C * C;
    const float* Fb = F + (size_t)b * C * N;
    const float* Hb = hiF + (size_t)b * C * Kpad;
    int tid = threadIdx.x;
    int wid = tid >> 5, lane = tid & 31;
    int g = lane >> 2, t = lane & 3;
    int warpM = wid >> 2, warpN = wid & 3;

    uint32_t sAu = smem_u32(&sA[0][0]);
    uint32_t sBu = smem_u32(&sB[0][0]);
    int lrow = tid >> 1, lhalf = tid & 1;
    int brow = tid >> 5, bcc = tid & 31;               // B: 8 rows x 32 chunks
    int bcol = n0 + bcc * 4;
    int brem = Kpad - bcol;                            // cols >= N are zero in hi
    int bbytes = (brem <= 0) ? 0 : ((brem >= 4) ? 16 : brem * 4);

    auto load_stage = [&](int stg, int k0) {
        cpa16(sAu + stg * 6144 + (lrow * 12 + lhalf * 4) * 4,
              Ab + (size_t)(m0 + lrow) * C + k0 + lhalf * 4);
        const float* src = (bbytes > 0) ? Hb + (size_t)(k0 + brow) * Kpad + bcol : Hb;
        cpa16z(sBu + stg * 4352 + (brow * 136 + bcc * 4) * 4, src, bbytes);
    };

    float acc[4][4][4];
#pragma unroll
    for (int i = 0; i < 4; i++)
#pragma unroll
        for (int j = 0; j < 4; j++)
#pragma unroll
            for (int r = 0; r < 4; r++) acc[i][j][r] = 0.f;

    const int ITERS = C / 8;   // 32
    load_stage(0, 0);
    cpa_commit();
    load_stage(1, 8);
    cpa_commit();

    int rc = 0, rw = 2;
    for (int it = 0; it < ITERS; it++) {
        cpa_wait1();
        __syncthreads();

        const float* A0 = &sA[rc][0];
        const float* B0 = &sB[rc][0];
        uint32_t af[4][4];
#pragma unroll
        for (int mt = 0; mt < 4; mt++) {
            int m = warpM * 64 + mt * 16 + g;
            af[mt][0] = __float_as_uint(A0[m * 12 + t]);
            af[mt][1] = __float_as_uint(A0[(m + 8) * 12 + t]);
            af[mt][2] = __float_as_uint(A0[m * 12 + t + 4]);
            af[mt][3] = __float_as_uint(A0[(m + 8) * 12 + t + 4]);
        }
        uint32_t bf[4][2];
#pragma unroll
        for (int nt = 0; nt < 4; nt++) {
            int n = warpN * 32 + nt * 8 + g;
            bf[nt][0] = __float_as_uint(B0[t * 136 + n]);
            bf[nt][1] = __float_as_uint(B0[(t + 4) * 136 + n]);
        }
#pragma unroll
        for (int mt = 0; mt < 4; mt++)
#pragma unroll
            for (int nt = 0; nt < 4; nt++)
                mma_tf32(acc[mt][nt][0], acc[mt][nt][1], acc[mt][nt][2], acc[mt][nt][3],
                         af[mt][0], af[mt][1], af[mt][2], af[mt][3],
                         bf[nt][0], bf[nt][1]);

        if (it + 2 < ITERS) load_stage(rw, (it + 2) * 8);
        cpa_commit();
        rc = (rc == 2) ? 0 : rc + 1;
        rw = (rw == 2) ? 0 : rw + 1;
    }

    float gm = gamma[0];
#pragma unroll
    for (int mt = 0; mt < 4; mt++) {
        int m = m0 + warpM * 64 + mt * 16 + g;
#pragma unroll
        for (int nt = 0; nt < 4; nt++) {
            int n = n0 + warpN * 32 + nt * 8 + t * 2;
            if (n < N) {
                O[((size_t)b * C + m) * N + n] = gm * acc[mt][nt][0] + Fb[(size_t)m * N + n];
                O[((size_t)b * C + m + 8) * N + n] = gm * acc[mt][nt][2] + Fb[(size_t)(m + 8) * N + n];
                if (n + 1 < N) {
                    O[((size_t)b * C + m) * N + n + 1] = gm * acc[mt][nt][1] + Fb[(size_t)m * N + n + 1];
                    O[((size_t)b * C + m + 8) * N + n + 1] = gm * acc[mt][nt][3] + Fb[(size_t)(m + 8) * N + n + 1];
                }
            }
        }
    }
}

// ---------------------------------------------------------------------------
// merged offset conv, channel-chunked partials.  grid (8, 8, 64)
// ---------------------------------------------------------------------------
__global__ __launch_bounds__(128) void offconv_chunk_kernel(const float* __restrict__ featX,
                                                            const float* __restrict__ featZ,
                                                            const float* __restrict__ woff,
                                                            float* __restrict__ off4x,
                                                            float* __restrict__ off4z) {
    const float* feat; float* off4; int H, W, b;
    if (blockIdx.z < 32) { feat = featX; off4 = off4x; H = 31; W = 31; b = blockIdx.z; }
    else {
        if (blockIdx.x >= 2) return;
        feat = featZ; off4 = off4z; H = 15; W = 15; b = blockIdx.z - 32;
    }
    __shared__ float sw[32 * 9 * 20];
    int chunk = blockIdx.y;
    int c0 = chunk * 32;
    for (int i = threadIdx.x; i < 32 * 9 * 18; i += 128) {
        int ch = i % 18;
        int rem = i / 18;
        int tap = rem % 9, cc = rem / 9;
        sw[(cc * 9 + tap) * 20 + ch] = woff[(size_t)ch * 2304 + (c0 + cc) * 9 + tap];
    }
    __syncthreads();
    int N = H * W;
    int n = blockIdx.x * 128 + threadIdx.x;
    if (n >= N) return;
    int h = n / W, w = n % W;
    int idx[9];
#pragma unroll
    for (int tap = 0; tap < 9; tap++) {
        int y = h + tap / 3 - 1, x = w + tap % 3 - 1;
        idx[tap] = ((unsigned)y < (unsigned)H && (unsigned)x < (unsigned)W) ? y * W + x : -1;
    }
    float acc[18];
#pragma unroll
    for (int ch = 0; ch < 18; ch++) acc[ch] = 0.f;

    const float* fb = feat + ((size_t)b * C + c0) * N;
    for (int cc = 0; cc < 32; cc++) {
        const float* fc = fb + (size_t)cc * N;
        float f[9];
#pragma unroll
        for (int tap = 0; tap < 9; tap++) f[tap] = (idx[tap] >= 0) ? fc[idx[tap]] : 0.f;
        const float* wp = sw + cc * 180;
#pragma unroll
        for (int tap = 0; tap < 9; tap++) {
            const float* wt = wp + tap * 20;
            float fv = f[tap];
#pragma unroll
            for (int ch = 0; ch < 18; ch++) acc[ch] += wt[ch] * fv;
        }
    }
    float* op = off4 + (((size_t)chunk * B + b) * 18) * N + n;
#pragma unroll
    for (int ch = 0; ch < 18; ch++) op[(size_t)ch * N] = acc[ch];
}

// ---------------------------------------------------------------------------
// merged bilinear sampling -> combined im2col.  grid (8, 18, 64)
// ---------------------------------------------------------------------------
__global__ __launch_bounds__(128) void sample_kernel(const float* __restrict__ featX,
                                                     const float* __restrict__ featZ,
                                                     const float* __restrict__ off4x,
                                                     const float* __restrict__ off4z,
                                                     const float* __restrict__ boff,
                                                     float* __restrict__ col) {
    const float* feat; const float* off4; int H, W, b, Npad, base;
    if (blockIdx.z < 32) {
        feat = featX; off4 = off4x; H = 31; W = 31; b = blockIdx.z;
        Npad = NPAD_X; base = ZCOLS;
    } else {
        if (blockIdx.x >= 2) return;
        feat = featZ; off4 = off4z; H = 15; W = 15; b = blockIdx.z - 32;
        Npad = NPAD_Z; base = 0;
    }
    int N = H * W;
    int k = blockIdx.y % 9;
    int c0 = (blockIdx.y / 9) * 128;
    int n = blockIdx.x * 128 + threadIdx.x;
    if (n >= N) return;
    int h = n / W, w = n % W;
    int ky = k / 3, kx = k % 3;

    const size_t cst = (size_t)B * 18 * N;
    const float* p = off4 + ((size_t)b * 18 + 2 * k) * N + n;
    float oy = __ldg(&boff[2 * k]);
    float ox = __ldg(&boff[2 * k + 1]);
#pragma unroll
    for (int q = 0; q < 8; q++) {
        oy += p[(size_t)q * cst];
        ox += p[(size_t)q * cst + N];
    }

    float py = (float)(h + ky - 1) + oy;
    float px = (float)(w + kx - 1) + ox;
    float y0f = floorf(py), x0f = floorf(px);
    float ly = py - y0f, lx = px - x0f;
    float Hm1 = (float)(H - 1), Wm1 = (float)(W - 1);

    float vy0 = (y0f >= 0.f && y0f <= Hm1) ? (1.f - ly) : 0.f;
    float vy1 = (y0f + 1.f >= 0.f && y0f + 1.f <= Hm1) ? ly : 0.f;
    float vx0 = (x0f >= 0.f && x0f <= Wm1) ? (1.f - lx) : 0.f;
    float vx1 = (x0f + 1.f >= 0.f && x0f + 1.f <= Wm1) ? lx : 0.f;
    int y0 = (int)fminf(fmaxf(y0f, 0.f), Hm1);
    int y1 = (int)fminf(fmaxf(y0f + 1.f, 0.f), Hm1);
    int x0 = (int)fminf(fmaxf(x0f, 0.f), Wm1);
    int x1 = (int)fminf(fmaxf(x0f + 1.f, 0.f), Wm1);

    int i00 = y0 * W + x0, i01 = y0 * W + x1, i10 = y1 * W + x0, i11 = y1 * W + x1;
    float w00 = vy0 * vx0, w01 = vy0 * vx1, w10 = vy1 * vx0, w11 = vy1 * vx1;

    const float* fb = feat + ((size_t)b * C + c0) * N;
    float* cp = col + (size_t)(c0 * 9 + k) * NTOTP + base + (size_t)b * Npad + n;
    const size_t cstride = (size_t)9 * NTOTP;
    for (int c = 0; c < 128; c++) {
        const float* fc = fb + (size_t)c * N;
        float v = w00 * fc[i00] + w01 * fc[i01] + w10 * fc[i10] + w11 * fc[i11];
        cp[(size_t)c * cstride] = round_tf32(v);
    }
}

// ---------------------------------------------------------------------------
// round W to tf32 once per scale
// ---------------------------------------------------------------------------
__global__ __launch_bounds__(256) void wround_kernel(const float* __restrict__ in,
                                                     float* __restrict__ out, int n) {
    int i = blockIdx.x * 256 + threadIdx.x;
    if (i < n) out[i] = round_tf32(in[i]);
}

// ---------------------------------------------------------------------------
// merged tf32 mma GEMM: out = W[256x2304] @ col[2304 x 40960]
// grid (2, 320); 3-stage cp.async ring, single barrier per iter
// ---------------------------------------------------------------------------
#define A_STRIDE 20
#define B_STRIDE 136

__global__ __launch_bounds__(256) void dconv_mma_kernel(const float* __restrict__ Wm,
                                                        const float* __restrict__ Bc,
                                                        float* __restrict__ outZ,
                                                        float* __restrict__ outX) {
    __shared__ float sA[3][128 * A_STRIDE];
    __shared__ float sB[3][16 * B_STRIDE];

    int tid = threadIdx.x;
    int wid = tid >> 5, lane = tid & 31;
    int g = lane >> 2, t = lane & 3;
    int warpM = wid >> 2;
    int warpN = wid & 3;

    int m0 = blockIdx.x * 128;
    int n0 = blockIdx.y * 128;

    float* out; int bb, nl0, Nsp;
    if (n0 < ZCOLS) {
        out = outZ; bb = n0 >> SH_Z; nl0 = n0 & (NPAD_Z - 1); Nsp = NZ;
    } else {
        int nx = n0 - ZCOLS;
        out = outX; bb = nx >> SH_X; nl0 = nx & (NPAD_X - 1); Nsp = NX;
    }

    uint32_t sAu = smem_u32(&sA[0][0]);
    uint32_t sBu = smem_u32(&sB[0][0]);

    auto load_stage = [&](int stg, int k0) {
        uint32_t aBase = sAu + stg * (128 * A_STRIDE * 4);
        uint32_t bBase = sBu + stg * (16 * B_STRIDE * 4);
#pragma unroll
        for (int i = 0; i < 2; i++) {
            int q = tid + i * 256;
            int row = q >> 2, c16 = q & 3;
            cpa16(aBase + (row * A_STRIDE + c16 * 4) * 4,
                  Wm + (size_t)(m0 + row) * KDIM + k0 + c16 * 4);
        }
#pragma unroll
        for (int i = 0; i < 2; i++) {
            int q = tid + i * 256;
            int row = q >> 5, c = q & 31;
            cpa16(bBase + (row * B_STRIDE + c * 4) * 4,
                  Bc + (size_t)(k0 + row) * NTOTP + n0 + c * 4);
        }
    };

    float acc[4][4][4];
#pragma unroll
    for (int i = 0; i < 4; i++)
#pragma unroll
        for (int j = 0; j < 4; j++)
#pragma unroll
            for (int r = 0; r < 4; r++) acc[i][j][r] = 0.f;

    const int ITERS = KDIM / 16;   // 144
    load_stage(0, 0);
    cpa_commit();
    load_stage(1, 16);
    cpa_commit();

    int rc = 0, rw = 2;
    for (int it = 0; it < ITERS; ++it) {
        cpa_wait1();
        __syncthreads();

        const float* A0 = &sA[rc][0];
        const float* B0 = &sB[rc][0];
#pragma unroll
        for (int ks = 0; ks < 2; ks++) {
            int kb = ks * 8;
            uint32_t af[4][4];
#pragma unroll
            for (int mt = 0; mt < 4; mt++) {
                int m = warpM * 64 + mt * 16 + g;
                af[mt][0] = __float_as_uint(A0[m * A_STRIDE + kb + t]);
                af[mt][1] = __float_as_uint(A0[(m + 8) * A_STRIDE + kb + t]);
                af[mt][2] = __float_as_uint(A0[m * A_STRIDE + kb + t + 4]);
                af[mt][3] = __float_as_uint(A0[(m + 8) * A_STRIDE + kb + t + 4]);
            }
            uint32_t bf[4][2];
#pragma unroll
            for (int nt = 0; nt < 4; nt++) {
                int n = warpN * 32 + nt * 8 + g;
                bf[nt][0] = __float_as_uint(B0[(kb + t) * B_STRIDE + n]);
                bf[nt][1] = __float_as_uint(B0[(kb + t + 4) * B_STRIDE + n]);
            }
#pragma unroll
            for (int mt = 0; mt < 4; mt++)
#pragma unroll
                for (int nt = 0; nt < 4; nt++)
                    mma_tf32(acc[mt][nt][0], acc[mt][nt][1], acc[mt][nt][2], acc[mt][nt][3],
                             af[mt][0], af[mt][1], af[mt][2], af[mt][3],
                             bf[nt][0], bf[nt][1]);
        }

        if (it + 2 < ITERS) load_stage(rw, (it + 2) * 16);
        cpa_commit();
        rc = (rc == 2) ? 0 : rc + 1;
        rw = (rw == 2) ? 0 : rw + 1;
    }

#pragma unroll
    for (int mt = 0; mt < 4; mt++) {
        int m = m0 + warpM * 64 + mt * 16 + g;
        float* r0 = out + ((size_t)bb * C + m) * Nsp;
        float* r1 = out + ((size_t)bb * C + m + 8) * Nsp;
#pragma unroll
        for (int nt = 0; nt < 4; nt++) {
            int n = nl0 + warpN * 32 + nt * 8 + t * 2;
            if (n < Nsp) {
                r0[n] = acc[mt][nt][0];
                r1[n] = acc[mt][nt][2];
                if (n + 1 < Nsp) {
                    r0[n + 1] = acc[mt][nt][1];
                    r1[n + 1] = acc[mt][nt][3];
                }
            }
        }
    }
}

// ---------------------------------------------------------------------------
extern "C" void kernel_launch(void* const* d_in, const int* in_sizes, int n_in,
                              void* d_out, int out_size) {
    const float *Z[3], *X[3], *OW[3], *OB[3], *DW[3], *G[3];
    int nz = 0, nx = 0, nw = 0, nb = 0, nd = 0, ng = 0;
    for (int i = 0; i < n_in; i++) {
        switch (in_sizes[i]) {
            case 1843200: Z[nz++]  = (const float*)d_in[i]; break;
            case 7872512: X[nx++]  = (const float*)d_in[i]; break;
            case 41472:   OW[nw++] = (const float*)d_in[i]; break;
            case 18:      OB[nb++] = (const float*)d_in[i]; break;
            case 589824:  DW[nd++] = (const float*)d_in[i]; break;
            case 1:       G[ng++]  = (const float*)d_in[i]; break;
            default: break;
        }
    }

    float *attnA, *attnB, *featZ, *featX, *off4x, *off4z, *colb, *wrb;
    float *hix, *lox, *hiz, *loz;
    cudaGetSymbolAddress((void**)&attnA, g_attnA);
    cudaGetSymbolAddress((void**)&attnB, g_attnB);
    cudaGetSymbolAddress((void**)&featZ, g_featZ);
    cudaGetSymbolAddress((void**)&featX, g_featX);
    cudaGetSymbolAddress((void**)&off4x, g_off4x);
    cudaGetSymbolAddress((void**)&off4z, g_off4z);
    cudaGetSymbolAddress((void**)&colb,  g_col);
    cudaGetSymbolAddress((void**)&wrb,   g_wr);
    cudaGetSymbolAddress((void**)&hix,   g_hix);
    cudaGetSymbolAddress((void**)&lox,   g_lox);
    cudaGetSymbolAddress((void**)&hiz,   g_hiz);
    cudaGetSymbolAddress((void**)&loz,   g_loz);

    float* outZ = (float*)d_out;
    float* outX = outZ + (size_t)3 * B * C * NZ;

    for (int i = 0; i < 3; i++) {
        splitf_kernel<<<dim3(CDIV(KPX, 256), 2 * B * C), 256>>>(X[i], Z[i],
                                                                hix, lox, hiz, loz);
        gram_mma3_kernel<<<dim3(2, 2, 64), 256>>>(hix, lox, hiz, loz, attnB, attnA);
        attn_softmax_kernel<<<2 * B * C, 256>>>(attnB, attnA);
        camuse_mma_kernel<<<dim3(8, 2, 64), 256>>>(attnA, attnB, hix, hiz, X[i], Z[i],
                                                   featX, featZ, G[i]);
        wround_kernel<<<CDIV(256 * KDIM, 256), 256>>>(DW[i], wrb, 256 * KDIM);
        offconv_chunk_kernel<<<dim3(8, 8, 64), 128>>>(featX, featZ, OW[i], off4x, off4z);
        sample_kernel<<<dim3(8, 18, 64), 128>>>(featX, featZ, off4x, off4z, OB[i], colb);
        dconv_mma_kernel<<<dim3(2, NTOTP / 128), 256>>>(wrb, colb,
                                                        outZ + (size_t)i * B * C * NZ,
                                                        outX + (size_t)i * B * C * NX);
    }
    (void)out_size;
}

// round 14
// speedup vs baseline: 1.8115x; 1.0284x over previous
#include <cuda_runtime.h>
#include <math.h>
#include <stdint.h>

#define CDIV(a,b) (((a)+(b)-1)/(b))

static const int B  = 32;
static const int C  = 256;
static const int NZ = 225;   // 15*15
static const int NX = 961;   // 31*31
static const int KDIM = 2304; // C*9

static const int KPX = 976;          // x K padded
static const int KPZ = 240;          // z K padded
static const int NPAD_Z = 256,  SH_Z = 8;
static const int NPAD_X = 1024, SH_X = 10;
static const int ZCOLS = 32 * 256;   // 8192
static const int XCOLS = 32 * 1024;  // 32768
static const int NTOTP = ZCOLS + XCOLS;  // 40960

// ---------------- scratch (device globals; no cudaMalloc allowed) ----------
__device__ float g_attnA[32 * 256 * 256];        // z gram/attn
__device__ float g_attnB[32 * 256 * 256];        // x gram/attn
__device__ float g_featZ[32 * 256 * 225];
__device__ float g_featX[32 * 256 * 961];
__device__ float g_off4x[8 * 32 * 18 * 961];
__device__ float g_off4z[8 * 32 * 18 * 225];
__device__ float g_col  [2304 * 40960];          // merged im2col (377 MB)
__device__ float g_wr   [256 * 2304];
__device__ float g_hix  [32 * 256 * 976];
__device__ float g_lox  [32 * 256 * 976];
__device__ float g_hiz  [32 * 256 * 240];
__device__ float g_loz  [32 * 256 * 240];

// ======================= PTX helpers =======================================
__device__ __forceinline__ uint32_t smem_u32(const void* p) {
    uint32_t a;
    asm("{ .reg .u64 t; cvta.to.shared.u64 t, %1; cvt.u32.u64 %0, t; }" : "=r"(a) : "l"(p));
    return a;
}
__device__ __forceinline__ void cpa16(uint32_t dst, const void* src) {
    asm volatile("cp.async.cg.shared.global [%0], [%1], 16;" :: "r"(dst), "l"(src));
}
__device__ __forceinline__ void cpa16z(uint32_t dst, const void* src, int bytes) {
    asm volatile("cp.async.cg.shared.global [%0], [%1], 16, %2;"
                 :: "r"(dst), "l"(src), "r"(bytes));
}
__device__ __forceinline__ void cpa_commit() {
    asm volatile("cp.async.commit_group;" ::: "memory");
}
__device__ __forceinline__ void cpa_wait1() {
    asm volatile("cp.async.wait_group 1;" ::: "memory");
}
__device__ __forceinline__ void cpa_wait2() {
    asm volatile("cp.async.wait_group 2;" ::: "memory");
}
__device__ __forceinline__ float round_tf32(float v) {
    uint32_t r;
    asm("cvt.rna.tf32.f32 %0, %1;" : "=r"(r) : "f"(v));
    return __uint_as_float(r);
}
__device__ __forceinline__ void mma_tf32(float& c0, float& c1, float& c2, float& c3,
                                         uint32_t a0, uint32_t a1, uint32_t a2, uint32_t a3,
                                         uint32_t b0, uint32_t b1) {
    asm volatile(
        "mma.sync.aligned.m16n8k8.row.col.f32.tf32.tf32.f32 "
        "{%0,%1,%2,%3},{%4,%5,%6,%7},{%8,%9},{%0,%1,%2,%3};"
        : "+f"(c0), "+f"(c1), "+f"(c2), "+f"(c3)
        : "r"(a0), "r"(a1), "r"(a2), "r"(a3), "r"(b0), "r"(b1));
}

// ---------------------------------------------------------------------------
// merged tf32 split: grid (4, 2*B*C); y < B*C -> x branch, else z
// ---------------------------------------------------------------------------
__global__ __launch_bounds__(256) void splitf_kernel(const float* __restrict__ inX,
                                                     const float* __restrict__ inZ,
                                                     float* __restrict__ hiX,
                                                     float* __restrict__ loX,
                                                     float* __restrict__ hiZ,
                                                     float* __restrict__ loZ) {
    int y = blockIdx.y;
    const float* in; float* hi; float* lo; int K, Kpad, bc;
    if (y < B * C) { in = inX; hi = hiX; lo = loX; K = NX; Kpad = KPX; bc = y; }
    else           { in = inZ; hi = hiZ; lo = loZ; K = NZ; Kpad = KPZ; bc = y - B * C; }
    int k = blockIdx.x * 256 + threadIdx.x;
    if (k >= Kpad) return;
    float v = (k < K) ? in[(size_t)bc * K + k] : 0.f;
    float h = round_tf32(v);
    size_t o = (size_t)bc * Kpad + k;
    hi[o] = h;
    lo[o] = round_tf32(v - h);
}

// ---------------------------------------------------------------------------
// merged gram via 3xTF32: grid (2,2,64); 3-stage cp.async ring, 1 barrier/iter
// ---------------------------------------------------------------------------
__global__ __launch_bounds__(256) void gram_mma3_kernel(const float* __restrict__ hiX,
                                                        const float* __restrict__ loX,
                                                        const float* __restrict__ hiZ,
                                                        const float* __restrict__ loZ,
                                                        float* __restrict__ Ex,
                                                        float* __restrict__ Ez) {
    __shared__ float Ah[3][1536], Al[3][1536], Bh[3][1536], Bl[3][1536];
    const float* hi; const float* lo; float* E; int Kpad, b;
    if (blockIdx.z < 32) { hi = hiX; lo = loX; E = Ex; Kpad = KPX; b = blockIdx.z; }
    else                 { hi = hiZ; lo = loZ; E = Ez; Kpad = KPZ; b = blockIdx.z - 32; }
    int c0 = blockIdx.y * 128, d0 = blockIdx.x * 128;
    const size_t fb = (size_t)b * C * Kpad;
    int tid = threadIdx.x;
    int wid = tid >> 5, lane = tid & 31;
    int g = lane >> 2, t = lane & 3;
    int warpM = wid >> 2, warpN = wid & 3;

    uint32_t ahU = smem_u32(&Ah[0][0]);
    uint32_t alU = smem_u32(&Al[0][0]);
    uint32_t bhU = smem_u32(&Bh[0][0]);
    uint32_t blU = smem_u32(&Bl[0][0]);

    int lrow = tid >> 1, lhalf = tid & 1;
    auto load_stage = [&](int stg, int k0) {
        uint32_t doff = stg * 6144 + (lrow * 12 + lhalf * 4) * 4;
        const size_t sA = fb + (size_t)(c0 + lrow) * Kpad + k0 + lhalf * 4;
        const size_t sB = fb + (size_t)(d0 + lrow) * Kpad + k0 + lhalf * 4;
        cpa16(ahU + doff, hi + sA);
        cpa16(alU + doff, lo + sA);
        cpa16(bhU + doff, hi + sB);
        cpa16(blU + doff, lo + sB);
    };

    float acc[4][4][4];
#pragma unroll
    for (int i = 0; i < 4; i++)
#pragma unroll
        for (int j = 0; j < 4; j++)
#pragma unroll
            for (int r = 0; r < 4; r++) acc[i][j][r] = 0.f;

    const int ITERS = Kpad / 8;
    load_stage(0, 0);
    cpa_commit();
    load_stage(1, 8);
    cpa_commit();

    int rc = 0, rw = 2;
    for (int it = 0; it < ITERS; it++) {
        cpa_wait1();
        __syncthreads();

        const float* A0h = &Ah[rc][0];
        const float* A0l = &Al[rc][0];
        const float* B0h = &Bh[rc][0];
        const float* B0l = &Bl[rc][0];

        uint32_t ah[4][4], al[4][4];
#pragma unroll
        for (int mt = 0; mt < 4; mt++) {
            int m = warpM * 64 + mt * 16 + g;
            ah[mt][0] = __float_as_uint(A0h[m * 12 + t]);
            ah[mt][1] = __float_as_uint(A0h[(m + 8) * 12 + t]);
            ah[mt][2] = __float_as_uint(A0h[m * 12 + t + 4]);
            ah[mt][3] = __float_as_uint(A0h[(m + 8) * 12 + t + 4]);
            al[mt][0] = __float_as_uint(A0l[m * 12 + t]);
            al[mt][1] = __float_as_uint(A0l[(m + 8) * 12 + t]);
            al[mt][2] = __float_as_uint(A0l[m * 12 + t + 4]);
            al[mt][3] = __float_as_uint(A0l[(m + 8) * 12 + t + 4]);
        }
        uint32_t bh[4][2], bl[4][2];
#pragma unroll
        for (int nt = 0; nt < 4; nt++) {
            int n = warpN * 32 + nt * 8 + g;
            bh[nt][0] = __float_as_uint(B0h[n * 12 + t]);
            bh[nt][1] = __float_as_uint(B0h[n * 12 + t + 4]);
            bl[nt][0] = __float_as_uint(B0l[n * 12 + t]);
            bl[nt][1] = __float_as_uint(B0l[n * 12 + t + 4]);
        }
#pragma unroll
        for (int mt = 0; mt < 4; mt++)
#pragma unroll
            for (int nt = 0; nt < 4; nt++) {
                mma_tf32(acc[mt][nt][0], acc[mt][nt][1], acc[mt][nt][2], acc[mt][nt][3],
                         ah[mt][0], ah[mt][1], ah[mt][2], ah[mt][3],
                         bh[nt][0], bh[nt][1]);
                mma_tf32(acc[mt][nt][0], acc[mt][nt][1], acc[mt][nt][2], acc[mt][nt][3],
                         ah[mt][0], ah[mt][1], ah[mt][2], ah[mt][3],
                         bl[nt][0], bl[nt][1]);
                mma_tf32(acc[mt][nt][0], acc[mt][nt][1], acc[mt][nt][2], acc[mt][nt][3],
                         al[mt][0], al[mt][1], al[mt][2], al[mt][3],
                         bh[nt][0], bh[nt][1]);
            }

        if (it + 2 < ITERS) load_stage(rw, (it + 2) * 8);
        cpa_commit();
        rc = (rc == 2) ? 0 : rc + 1;
        rw = (rw == 2) ? 0 : rw + 1;
    }

    float* Eb = E + (size_t)b * C * C;
#pragma unroll
    for (int mt = 0; mt < 4; mt++) {
        int m = c0 + warpM * 64 + mt * 16 + g;
#pragma unroll
        for (int nt = 0; nt < 4; nt++) {
            int n = d0 + warpN * 32 + nt * 8 + t * 2;
            Eb[(size_t)m * C + n]           = acc[mt][nt][0];
            Eb[(size_t)m * C + n + 1]       = acc[mt][nt][1];
            Eb[(size_t)(m + 8) * C + n]     = acc[mt][nt][2];
            Eb[(size_t)(m + 8) * C + n + 1] = acc[mt][nt][3];
        }
    }
}

// ---------------------------------------------------------------------------
// merged softmax: grid 2*B*C; row < B*C -> Ex else Ez
// ---------------------------------------------------------------------------
__global__ __launch_bounds__(256) void attn_softmax_kernel(float* __restrict__ Ex,
                                                           float* __restrict__ Ez) {
    int row = blockIdx.x;
    float* e = (row < B * C) ? Ex + (size_t)row * 256
                             : Ez + (size_t)(row - B * C) * 256;
    int t = threadIdx.x;
    int warp = t >> 5, lane = t & 31;
    __shared__ float sm[16];
    float v = e[t];
    float m = v;
#pragma unroll
    for (int s = 16; s > 0; s >>= 1) m = fminf(m, __shfl_xor_sync(0xffffffffu, m, s));
    if (lane == 0) sm[warp] = m;
    __syncthreads();
    float emin = fminf(fminf(fminf(sm[0], sm[1]), fminf(sm[2], sm[3])),
                       fminf(fminf(sm[4], sm[5]), fminf(sm[6], sm[7])));
    float p = expf(emin - v);
    float sum = p;
#pragma unroll
    for (int s = 16; s > 0; s >>= 1) sum += __shfl_xor_sync(0xffffffffu, sum, s);
    if (lane == 0) sm[8 + warp] = sum;
    __syncthreads();
    float tot = (sm[8] + sm[9]) + (sm[10] + sm[11]) + (sm[12] + sm[13]) + (sm[14] + sm[15]);
    e[t] = p / tot;
}

// ---------------------------------------------------------------------------
// merged cam_use via tf32 MMA: grid (8,2,64); BK=16, 3-stage cp.async ring.
// B operand async-loaded from the pre-rounded, padded hi arrays (16B-aligned).
// ---------------------------------------------------------------------------
__global__ __launch_bounds__(256) void camuse_mma_kernel(const float* __restrict__ attnA,
                                                         const float* __restrict__ attnB,
                                                         const float* __restrict__ hiX,
                                                         const float* __restrict__ hiZ,
                                                         const float* __restrict__ Xf,
                                                         const float* __restrict__ Zf,
                                                         float* __restrict__ featX,
                                                         float* __restrict__ featZ,
                                                         const float* __restrict__ gamma) {
    const float* A; const float* hiF; const float* F; float* O; int N, Kpad, b;
    if (blockIdx.z < 32) {
        A = attnA; hiF = hiX; F = Xf; O = featX; N = NX; Kpad = KPX; b = blockIdx.z;
    } else {
        if (blockIdx.x >= 2) return;
        A = attnB; hiF = hiZ; F = Zf; O = featZ; N = NZ; Kpad = KPZ; b = blockIdx.z - 32;
    }
    __shared__ float sA[3][2560];    // 128 x 16 (stride 20)
    __shared__ float sB[3][2176];    // 16 x 128 (stride 136)
    int m0 = blockIdx.y * 128, n0 = blockIdx.x * 128;
    const float* Ab = A + (size_t)b * C * C;
    const float* Fb = F + (size_t)b * C * N;
    const float* Hb = hiF + (size_t)b * C * Kpad;
    int tid = threadIdx.x;
    int wid = tid >> 5, lane = tid & 31;
    int g = lane >> 2, t = lane & 3;
    int warpM = wid >> 2, warpN = wid & 3;

    uint32_t sAu = smem_u32(&sA[0][0]);
    uint32_t sBu = smem_u32(&sB[0][0]);
    int bcc = tid & 31;
    int bcol = n0 + bcc * 4;
    int brem = Kpad - bcol;                 // cols >= N are zero in hi
    int bbytes = (brem <= 0) ? 0 : ((brem >= 4) ? 16 : brem * 4);

    auto load_stage = [&](int stg, int k0) {
#pragma unroll
        for (int i = 0; i < 2; i++) {        // A: 128 rows x 4 chunks of 16B
            int q = tid + i * 256;
            int row = q >> 2, c16 = q & 3;
            cpa16(sAu + stg * 10240 + (row * 20 + c16 * 4) * 4,
                  Ab + (size_t)(m0 + row) * C + k0 + c16 * 4);
        }
#pragma unroll
        for (int i = 0; i < 2; i++) {        // B: 16 rows x 32 chunks
            int q = tid + i * 256;
            int row = q >> 5;                // 0..15
            const float* src = (bbytes > 0) ? Hb + (size_t)(k0 + row) * Kpad + bcol : Hb;
            cpa16z(sBu + stg * 8704 + (row * 136 + bcc * 4) * 4, src, bbytes);
        }
    };

    float acc[4][4][4];
#pragma unroll
    for (int i = 0; i < 4; i++)
#pragma unroll
        for (int j = 0; j < 4; j++)
#pragma unroll
            for (int r = 0; r < 4; r++) acc[i][j][r] = 0.f;

    const int ITERS = C / 16;   // 16
    load_stage(0, 0);
    cpa_commit();
    load_stage(1, 16);
    cpa_commit();

    int rc = 0, rw = 2;
    for (int it = 0; it < ITERS; it++) {
        cpa_wait1();
        __syncthreads();

        const float* A0 = &sA[rc][0];
        const float* B0 = &sB[rc][0];
#pragma unroll
        for (int ks = 0; ks < 2; ks++) {
            int kb = ks * 8;
            uint32_t af[4][4];
#pragma unroll
            for (int mt = 0; mt < 4; mt++) {
                int m = warpM * 64 + mt * 16 + g;
                af[mt][0] = __float_as_uint(A0[m * 20 + kb + t]);
                af[mt][1] = __float_as_uint(A0[(m + 8) * 20 + kb + t]);
                af[mt][2] = __float_as_uint(A0[m * 20 + kb + t + 4]);
                af[mt][3] = __float_as_uint(A0[(m + 8) * 20 + kb + t + 4]);
            }
            uint32_t bf[4][2];
#pragma unroll
            for (int nt = 0; nt < 4; nt++) {
                int n = warpN * 32 + nt * 8 + g;
                bf[nt][0] = __float_as_uint(B0[(kb + t) * 136 + n]);
                bf[nt][1] = __float_as_uint(B0[(kb + t + 4) * 136 + n]);
            }
#pragma unroll
            for (int mt = 0; mt < 4; mt++)
#pragma unroll
                for (int nt = 0; nt < 4; nt++)
                    mma_tf32(acc[mt][nt][0], acc[mt][nt][1], acc[mt][nt][2], acc[mt][nt][3],
                             af[mt][0], af[mt][1], af[mt][2], af[mt][3],
                             bf[nt][0], bf[nt][1]);
        }

        if (it + 2 < ITERS) load_stage(rw, (it + 2) * 16);
        cpa_commit();
        rc = (rc == 2) ? 0 : rc + 1;
        rw = (rw == 2) ? 0 : rw + 1;
    }

    float gm = gamma[0];
#pragma unroll
    for (int mt = 0; mt < 4; mt++) {
        int m = m0 + warpM * 64 + mt * 16 + g;
#pragma unroll
        for (int nt = 0; nt < 4; nt++) {
            int n = n0 + warpN * 32 + nt * 8 + t * 2;
            if (n < N) {
                O[((size_t)b * C + m) * N + n] = gm * acc[mt][nt][0] + Fb[(size_t)m * N + n];
                O[((size_t)b * C + m + 8) * N + n] = gm * acc[mt][nt][2] + Fb[(size_t)(m + 8) * N + n];
                if (n + 1 < N) {
                    O[((size_t)b * C + m) * N + n + 1] = gm * acc[mt][nt][1] + Fb[(size_t)m * N + n + 1];
                    O[((size_t)b * C + m + 8) * N + n + 1] = gm * acc[mt][nt][3] + Fb[(size_t)(m + 8) * N + n + 1];
                }
            }
        }
    }
}

// ---------------------------------------------------------------------------
// merged offset conv, channel-chunked partials.  grid (8, 8, 64)
// ---------------------------------------------------------------------------
__global__ __launch_bounds__(128) void offconv_chunk_kernel(const float* __restrict__ featX,
                                                            const float* __restrict__ featZ,
                                                            const float* __restrict__ woff,
                                                            float* __restrict__ off4x,
                                                            float* __restrict__ off4z) {
    const float* feat; float* off4; int H, W, b;
    if (blockIdx.z < 32) { feat = featX; off4 = off4x; H = 31; W = 31; b = blockIdx.z; }
    else {
        if (blockIdx.x >= 2) return;
        feat = featZ; off4 = off4z; H = 15; W = 15; b = blockIdx.z - 32;
    }
    __shared__ float sw[32 * 9 * 20];
    int chunk = blockIdx.y;
    int c0 = chunk * 32;
    for (int i = threadIdx.x; i < 32 * 9 * 18; i += 128) {
        int ch = i % 18;
        int rem = i / 18;
        int tap = rem % 9, cc = rem / 9;
        sw[(cc * 9 + tap) * 20 + ch] = woff[(size_t)ch * 2304 + (c0 + cc) * 9 + tap];
    }
    __syncthreads();
    int N = H * W;
    int n = blockIdx.x * 128 + threadIdx.x;
    if (n >= N) return;
    int h = n / W, w = n % W;
    int idx[9];
#pragma unroll
    for (int tap = 0; tap < 9; tap++) {
        int y = h + tap / 3 - 1, x = w + tap % 3 - 1;
        idx[tap] = ((unsigned)y < (unsigned)H && (unsigned)x < (unsigned)W) ? y * W + x : -1;
    }
    float acc[18];
#pragma unroll
    for (int ch = 0; ch < 18; ch++) acc[ch] = 0.f;

    const float* fb = feat + ((size_t)b * C + c0) * N;
    for (int cc = 0; cc < 32; cc++) {
        const float* fc = fb + (size_t)cc * N;
        float f[9];
#pragma unroll
        for (int tap = 0; tap < 9; tap++) f[tap] = (idx[tap] >= 0) ? fc[idx[tap]] : 0.f;
        const float* wp = sw + cc * 180;
#pragma unroll
        for (int tap = 0; tap < 9; tap++) {
            const float* wt = wp + tap * 20;
            float fv = f[tap];
#pragma unroll
            for (int ch = 0; ch < 18; ch++) acc[ch] += wt[ch] * fv;
        }
    }
    float* op = off4 + (((size_t)chunk * B + b) * 18) * N + n;
#pragma unroll
    for (int ch = 0; ch < 18; ch++) op[(size_t)ch * N] = acc[ch];
}

// ---------------------------------------------------------------------------
// merged bilinear sampling -> combined im2col.  grid (8, 18, 64)
// ---------------------------------------------------------------------------
__global__ __launch_bounds__(128) void sample_kernel(const float* __restrict__ featX,
                                                     const float* __restrict__ featZ,
                                                     const float* __restrict__ off4x,
                                                     const float* __restrict__ off4z,
                                                     const float* __restrict__ boff,
                                                     float* __restrict__ col) {
    const float* feat; const float* off4; int H, W, b, Npad, base;
    if (blockIdx.z < 32) {
        feat = featX; off4 = off4x; H = 31; W = 31; b = blockIdx.z;
        Npad = NPAD_X; base = ZCOLS;
    } else {
        if (blockIdx.x >= 2) return;
        feat = featZ; off4 = off4z; H = 15; W = 15; b = blockIdx.z - 32;
        Npad = NPAD_Z; base = 0;
    }
    int N = H * W;
    int k = blockIdx.y % 9;
    int c0 = (blockIdx.y / 9) * 128;
    int n = blockIdx.x * 128 + threadIdx.x;
    if (n >= N) return;
    int h = n / W, w = n % W;
    int ky = k / 3, kx = k % 3;

    const size_t cst = (size_t)B * 18 * N;
    const float* p = off4 + ((size_t)b * 18 + 2 * k) * N + n;
    float oy = __ldg(&boff[2 * k]);
    float ox = __ldg(&boff[2 * k + 1]);
#pragma unroll
    for (int q = 0; q < 8; q++) {
        oy += p[(size_t)q * cst];
        ox += p[(size_t)q * cst + N];
    }

    float py = (float)(h + ky - 1) + oy;
    float px = (float)(w + kx - 1) + ox;
    float y0f = floorf(py), x0f = floorf(px);
    float ly = py - y0f, lx = px - x0f;
    float Hm1 = (float)(H - 1), Wm1 = (float)(W - 1);

    float vy0 = (y0f >= 0.f && y0f <= Hm1) ? (1.f - ly) : 0.f;
    float vy1 = (y0f + 1.f >= 0.f && y0f + 1.f <= Hm1) ? ly : 0.f;
    float vx0 = (x0f >= 0.f && x0f <= Wm1) ? (1.f - lx) : 0.f;
    float vx1 = (x0f + 1.f >= 0.f && x0f + 1.f <= Wm1) ? lx : 0.f;
    int y0 = (int)fminf(fmaxf(y0f, 0.f), Hm1);
    int y1 = (int)fminf(fmaxf(y0f + 1.f, 0.f), Hm1);
    int x0 = (int)fminf(fmaxf(x0f, 0.f), Wm1);
    int x1 = (int)fminf(fmaxf(x0f + 1.f, 0.f), Wm1);

    int i00 = y0 * W + x0, i01 = y0 * W + x1, i10 = y1 * W + x0, i11 = y1 * W + x1;
    float w00 = vy0 * vx0, w01 = vy0 * vx1, w10 = vy1 * vx0, w11 = vy1 * vx1;

    const float* fb = feat + ((size_t)b * C + c0) * N;
    float* cp = col + (size_t)(c0 * 9 + k) * NTOTP + base + (size_t)b * Npad + n;
    const size_t cstride = (size_t)9 * NTOTP;
    for (int c = 0; c < 128; c++) {
        const float* fc = fb + (size_t)c * N;
        float v = w00 * fc[i00] + w01 * fc[i01] + w10 * fc[i10] + w11 * fc[i11];
        cp[(size_t)c * cstride] = round_tf32(v);
    }
}

// ---------------------------------------------------------------------------
// round W to tf32 once per scale
// ---------------------------------------------------------------------------
__global__ __launch_bounds__(256) void wround_kernel(const float* __restrict__ in,
                                                     float* __restrict__ out, int n) {
    int i = blockIdx.x * 256 + threadIdx.x;
    if (i < n) out[i] = round_tf32(in[i]);
}

// ---------------------------------------------------------------------------
// merged tf32 mma GEMM: out = W[256x2304] @ col[2304 x 40960]
// grid (2, 320); 4-stage cp.async ring (dynamic smem), single barrier per iter
// ---------------------------------------------------------------------------
#define A_STRIDE 20
#define B_STRIDE 136
#define DCONV_SMEM (4 * (128 * A_STRIDE + 16 * B_STRIDE) * 4)   // 75776 B

__global__ __launch_bounds__(256) void dconv_mma_kernel(const float* __restrict__ Wm,
                                                        const float* __restrict__ Bc,
                                                        float* __restrict__ outZ,
                                                        float* __restrict__ outX) {
    extern __shared__ float dsm[];
    float* sAd = dsm;                          // 4 stages x 2560
    float* sBd = dsm + 4 * 128 * A_STRIDE;     // 4 stages x 2176

    int tid = threadIdx.x;
    int wid = tid >> 5, lane = tid & 31;
    int g = lane >> 2, t = lane & 3;
    int warpM = wid >> 2;
    int warpN = wid & 3;

    int m0 = blockIdx.x * 128;
    int n0 = blockIdx.y * 128;

    float* out; int bb, nl0, Nsp;
    if (n0 < ZCOLS) {
        out = outZ; bb = n0 >> SH_Z; nl0 = n0 & (NPAD_Z - 1); Nsp = NZ;
    } else {
        int nx = n0 - ZCOLS;
        out = outX; bb = nx >> SH_X; nl0 = nx & (NPAD_X - 1); Nsp = NX;
    }

    uint32_t sAu = smem_u32(sAd);
    uint32_t sBu = smem_u32(sBd);

    auto load_stage = [&](int stg, int k0) {
        uint32_t aBase = sAu + stg * (128 * A_STRIDE * 4);
        uint32_t bBase = sBu + stg * (16 * B_STRIDE * 4);
#pragma unroll
        for (int i = 0; i < 2; i++) {
            int q = tid + i * 256;
            int row = q >> 2, c16 = q & 3;
            cpa16(aBase + (row * A_STRIDE + c16 * 4) * 4,
                  Wm + (size_t)(m0 + row) * KDIM + k0 + c16 * 4);
        }
#pragma unroll
        for (int i = 0; i < 2; i++) {
            int q = tid + i * 256;
            int row = q >> 5, c = q & 31;
            cpa16(bBase + (row * B_STRIDE + c * 4) * 4,
                  Bc + (size_t)(k0 + row) * NTOTP + n0 + c * 4);
        }
    };

    float acc[4][4][4];
#pragma unroll
    for (int i = 0; i < 4; i++)
#pragma unroll
        for (int j = 0; j < 4; j++)
#pragma unroll
            for (int r = 0; r < 4; r++) acc[i][j][r] = 0.f;

    const int ITERS = KDIM / 16;   // 144
    load_stage(0, 0);
    cpa_commit();
    load_stage(1, 16);
    cpa_commit();
    load_stage(2, 32);
    cpa_commit();

    int rc = 0, rw = 3;
    for (int it = 0; it < ITERS; ++it) {
        cpa_wait2();
        __syncthreads();

        const float* A0 = &sAd[rc * 128 * A_STRIDE];
        const float* B0 = &sBd[rc * 16 * B_STRIDE];
#pragma unroll
        for (int ks = 0; ks < 2; ks++) {
            int kb = ks * 8;
            uint32_t af[4][4];
#pragma unroll
            for (int mt = 0; mt < 4; mt++) {
                int m = warpM * 64 + mt * 16 + g;
                af[mt][0] = __float_as_uint(A0[m * A_STRIDE + kb + t]);
                af[mt][1] = __float_as_uint(A0[(m + 8) * A_STRIDE + kb + t]);
                af[mt][2] = __float_as_uint(A0[m * A_STRIDE + kb + t + 4]);
                af[mt][3] = __float_as_uint(A0[(m + 8) * A_STRIDE + kb + t + 4]);
            }
            uint32_t bf[4][2];
#pragma unroll
            for (int nt = 0; nt < 4; nt++) {
                int n = warpN * 32 + nt * 8 + g;
                bf[nt][0] = __float_as_uint(B0[(kb + t) * B_STRIDE + n]);
                bf[nt][1] = __float_as_uint(B0[(kb + t + 4) * B_STRIDE + n]);
            }
#pragma unroll
            for (int mt = 0; mt < 4; mt++)
#pragma unroll
                for (int nt = 0; nt < 4; nt++)
                    mma_tf32(acc[mt][nt][0], acc[mt][nt][1], acc[mt][nt][2], acc[mt][nt][3],
                             af[mt][0], af[mt][1], af[mt][2], af[mt][3],
                             bf[nt][0], bf[nt][1]);
        }

        if (it + 3 < ITERS) load_stage(rw, (it + 3) * 16);
        cpa_commit();
        rc = (rc + 1) & 3;
        rw = (rw + 1) & 3;
    }

#pragma unroll
    for (int mt = 0; mt < 4; mt++) {
        int m = m0 + warpM * 64 + mt * 16 + g;
        float* r0 = out + ((size_t)bb * C + m) * Nsp;
        float* r1 = out + ((size_t)bb * C + m + 8) * Nsp;
#pragma unroll
        for (int nt = 0; nt < 4; nt++) {
            int n = nl0 + warpN * 32 + nt * 8 + t * 2;
            if (n < Nsp) {
                r0[n] = acc[mt][nt][0];
                r1[n] = acc[mt][nt][2];
                if (n + 1 < Nsp) {
                    r0[n + 1] = acc[mt][nt][1];
                    r1[n + 1] = acc[mt][nt][3];
                }
            }
        }
    }
}

// ---------------------------------------------------------------------------
extern "C" void kernel_launch(void* const* d_in, const int* in_sizes, int n_in,
                              void* d_out, int out_size) {
    const float *Z[3], *X[3], *OW[3], *OB[3], *DW[3], *G[3];
    int nz = 0, nx = 0, nw = 0, nb = 0, nd = 0, ng = 0;
    for (int i = 0; i < n_in; i++) {
        switch (in_sizes[i]) {
            case 1843200: Z[nz++]  = (const float*)d_in[i]; break;
            case 7872512: X[nx++]  = (const float*)d_in[i]; break;
            case 41472:   OW[nw++] = (const float*)d_in[i]; break;
            case 18:      OB[nb++] = (const float*)d_in[i]; break;
            case 589824:  DW[nd++] = (const float*)d_in[i]; break;
            case 1:       G[ng++]  = (const float*)d_in[i]; break;
            default: break;
        }
    }

    float *attnA, *attnB, *featZ, *featX, *off4x, *off4z, *colb, *wrb;
    float *hix, *lox, *hiz, *loz;
    cudaGetSymbolAddress((void**)&attnA, g_attnA);
    cudaGetSymbolAddress((void**)&attnB, g_attnB);
    cudaGetSymbolAddress((void**)&featZ, g_featZ);
    cudaGetSymbolAddress((void**)&featX, g_featX);
    cudaGetSymbolAddress((void**)&off4x, g_off4x);
    cudaGetSymbolAddress((void**)&off4z, g_off4z);
    cudaGetSymbolAddress((void**)&colb,  g_col);
    cudaGetSymbolAddress((void**)&wrb,   g_wr);
    cudaGetSymbolAddress((void**)&hix,   g_hix);
    cudaGetSymbolAddress((void**)&lox,   g_lox);
    cudaGetSymbolAddress((void**)&hiz,   g_hiz);
    cudaGetSymbolAddress((void**)&loz,   g_loz);

    cudaFuncSetAttribute(dconv_mma_kernel,
                         cudaFuncAttributeMaxDynamicSharedMemorySize, DCONV_SMEM);

    float* outZ = (float*)d_out;
    float* outX = outZ + (size_t)3 * B * C * NZ;

    for (int i = 0; i < 3; i++) {
        splitf_kernel<<<dim3(CDIV(KPX, 256), 2 * B * C), 256>>>(X[i], Z[i],
                                                                hix, lox, hiz, loz);
        gram_mma3_kernel<<<dim3(2, 2, 64), 256>>>(hix, lox, hiz, loz, attnB, attnA);
        attn_softmax_kernel<<<2 * B * C, 256>>>(attnB, attnA);
        camuse_mma_kernel<<<dim3(8, 2, 64), 256>>>(attnA, attnB, hix, hiz, X[i], Z[i],
                                                   featX, featZ, G[i]);
        wround_kernel<<<CDIV(256 * KDIM, 256), 256>>>(DW[i], wrb, 256 * KDIM);
        offconv_chunk_kernel<<<dim3(8, 8, 64), 128>>>(featX, featZ, OW[i], off4x, off4z);
        sample_kernel<<<dim3(8, 18, 64), 128>>>(featX, featZ, off4x, off4z, OB[i], colb);
        dconv_mma_kernel<<<dim3(2, NTOTP / 128), 256, DCONV_SMEM>>>(wrb, colb,
                                                        outZ + (size_t)i * B * C * NZ,
                                                        outX + (size_t)i * B * C * NX);
    }
    (void)out_size;
}

// round 15
// speedup vs baseline: 1.8731x; 1.0340x over previous
#include <cuda_runtime.h>
#include <math.h>
#include <stdint.h>

#define CDIV(a,b) (((a)+(b)-1)/(b))

static const int B  = 32;
static const int C  = 256;
static const int NZ = 225;   // 15*15
static const int NX = 961;   // 31*31
static const int KDIM = 2304; // C*9

static const int KPX = 976;          // x K padded
static const int KPZ = 240;          // z K padded
static const int NPAD_Z = 256,  SH_Z = 8;
static const int NPAD_X = 1024, SH_X = 10;
static const int ZCOLS = 32 * 256;   // 8192
static const int XCOLS = 32 * 1024;  // 32768
static const int NTOTP = ZCOLS + XCOLS;  // 40960

// ---------------- scratch (device globals; no cudaMalloc allowed) ----------
__device__ float g_attnA[32 * 256 * 256];        // z gram/attn
__device__ float g_attnB[32 * 256 * 256];        // x gram/attn
__device__ float g_featZ[32 * 256 * 225];
__device__ float g_featX[32 * 256 * 961];
__device__ float g_off4x[8 * 32 * 18 * 961];
__device__ float g_off4z[8 * 32 * 18 * 225];
__device__ float g_col  [2304 * 40960];          // merged im2col (377 MB)
__device__ float g_wr   [256 * 2304];
__device__ float g_hix  [32 * 256 * 976];
__device__ float g_lox  [32 * 256 * 976];
__device__ float g_hiz  [32 * 256 * 240];
__device__ float g_loz  [32 * 256 * 240];

// ======================= PTX helpers =======================================
__device__ __forceinline__ uint32_t smem_u32(const void* p) {
    uint32_t a;
    asm("{ .reg .u64 t; cvta.to.shared.u64 t, %1; cvt.u32.u64 %0, t; }" : "=r"(a) : "l"(p));
    return a;
}
__device__ __forceinline__ void cpa16(uint32_t dst, const void* src) {
    asm volatile("cp.async.cg.shared.global [%0], [%1], 16;" :: "r"(dst), "l"(src));
}
__device__ __forceinline__ void cpa16z(uint32_t dst, const void* src, int bytes) {
    asm volatile("cp.async.cg.shared.global [%0], [%1], 16, %2;"
                 :: "r"(dst), "l"(src), "r"(bytes));
}
__device__ __forceinline__ void cpa_commit() {
    asm volatile("cp.async.commit_group;" ::: "memory");
}
__device__ __forceinline__ void cpa_wait1() {
    asm volatile("cp.async.wait_group 1;" ::: "memory");
}
__device__ __forceinline__ void cpa_wait2() {
    asm volatile("cp.async.wait_group 2;" ::: "memory");
}
__device__ __forceinline__ float round_tf32(float v) {
    uint32_t r;
    asm("cvt.rna.tf32.f32 %0, %1;" : "=r"(r) : "f"(v));
    return __uint_as_float(r);
}
__device__ __forceinline__ void mma_tf32(float& c0, float& c1, float& c2, float& c3,
                                         uint32_t a0, uint32_t a1, uint32_t a2, uint32_t a3,
                                         uint32_t b0, uint32_t b1) {
    asm volatile(
        "mma.sync.aligned.m16n8k8.row.col.f32.tf32.tf32.f32 "
        "{%0,%1,%2,%3},{%4,%5,%6,%7},{%8,%9},{%0,%1,%2,%3};"
        : "+f"(c0), "+f"(c1), "+f"(c2), "+f"(c3)
        : "r"(a0), "r"(a1), "r"(a2), "r"(a3), "r"(b0), "r"(b1));
}

// ---------------------------------------------------------------------------
// merged tf32 split: grid (4, 2*B*C); y < B*C -> x branch, else z
// ---------------------------------------------------------------------------
__global__ __launch_bounds__(256) void splitf_kernel(const float* __restrict__ inX,
                                                     const float* __restrict__ inZ,
                                                     float* __restrict__ hiX,
                                                     float* __restrict__ loX,
                                                     float* __restrict__ hiZ,
                                                     float* __restrict__ loZ) {
    int y = blockIdx.y;
    const float* in; float* hi; float* lo; int K, Kpad, bc;
    if (y < B * C) { in = inX; hi = hiX; lo = loX; K = NX; Kpad = KPX; bc = y; }
    else           { in = inZ; hi = hiZ; lo = loZ; K = NZ; Kpad = KPZ; bc = y - B * C; }
    int k = blockIdx.x * 256 + threadIdx.x;
    if (k >= Kpad) return;
    float v = (k < K) ? in[(size_t)bc * K + k] : 0.f;
    float h = round_tf32(v);
    size_t o = (size_t)bc * Kpad + k;
    hi[o] = h;
    lo[o] = round_tf32(v - h);
}

// ---------------------------------------------------------------------------
// merged gram via 3xTF32: grid (2,2,64); 3-stage cp.async ring, 1 barrier/iter
// ---------------------------------------------------------------------------
__global__ __launch_bounds__(256) void gram_mma3_kernel(const float* __restrict__ hiX,
                                                        const float* __restrict__ loX,
                                                        const float* __restrict__ hiZ,
                                                        const float* __restrict__ loZ,
                                                        float* __restrict__ Ex,
                                                        float* __restrict__ Ez) {
    __shared__ float Ah[3][1536], Al[3][1536], Bh[3][1536], Bl[3][1536];
    const float* hi; const float* lo; float* E; int Kpad, b;
    if (blockIdx.z < 32) { hi = hiX; lo = loX; E = Ex; Kpad = KPX; b = blockIdx.z; }
    else                 { hi = hiZ; lo = loZ; E = Ez; Kpad = KPZ; b = blockIdx.z - 32; }
    int c0 = blockIdx.y * 128, d0 = blockIdx.x * 128;
    const size_t fb = (size_t)b * C * Kpad;
    int tid = threadIdx.x;
    int wid = tid >> 5, lane = tid & 31;
    int g = lane >> 2, t = lane & 3;
    int warpM = wid >> 2, warpN = wid & 3;

    uint32_t ahU = smem_u32(&Ah[0][0]);
    uint32_t alU = smem_u32(&Al[0][0]);
    uint32_t bhU = smem_u32(&Bh[0][0]);
    uint32_t blU = smem_u32(&Bl[0][0]);

    int lrow = tid >> 1, lhalf = tid & 1;
    auto load_stage = [&](int stg, int k0) {
        uint32_t doff = stg * 6144 + (lrow * 12 + lhalf * 4) * 4;
        const size_t sA = fb + (size_t)(c0 + lrow) * Kpad + k0 + lhalf * 4;
        const size_t sB = fb + (size_t)(d0 + lrow) * Kpad + k0 + lhalf * 4;
        cpa16(ahU + doff, hi + sA);
        cpa16(alU + doff, lo + sA);
        cpa16(bhU + doff, hi + sB);
        cpa16(blU + doff, lo + sB);
    };

    float acc[4][4][4];
#pragma unroll
    for (int i = 0; i < 4; i++)
#pragma unroll
        for (int j = 0; j < 4; j++)
#pragma unroll
            for (int r = 0; r < 4; r++) acc[i][j][r] = 0.f;

    const int ITERS = Kpad / 8;
    load_stage(0, 0);
    cpa_commit();
    load_stage(1, 8);
    cpa_commit();

    int rc = 0, rw = 2;
    for (int it = 0; it < ITERS; it++) {
        cpa_wait1();
        __syncthreads();

        const float* A0h = &Ah[rc][0];
        const float* A0l = &Al[rc][0];
        const float* B0h = &Bh[rc][0];
        const float* B0l = &Bl[rc][0];

        uint32_t ah[4][4], al[4][4];
#pragma unroll
        for (int mt = 0; mt < 4; mt++) {
            int m = warpM * 64 + mt * 16 + g;
            ah[mt][0] = __float_as_uint(A0h[m * 12 + t]);
            ah[mt][1] = __float_as_uint(A0h[(m + 8) * 12 + t]);
            ah[mt][2] = __float_as_uint(A0h[m * 12 + t + 4]);
            ah[mt][3] = __float_as_uint(A0h[(m + 8) * 12 + t + 4]);
            al[mt][0] = __float_as_uint(A0l[m * 12 + t]);
            al[mt][1] = __float_as_uint(A0l[(m + 8) * 12 + t]);
            al[mt][2] = __float_as_uint(A0l[m * 12 + t + 4]);
            al[mt][3] = __float_as_uint(A0l[(m + 8) * 12 + t + 4]);
        }
        uint32_t bh[4][2], bl[4][2];
#pragma unroll
        for (int nt = 0; nt < 4; nt++) {
            int n = warpN * 32 + nt * 8 + g;
            bh[nt][0] = __float_as_uint(B0h[n * 12 + t]);
            bh[nt][1] = __float_as_uint(B0h[n * 12 + t + 4]);
            bl[nt][0] = __float_as_uint(B0l[n * 12 + t]);
            bl[nt][1] = __float_as_uint(B0l[n * 12 + t + 4]);
        }
#pragma unroll
        for (int mt = 0; mt < 4; mt++)
#pragma unroll
            for (int nt = 0; nt < 4; nt++) {
                mma_tf32(acc[mt][nt][0], acc[mt][nt][1], acc[mt][nt][2], acc[mt][nt][3],
                         ah[mt][0], ah[mt][1], ah[mt][2], ah[mt][3],
                         bh[nt][0], bh[nt][1]);
                mma_tf32(acc[mt][nt][0], acc[mt][nt][1], acc[mt][nt][2], acc[mt][nt][3],
                         ah[mt][0], ah[mt][1], ah[mt][2], ah[mt][3],
                         bl[nt][0], bl[nt][1]);
                mma_tf32(acc[mt][nt][0], acc[mt][nt][1], acc[mt][nt][2], acc[mt][nt][3],
                         al[mt][0], al[mt][1], al[mt][2], al[mt][3],
                         bh[nt][0], bh[nt][1]);
            }

        if (it + 2 < ITERS) load_stage(rw, (it + 2) * 8);
        cpa_commit();
        rc = (rc == 2) ? 0 : rc + 1;
        rw = (rw == 2) ? 0 : rw + 1;
    }

    float* Eb = E + (size_t)b * C * C;
#pragma unroll
    for (int mt = 0; mt < 4; mt++) {
        int m = c0 + warpM * 64 + mt * 16 + g;
#pragma unroll
        for (int nt = 0; nt < 4; nt++) {
            int n = d0 + warpN * 32 + nt * 8 + t * 2;
            Eb[(size_t)m * C + n]           = acc[mt][nt][0];
            Eb[(size_t)m * C + n + 1]       = acc[mt][nt][1];
            Eb[(size_t)(m + 8) * C + n]     = acc[mt][nt][2];
            Eb[(size_t)(m + 8) * C + n + 1] = acc[mt][nt][3];
        }
    }
}

// ---------------------------------------------------------------------------
// merged softmax: grid 2*B*C; row < B*C -> Ex else Ez
// ---------------------------------------------------------------------------
__global__ __launch_bounds__(256) void attn_softmax_kernel(float* __restrict__ Ex,
                                                           float* __restrict__ Ez) {
    int row = blockIdx.x;
    float* e = (row < B * C) ? Ex + (size_t)row * 256
                             : Ez + (size_t)(row - B * C) * 256;
    int t = threadIdx.x;
    int warp = t >> 5, lane = t & 31;
    __shared__ float sm[16];
    float v = e[t];
    float m = v;
#pragma unroll
    for (int s = 16; s > 0; s >>= 1) m = fminf(m, __shfl_xor_sync(0xffffffffu, m, s));
    if (lane == 0) sm[warp] = m;
    __syncthreads();
    float emin = fminf(fminf(fminf(sm[0], sm[1]), fminf(sm[2], sm[3])),
                       fminf(fminf(sm[4], sm[5]), fminf(sm[6], sm[7])));
    float p = expf(emin - v);
    float sum = p;
#pragma unroll
    for (int s = 16; s > 0; s >>= 1) sum += __shfl_xor_sync(0xffffffffu, sum, s);
    if (lane == 0) sm[8 + warp] = sum;
    __syncthreads();
    float tot = (sm[8] + sm[9]) + (sm[10] + sm[11]) + (sm[12] + sm[13]) + (sm[14] + sm[15]);
    e[t] = p / tot;
}

// ---------------------------------------------------------------------------
// merged cam_use via tf32 MMA: grid (8,2,64); BK=16, 4-stage dynamic ring.
// B operand async-loaded from the pre-rounded, padded hi arrays (16B-aligned).
// ---------------------------------------------------------------------------
#define CAM_SMEM (4 * (2560 + 2176) * 4)   // 75776 B

__global__ __launch_bounds__(256) void camuse_mma_kernel(const float* __restrict__ attnA,
                                                         const float* __restrict__ attnB,
                                                         const float* __restrict__ hiX,
                                                         const float* __restrict__ hiZ,
                                                         const float* __restrict__ Xf,
                                                         const float* __restrict__ Zf,
                                                         float* __restrict__ featX,
                                                         float* __restrict__ featZ,
                                                         const float* __restrict__ gamma) {
    const float* A; const float* hiF; const float* F; float* O; int N, Kpad, b;
    if (blockIdx.z < 32) {
        A = attnA; hiF = hiX; F = Xf; O = featX; N = NX; Kpad = KPX; b = blockIdx.z;
    } else {
        if (blockIdx.x >= 2) return;
        A = attnB; hiF = hiZ; F = Zf; O = featZ; N = NZ; Kpad = KPZ; b = blockIdx.z - 32;
    }
    extern __shared__ float csm[];
    float* sAd = csm;                  // 4 stages x 2560 (128 x 16, stride 20)
    float* sBd = csm + 4 * 2560;       // 4 stages x 2176 (16 x 128, stride 136)
    int m0 = blockIdx.y * 128, n0 = blockIdx.x * 128;
    const float* Ab = A + (size_t)b * C * C;
    const float* Fb = F + (size_t)b * C * N;
    const float* Hb = hiF + (size_t)b * C * Kpad;
    int tid = threadIdx.x;
    int wid = tid >> 5, lane = tid & 31;
    int g = lane >> 2, t = lane & 3;
    int warpM = wid >> 2, warpN = wid & 3;

    uint32_t sAu = smem_u32(sAd);
    uint32_t sBu = smem_u32(sBd);
    int bcc = tid & 31;
    int bcol = n0 + bcc * 4;
    int brem = Kpad - bcol;                 // cols >= N are zero in hi
    int bbytes = (brem <= 0) ? 0 : ((brem >= 4) ? 16 : brem * 4);

    auto load_stage = [&](int stg, int k0) {
#pragma unroll
        for (int i = 0; i < 2; i++) {        // A: 128 rows x 4 chunks of 16B
            int q = tid + i * 256;
            int row = q >> 2, c16 = q & 3;
            cpa16(sAu + stg * 10240 + (row * 20 + c16 * 4) * 4,
                  Ab + (size_t)(m0 + row) * C + k0 + c16 * 4);
        }
#pragma unroll
        for (int i = 0; i < 2; i++) {        // B: 16 rows x 32 chunks
            int q = tid + i * 256;
            int row = q >> 5;                // 0..15
            const float* src = (bbytes > 0) ? Hb + (size_t)(k0 + row) * Kpad + bcol : Hb;
            cpa16z(sBu + stg * 8704 + (row * 136 + bcc * 4) * 4, src, bbytes);
        }
    };

    float acc[4][4][4];
#pragma unroll
    for (int i = 0; i < 4; i++)
#pragma unroll
        for (int j = 0; j < 4; j++)
#pragma unroll
            for (int r = 0; r < 4; r++) acc[i][j][r] = 0.f;

    const int ITERS = C / 16;   // 16
    load_stage(0, 0);
    cpa_commit();
    load_stage(1, 16);
    cpa_commit();
    load_stage(2, 32);
    cpa_commit();

    int rc = 0, rw = 3;
    for (int it = 0; it < ITERS; it++) {
        cpa_wait2();
        __syncthreads();

        const float* A0 = &sAd[rc * 2560];
        const float* B0 = &sBd[rc * 2176];
#pragma unroll
        for (int ks = 0; ks < 2; ks++) {
            int kb = ks * 8;
            uint32_t af[4][4];
#pragma unroll
            for (int mt = 0; mt < 4; mt++) {
                int m = warpM * 64 + mt * 16 + g;
                af[mt][0] = __float_as_uint(A0[m * 20 + kb + t]);
                af[mt][1] = __float_as_uint(A0[(m + 8) * 20 + kb + t]);
                af[mt][2] = __float_as_uint(A0[m * 20 + kb + t + 4]);
                af[mt][3] = __float_as_uint(A0[(m + 8) * 20 + kb + t + 4]);
            }
            uint32_t bf[4][2];
#pragma unroll
            for (int nt = 0; nt < 4; nt++) {
                int n = warpN * 32 + nt * 8 + g;
                bf[nt][0] = __float_as_uint(B0[(kb + t) * 136 + n]);
                bf[nt][1] = __float_as_uint(B0[(kb + t + 4) * 136 + n]);
            }
#pragma unroll
            for (int mt = 0; mt < 4; mt++)
#pragma unroll
                for (int nt = 0; nt < 4; nt++)
                    mma_tf32(acc[mt][nt][0], acc[mt][nt][1], acc[mt][nt][2], acc[mt][nt][3],
                             af[mt][0], af[mt][1], af[mt][2], af[mt][3],
                             bf[nt][0], bf[nt][1]);
        }

        if (it + 3 < ITERS) load_stage(rw, (it + 3) * 16);
        cpa_commit();
        rc = (rc + 1) & 3;
        rw = (rw + 1) & 3;
    }

    float gm = gamma[0];
#pragma unroll
    for (int mt = 0; mt < 4; mt++) {
        int m = m0 + warpM * 64 + mt * 16 + g;
#pragma unroll
        for (int nt = 0; nt < 4; nt++) {
            int n = n0 + warpN * 32 + nt * 8 + t * 2;
            if (n < N) {
                O[((size_t)b * C + m) * N + n] = gm * acc[mt][nt][0] + Fb[(size_t)m * N + n];
                O[((size_t)b * C + m + 8) * N + n] = gm * acc[mt][nt][2] + Fb[(size_t)(m + 8) * N + n];
                if (n + 1 < N) {
                    O[((size_t)b * C + m) * N + n + 1] = gm * acc[mt][nt][1] + Fb[(size_t)m * N + n + 1];
                    O[((size_t)b * C + m + 8) * N + n + 1] = gm * acc[mt][nt][3] + Fb[(size_t)(m + 8) * N + n + 1];
                }
            }
        }
    }
}

// ---------------------------------------------------------------------------
// merged offset conv, channel-chunked partials.  grid (8, 8, 64)
// ---------------------------------------------------------------------------
__global__ __launch_bounds__(128) void offconv_chunk_kernel(const float* __restrict__ featX,
                                                            const float* __restrict__ featZ,
                                                            const float* __restrict__ woff,
                                                            float* __restrict__ off4x,
                                                            float* __restrict__ off4z) {
    const float* feat; float* off4; int H, W, b;
    if (blockIdx.z < 32) { feat = featX; off4 = off4x; H = 31; W = 31; b = blockIdx.z; }
    else {
        if (blockIdx.x >= 2) return;
        feat = featZ; off4 = off4z; H = 15; W = 15; b = blockIdx.z - 32;
    }
    __shared__ float sw[32 * 9 * 20];
    int chunk = blockIdx.y;
    int c0 = chunk * 32;
    for (int i = threadIdx.x; i < 32 * 9 * 18; i += 128) {
        int ch = i % 18;
        int rem = i / 18;
        int tap = rem % 9, cc = rem / 9;
        sw[(cc * 9 + tap) * 20 + ch] = woff[(size_t)ch * 2304 + (c0 + cc) * 9 + tap];
    }
    __syncthreads();
    int N = H * W;
    int n = blockIdx.x * 128 + threadIdx.x;
    if (n >= N) return;
    int h = n / W, w = n % W;
    int idx[9];
#pragma unroll
    for (int tap = 0; tap < 9; tap++) {
        int y = h + tap / 3 - 1, x = w + tap % 3 - 1;
        idx[tap] = ((unsigned)y < (unsigned)H && (unsigned)x < (unsigned)W) ? y * W + x : -1;
    }
    float acc[18];
#pragma unroll
    for (int ch = 0; ch < 18; ch++) acc[ch] = 0.f;

    const float* fb = feat + ((size_t)b * C + c0) * N;
    for (int cc = 0; cc < 32; cc++) {
        const float* fc = fb + (size_t)cc * N;
        float f[9];
#pragma unroll
        for (int tap = 0; tap < 9; tap++) f[tap] = (idx[tap] >= 0) ? fc[idx[tap]] : 0.f;
        const float* wp = sw + cc * 180;
#pragma unroll
        for (int tap = 0; tap < 9; tap++) {
            const float* wt = wp + tap * 20;
            float fv = f[tap];
#pragma unroll
            for (int ch = 0; ch < 18; ch++) acc[ch] += wt[ch] * fv;
        }
    }
    float* op = off4 + (((size_t)chunk * B + b) * 18) * N + n;
#pragma unroll
    for (int ch = 0; ch < 18; ch++) op[(size_t)ch * N] = acc[ch];
}

// ---------------------------------------------------------------------------
// merged bilinear sampling -> combined im2col.  grid (8, 18, 64)
// ---------------------------------------------------------------------------
__global__ __launch_bounds__(128) void sample_kernel(const float* __restrict__ featX,
                                                     const float* __restrict__ featZ,
                                                     const float* __restrict__ off4x,
                                                     const float* __restrict__ off4z,
                                                     const float* __restrict__ boff,
                                                     float* __restrict__ col) {
    const float* feat; const float* off4; int H, W, b, Npad, base;
    if (blockIdx.z < 32) {
        feat = featX; off4 = off4x; H = 31; W = 31; b = blockIdx.z;
        Npad = NPAD_X; base = ZCOLS;
    } else {
        if (blockIdx.x >= 2) return;
        feat = featZ; off4 = off4z; H = 15; W = 15; b = blockIdx.z - 32;
        Npad = NPAD_Z; base = 0;
    }
    int N = H * W;
    int k = blockIdx.y % 9;
    int c0 = (blockIdx.y / 9) * 128;
    int n = blockIdx.x * 128 + threadIdx.x;
    if (n >= N) return;
    int h = n / W, w = n % W;
    int ky = k / 3, kx = k % 3;

    const size_t cst = (size_t)B * 18 * N;
    const float* p = off4 + ((size_t)b * 18 + 2 * k) * N + n;
    float oy = __ldg(&boff[2 * k]);
    float ox = __ldg(&boff[2 * k + 1]);
#pragma unroll
    for (int q = 0; q < 8; q++) {
        oy += p[(size_t)q * cst];
        ox += p[(size_t)q * cst + N];
    }

    float py = (float)(h + ky - 1) + oy;
    float px = (float)(w + kx - 1) + ox;
    float y0f = floorf(py), x0f = floorf(px);
    float ly = py - y0f, lx = px - x0f;
    float Hm1 = (float)(H - 1), Wm1 = (float)(W - 1);

    float vy0 = (y0f >= 0.f && y0f <= Hm1) ? (1.f - ly) : 0.f;
    float vy1 = (y0f + 1.f >= 0.f && y0f + 1.f <= Hm1) ? ly : 0.f;
    float vx0 = (x0f >= 0.f && x0f <= Wm1) ? (1.f - lx) : 0.f;
    float vx1 = (x0f + 1.f >= 0.f && x0f + 1.f <= Wm1) ? lx : 0.f;
    int y0 = (int)fminf(fmaxf(y0f, 0.f), Hm1);
    int y1 = (int)fminf(fmaxf(y0f + 1.f, 0.f), Hm1);
    int x0 = (int)fminf(fmaxf(x0f, 0.f), Wm1);
    int x1 = (int)fminf(fmaxf(x0f + 1.f, 0.f), Wm1);

    int i00 = y0 * W + x0, i01 = y0 * W + x1, i10 = y1 * W + x0, i11 = y1 * W + x1;
    float w00 = vy0 * vx0, w01 = vy0 * vx1, w10 = vy1 * vx0, w11 = vy1 * vx1;

    const float* fb = feat + ((size_t)b * C + c0) * N;
    float* cp = col + (size_t)(c0 * 9 + k) * NTOTP + base + (size_t)b * Npad + n;
    const size_t cstride = (size_t)9 * NTOTP;
    for (int c = 0; c < 128; c++) {
        const float* fc = fb + (size_t)c * N;
        float v = w00 * fc[i00] + w01 * fc[i01] + w10 * fc[i10] + w11 * fc[i11];
        cp[(size_t)c * cstride] = round_tf32(v);
    }
}

// ---------------------------------------------------------------------------
// round W to tf32 once per scale
// ---------------------------------------------------------------------------
__global__ __launch_bounds__(256) void wround_kernel(const float* __restrict__ in,
                                                     float* __restrict__ out, int n) {
    int i = blockIdx.x * 256 + threadIdx.x;
    if (i < n) out[i] = round_tf32(in[i]);
}

// ---------------------------------------------------------------------------
// merged tf32 mma GEMM: out = W[256x2304] @ col[2304 x 40960]
// grid (2, 320); BK=32, 3-stage dynamic-smem ring, 1 barrier per iter
// ---------------------------------------------------------------------------
#define DA_STRIDE 36
#define DB_STRIDE 136
#define DCONV_SMEM (3 * (128 * DA_STRIDE + 32 * DB_STRIDE) * 4)   // 107520 B

__global__ __launch_bounds__(256) void dconv_mma_kernel(const float* __restrict__ Wm,
                                                        const float* __restrict__ Bc,
                                                        float* __restrict__ outZ,
                                                        float* __restrict__ outX) {
    extern __shared__ float dsm[];
    float* sAd = dsm;                          // 3 stages x 128*36
    float* sBd = dsm + 3 * 128 * DA_STRIDE;    // 3 stages x 32*136

    int tid = threadIdx.x;
    int wid = tid >> 5, lane = tid & 31;
    int g = lane >> 2, t = lane & 3;
    int warpM = wid >> 2;
    int warpN = wid & 3;

    int m0 = blockIdx.x * 128;
    int n0 = blockIdx.y * 128;

    float* out; int bb, nl0, Nsp;
    if (n0 < ZCOLS) {
        out = outZ; bb = n0 >> SH_Z; nl0 = n0 & (NPAD_Z - 1); Nsp = NZ;
    } else {
        int nx = n0 - ZCOLS;
        out = outX; bb = nx >> SH_X; nl0 = nx & (NPAD_X - 1); Nsp = NX;
    }

    uint32_t sAu = smem_u32(sAd);
    uint32_t sBu = smem_u32(sBd);

    auto load_stage = [&](int stg, int k0) {
        uint32_t aBase = sAu + stg * (128 * DA_STRIDE * 4);
        uint32_t bBase = sBu + stg * (32 * DB_STRIDE * 4);
#pragma unroll
        for (int i = 0; i < 4; i++) {           // A: 128 rows x 8 chunks of 16B
            int q = tid + i * 256;
            int row = q >> 3, c16 = q & 7;
            cpa16(aBase + (row * DA_STRIDE + c16 * 4) * 4,
                  Wm + (size_t)(m0 + row) * KDIM + k0 + c16 * 4);
        }
#pragma unroll
        for (int i = 0; i < 4; i++) {           // B: 32 rows x 32 chunks
            int q = tid + i * 256;
            int row = q >> 5, c = q & 31;
            cpa16(bBase + (row * DB_STRIDE + c * 4) * 4,
                  Bc + (size_t)(k0 + row) * NTOTP + n0 + c * 4);
        }
    };

    float acc[4][4][4];
#pragma unroll
    for (int i = 0; i < 4; i++)
#pragma unroll
        for (int j = 0; j < 4; j++)
#pragma unroll
            for (int r = 0; r < 4; r++) acc[i][j][r] = 0.f;

    const int ITERS = KDIM / 32;   // 72
    load_stage(0, 0);
    cpa_commit();
    load_stage(1, 32);
    cpa_commit();

    int rc = 0, rw = 2;
    for (int it = 0; it < ITERS; ++it) {
        cpa_wait1();
        __syncthreads();

        const float* A0 = &sAd[rc * 128 * DA_STRIDE];
        const float* B0 = &sBd[rc * 32 * DB_STRIDE];
#pragma unroll
        for (int ks = 0; ks < 4; ks++) {
            int kb = ks * 8;
            uint32_t af[4][4];
#pragma unroll
            for (int mt = 0; mt < 4; mt++) {
                int m = warpM * 64 + mt * 16 + g;
                af[mt][0] = __float_as_uint(A0[m * DA_STRIDE + kb + t]);
                af[mt][1] = __float_as_uint(A0[(m + 8) * DA_STRIDE + kb + t]);
                af[mt][2] = __float_as_uint(A0[m * DA_STRIDE + kb + t + 4]);
                af[mt][3] = __float_as_uint(A0[(m + 8) * DA_STRIDE + kb + t + 4]);
            }
            uint32_t bf[4][2];
#pragma unroll
            for (int nt = 0; nt < 4; nt++) {
                int n = warpN * 32 + nt * 8 + g;
                bf[nt][0] = __float_as_uint(B0[(kb + t) * DB_STRIDE + n]);
                bf[nt][1] = __float_as_uint(B0[(kb + t + 4) * DB_STRIDE + n]);
            }
#pragma unroll
            for (int mt = 0; mt < 4; mt++)
#pragma unroll
                for (int nt = 0; nt < 4; nt++)
                    mma_tf32(acc[mt][nt][0], acc[mt][nt][1], acc[mt][nt][2], acc[mt][nt][3],
                             af[mt][0], af[mt][1], af[mt][2], af[mt][3],
                             bf[nt][0], bf[nt][1]);
        }

        if (it + 2 < ITERS) load_stage(rw, (it + 2) * 32);
        cpa_commit();
        rc = (rc == 2) ? 0 : rc + 1;
        rw = (rw == 2) ? 0 : rw + 1;
    }

#pragma unroll
    for (int mt = 0; mt < 4; mt++) {
        int m = m0 + warpM * 64 + mt * 16 + g;
        float* r0 = out + ((size_t)bb * C + m) * Nsp;
        float* r1 = out + ((size_t)bb * C + m + 8) * Nsp;
#pragma unroll
        for (int nt = 0; nt < 4; nt++) {
            int n = nl0 + warpN * 32 + nt * 8 + t * 2;
            if (n < Nsp) {
                r0[n] = acc[mt][nt][0];
                r1[n] = acc[mt][nt][2];
                if (n + 1 < Nsp) {
                    r0[n + 1] = acc[mt][nt][1];
                    r1[n + 1] = acc[mt][nt][3];
                }
            }
        }
    }
}

// ---------------------------------------------------------------------------
extern "C" void kernel_launch(void* const* d_in, const int* in_sizes, int n_in,
                              void* d_out, int out_size) {
    const float *Z[3], *X[3], *OW[3], *OB[3], *DW[3], *G[3];
    int nz = 0, nx = 0, nw = 0, nb = 0, nd = 0, ng = 0;
    for (int i = 0; i < n_in; i++) {
        switch (in_sizes[i]) {
            case 1843200: Z[nz++]  = (const float*)d_in[i]; break;
            case 7872512: X[nx++]  = (const float*)d_in[i]; break;
            case 41472:   OW[nw++] = (const float*)d_in[i]; break;
            case 18:      OB[nb++] = (const float*)d_in[i]; break;
            case 589824:  DW[nd++] = (const float*)d_in[i]; break;
            case 1:       G[ng++]  = (const float*)d_in[i]; break;
            default: break;
        }
    }

    float *attnA, *attnB, *featZ, *featX, *off4x, *off4z, *colb, *wrb;
    float *hix, *lox, *hiz, *loz;
    cudaGetSymbolAddress((void**)&attnA, g_attnA);
    cudaGetSymbolAddress((void**)&attnB, g_attnB);
    cudaGetSymbolAddress((void**)&featZ, g_featZ);
    cudaGetSymbolAddress((void**)&featX, g_featX);
    cudaGetSymbolAddress((void**)&off4x, g_off4x);
    cudaGetSymbolAddress((void**)&off4z, g_off4z);
    cudaGetSymbolAddress((void**)&colb,  g_col);
    cudaGetSymbolAddress((void**)&wrb,   g_wr);
    cudaGetSymbolAddress((void**)&hix,   g_hix);
    cudaGetSymbolAddress((void**)&lox,   g_lox);
    cudaGetSymbolAddress((void**)&hiz,   g_hiz);
    cudaGetSymbolAddress((void**)&loz,   g_loz);

    cudaFuncSetAttribute(dconv_mma_kernel,
                         cudaFuncAttributeMaxDynamicSharedMemorySize, DCONV_SMEM);
    cudaFuncSetAttribute(camuse_mma_kernel,
                         cudaFuncAttributeMaxDynamicSharedMemorySize, CAM_SMEM);

    float* outZ = (float*)d_out;
    float* outX = outZ + (size_t)3 * B * C * NZ;

    for (int i = 0; i < 3; i++) {
        splitf_kernel<<<dim3(CDIV(KPX, 256), 2 * B * C), 256>>>(X[i], Z[i],
                                                                hix, lox, hiz, loz);
        gram_mma3_kernel<<<dim3(2, 2, 64), 256>>>(hix, lox, hiz, loz, attnB, attnA);
        attn_softmax_kernel<<<2 * B * C, 256>>>(attnB, attnA);
        camuse_mma_kernel<<<dim3(8, 2, 64), 256, CAM_SMEM>>>(attnA, attnB, hix, hiz,
                                                             X[i], Z[i],
                                                             featX, featZ, G[i]);
        wround_kernel<<<CDIV(256 * KDIM, 256), 256>>>(DW[i], wrb, 256 * KDIM);
        offconv_chunk_kernel<<<dim3(8, 8, 64), 128>>>(featX, featZ, OW[i], off4x, off4z);
        sample_kernel<<<dim3(8, 18, 64), 128>>>(featX, featZ, off4x, off4z, OB[i], colb);
        dconv_mma_kernel<<<dim3(2, NTOTP / 128), 256, DCONV_SMEM>>>(wrb, colb,
                                                        outZ + (size_t)i * B * C * NZ,
                                                        outX + (size_t)i * B * C * NX);
    }
    (void)out_size;
}

// round 16
// speedup vs baseline: 2.0151x; 1.0758x over previous
#include <cuda_runtime.h>
#include <math.h>
#include <stdint.h>

#define CDIV(a,b) (((a)+(b)-1)/(b))

static const int B  = 32;
static const int C  = 256;
static const int NZ = 225;   // 15*15
static const int NX = 961;   // 31*31
static const int KDIM = 2304; // C*9

static const int KPX = 976;
static const int KPZ = 240;
static const int NPAD_Z = 256,  SH_Z = 8;
static const int NPAD_X = 1024, SH_X = 10;
static const int ZCOLS = 32 * 256;   // 8192
static const int XCOLS = 32 * 1024;  // 32768
static const int NTOTP = ZCOLS + XCOLS;  // 40960

// per-scale strides
#define ATTN_S  (32 * 256 * 256)
#define FEATZ_S (32 * 256 * 225)
#define FEATX_S (32 * 256 * 961)
#define OFF4X_S (8 * 32 * 18 * 961)
#define OFF4Z_S (8 * 32 * 18 * 225)
#define COL_S   ((size_t)2304 * 40960)
#define WR_S    (256 * 2304)
#define HIX_S   (32 * 256 * 976)
#define HIZ_S   (32 * 256 * 240)

// ---------------- scratch (device globals; no cudaMalloc allowed) ----------
__device__ float g_attnA[3 * ATTN_S];
__device__ float g_attnB[3 * ATTN_S];
__device__ float g_featZ[3 * FEATZ_S];
__device__ float g_featX[3 * FEATX_S];
__device__ float g_off4x[3 * OFF4X_S];
__device__ float g_off4z[3 * OFF4Z_S];
__device__ float g_col  [3 * COL_S];        // 1.13 GB merged im2col
__device__ float g_wr   [3 * WR_S];
__device__ float g_hix  [3 * HIX_S];
__device__ float g_lox  [3 * HIX_S];
__device__ float g_hiz  [3 * HIZ_S];
__device__ float g_loz  [3 * HIZ_S];

// ======================= PTX helpers =======================================
__device__ __forceinline__ uint32_t smem_u32(const void* p) {
    uint32_t a;
    asm("{ .reg .u64 t; cvta.to.shared.u64 t, %1; cvt.u32.u64 %0, t; }" : "=r"(a) : "l"(p));
    return a;
}
__device__ __forceinline__ void cpa16(uint32_t dst, const void* src) {
    asm volatile("cp.async.cg.shared.global [%0], [%1], 16;" :: "r"(dst), "l"(src));
}
__device__ __forceinline__ void cpa16z(uint32_t dst, const void* src, int bytes) {
    asm volatile("cp.async.cg.shared.global [%0], [%1], 16, %2;"
                 :: "r"(dst), "l"(src), "r"(bytes));
}
__device__ __forceinline__ void cpa_commit() {
    asm volatile("cp.async.commit_group;" ::: "memory");
}
__device__ __forceinline__ void cpa_wait1() {
    asm volatile("cp.async.wait_group 1;" ::: "memory");
}
__device__ __forceinline__ void cpa_wait2() {
    asm volatile("cp.async.wait_group 2;" ::: "memory");
}
__device__ __forceinline__ float round_tf32(float v) {
    uint32_t r;
    asm("cvt.rna.tf32.f32 %0, %1;" : "=r"(r) : "f"(v));
    return __uint_as_float(r);
}
__device__ __forceinline__ void mma_tf32(float& c0, float& c1, float& c2, float& c3,
                                         uint32_t a0, uint32_t a1, uint32_t a2, uint32_t a3,
                                         uint32_t b0, uint32_t b1) {
    asm volatile(
        "mma.sync.aligned.m16n8k8.row.col.f32.tf32.tf32.f32 "
        "{%0,%1,%2,%3},{%4,%5,%6,%7},{%8,%9},{%0,%1,%2,%3};"
        : "+f"(c0), "+f"(c1), "+f"(c2), "+f"(c3)
        : "r"(a0), "r"(a1), "r"(a2), "r"(a3), "r"(b0), "r"(b1));
}
__device__ __forceinline__ const float* pick3(int s, const float* p0,
                                              const float* p1, const float* p2) {
    return (s == 0) ? p0 : ((s == 1) ? p1 : p2);
}

// ---------------------------------------------------------------------------
// merged tf32 split: grid (4, 2*B*C, 3)
// ---------------------------------------------------------------------------
__global__ __launch_bounds__(256) void splitf_kernel(const float* __restrict__ X0,
                                                     const float* __restrict__ X1,
                                                     const float* __restrict__ X2,
                                                     const float* __restrict__ Z0,
                                                     const float* __restrict__ Z1,
                                                     const float* __restrict__ Z2,
                                                     float* __restrict__ hiX,
                                                     float* __restrict__ loX,
                                                     float* __restrict__ hiZ,
                                                     float* __restrict__ loZ) {
    int s = blockIdx.z;
    int y = blockIdx.y;
    const float* in; float* hi; float* lo; int K, Kpad, bc;
    if (y < B * C) {
        in = pick3(s, X0, X1, X2);
        hi = hiX + (size_t)s * HIX_S; lo = loX + (size_t)s * HIX_S;
        K = NX; Kpad = KPX; bc = y;
    } else {
        in = pick3(s, Z0, Z1, Z2);
        hi = hiZ + (size_t)s * HIZ_S; lo = loZ + (size_t)s * HIZ_S;
        K = NZ; Kpad = KPZ; bc = y - B * C;
    }
    int k = blockIdx.x * 256 + threadIdx.x;
    if (k >= Kpad) return;
    float v = (k < K) ? in[(size_t)bc * K + k] : 0.f;
    float h = round_tf32(v);
    size_t o = (size_t)bc * Kpad + k;
    hi[o] = h;
    lo[o] = round_tf32(v - h);
}

// ---------------------------------------------------------------------------
// merged gram via 3xTF32: grid (2,2,192); 3-stage cp.async ring
// ---------------------------------------------------------------------------
__global__ __launch_bounds__(256) void gram_mma3_kernel(const float* __restrict__ hiXb,
                                                        const float* __restrict__ loXb,
                                                        const float* __restrict__ hiZb,
                                                        const float* __restrict__ loZb,
                                                        float* __restrict__ Exb,
                                                        float* __restrict__ Ezb) {
    __shared__ float Ah[3][1536], Al[3][1536], Bh[3][1536], Bl[3][1536];
    int s = blockIdx.z >> 6;
    int bz = blockIdx.z & 63;
    const float* hi; const float* lo; float* E; int Kpad, b;
    if (bz < 32) {
        hi = hiXb + (size_t)s * HIX_S; lo = loXb + (size_t)s * HIX_S;
        E = Exb + (size_t)s * ATTN_S; Kpad = KPX; b = bz;
    } else {
        hi = hiZb + (size_t)s * HIZ_S; lo = loZb + (size_t)s * HIZ_S;
        E = Ezb + (size_t)s * ATTN_S; Kpad = KPZ; b = bz - 32;
    }
    int c0 = blockIdx.y * 128, d0 = blockIdx.x * 128;
    const size_t fb = (size_t)b * C * Kpad;
    int tid = threadIdx.x;
    int wid = tid >> 5, lane = tid & 31;
    int g = lane >> 2, t = lane & 3;
    int warpM = wid >> 2, warpN = wid & 3;

    uint32_t ahU = smem_u32(&Ah[0][0]);
    uint32_t alU = smem_u32(&Al[0][0]);
    uint32_t bhU = smem_u32(&Bh[0][0]);
    uint32_t blU = smem_u32(&Bl[0][0]);

    int lrow = tid >> 1, lhalf = tid & 1;
    auto load_stage = [&](int stg, int k0) {
        uint32_t doff = stg * 6144 + (lrow * 12 + lhalf * 4) * 4;
        const size_t sA = fb + (size_t)(c0 + lrow) * Kpad + k0 + lhalf * 4;
        const size_t sB = fb + (size_t)(d0 + lrow) * Kpad + k0 + lhalf * 4;
        cpa16(ahU + doff, hi + sA);
        cpa16(alU + doff, lo + sA);
        cpa16(bhU + doff, hi + sB);
        cpa16(blU + doff, lo + sB);
    };

    float acc[4][4][4];
#pragma unroll
    for (int i = 0; i < 4; i++)
#pragma unroll
        for (int j = 0; j < 4; j++)
#pragma unroll
            for (int r = 0; r < 4; r++) acc[i][j][r] = 0.f;

    const int ITERS = Kpad / 8;
    load_stage(0, 0);
    cpa_commit();
    load_stage(1, 8);
    cpa_commit();

    int rc = 0, rw = 2;
    for (int it = 0; it < ITERS; it++) {
        cpa_wait1();
        __syncthreads();

        const float* A0h = &Ah[rc][0];
        const float* A0l = &Al[rc][0];
        const float* B0h = &Bh[rc][0];
        const float* B0l = &Bl[rc][0];

        uint32_t ah[4][4], al[4][4];
#pragma unroll
        for (int mt = 0; mt < 4; mt++) {
            int m = warpM * 64 + mt * 16 + g;
            ah[mt][0] = __float_as_uint(A0h[m * 12 + t]);
            ah[mt][1] = __float_as_uint(A0h[(m + 8) * 12 + t]);
            ah[mt][2] = __float_as_uint(A0h[m * 12 + t + 4]);
            ah[mt][3] = __float_as_uint(A0h[(m + 8) * 12 + t + 4]);
            al[mt][0] = __float_as_uint(A0l[m * 12 + t]);
            al[mt][1] = __float_as_uint(A0l[(m + 8) * 12 + t]);
            al[mt][2] = __float_as_uint(A0l[m * 12 + t + 4]);
            al[mt][3] = __float_as_uint(A0l[(m + 8) * 12 + t + 4]);
        }
        uint32_t bh[4][2], bl[4][2];
#pragma unroll
        for (int nt = 0; nt < 4; nt++) {
            int n = warpN * 32 + nt * 8 + g;
            bh[nt][0] = __float_as_uint(B0h[n * 12 + t]);
            bh[nt][1] = __float_as_uint(B0h[n * 12 + t + 4]);
            bl[nt][0] = __float_as_uint(B0l[n * 12 + t]);
            bl[nt][1] = __float_as_uint(B0l[n * 12 + t + 4]);
        }
#pragma unroll
        for (int mt = 0; mt < 4; mt++)
#pragma unroll
            for (int nt = 0; nt < 4; nt++) {
                mma_tf32(acc[mt][nt][0], acc[mt][nt][1], acc[mt][nt][2], acc[mt][nt][3],
                         ah[mt][0], ah[mt][1], ah[mt][2], ah[mt][3],
                         bh[nt][0], bh[nt][1]);
                mma_tf32(acc[mt][nt][0], acc[mt][nt][1], acc[mt][nt][2], acc[mt][nt][3],
                         ah[mt][0], ah[mt][1], ah[mt][2], ah[mt][3],
                         bl[nt][0], bl[nt][1]);
                mma_tf32(acc[mt][nt][0], acc[mt][nt][1], acc[mt][nt][2], acc[mt][nt][3],
                         al[mt][0], al[mt][1], al[mt][2], al[mt][3],
                         bh[nt][0], bh[nt][1]);
            }

        if (it + 2 < ITERS) load_stage(rw, (it + 2) * 8);
        cpa_commit();
        rc = (rc == 2) ? 0 : rc + 1;
        rw = (rw == 2) ? 0 : rw + 1;
    }

    float* Eb = E + (size_t)b * C * C;
#pragma unroll
    for (int mt = 0; mt < 4; mt++) {
        int m = c0 + warpM * 64 + mt * 16 + g;
#pragma unroll
        for (int nt = 0; nt < 4; nt++) {
            int n = d0 + warpN * 32 + nt * 8 + t * 2;
            Eb[(size_t)m * C + n]           = acc[mt][nt][0];
            Eb[(size_t)m * C + n + 1]       = acc[mt][nt][1];
            Eb[(size_t)(m + 8) * C + n]     = acc[mt][nt][2];
            Eb[(size_t)(m + 8) * C + n + 1] = acc[mt][nt][3];
        }
    }
}

// ---------------------------------------------------------------------------
// merged softmax: grid 3*2*B*C (49152)
// ---------------------------------------------------------------------------
__global__ __launch_bounds__(256) void attn_softmax_kernel(float* __restrict__ Exb,
                                                           float* __restrict__ Ezb) {
    int row = blockIdx.x;
    int s = row >> 14;                 // 2*B*C = 16384
    int r = row & 16383;
    float* e = (r < B * C) ? Exb + (size_t)s * ATTN_S + (size_t)r * 256
                           : Ezb + (size_t)s * ATTN_S + (size_t)(r - B * C) * 256;
    int t = threadIdx.x;
    int warp = t >> 5, lane = t & 31;
    __shared__ float sm[16];
    float v = e[t];
    float m = v;
#pragma unroll
    for (int q = 16; q > 0; q >>= 1) m = fminf(m, __shfl_xor_sync(0xffffffffu, m, q));
    if (lane == 0) sm[warp] = m;
    __syncthreads();
    float emin = fminf(fminf(fminf(sm[0], sm[1]), fminf(sm[2], sm[3])),
                       fminf(fminf(sm[4], sm[5]), fminf(sm[6], sm[7])));
    float p = expf(emin - v);
    float sum = p;
#pragma unroll
    for (int q = 16; q > 0; q >>= 1) sum += __shfl_xor_sync(0xffffffffu, sum, q);
    if (lane == 0) sm[8 + warp] = sum;
    __syncthreads();
    float tot = (sm[8] + sm[9]) + (sm[10] + sm[11]) + (sm[12] + sm[13]) + (sm[14] + sm[15]);
    e[t] = p / tot;
}

// ---------------------------------------------------------------------------
// merged cam_use via tf32 MMA: grid (8,2,192); BK=16, 4-stage dynamic ring
// ---------------------------------------------------------------------------
#define CAM_SMEM (4 * (2560 + 2176) * 4)   // 75776 B

__global__ __launch_bounds__(256) void camuse_mma_kernel(const float* __restrict__ attnAb,
                                                         const float* __restrict__ attnBb,
                                                         const float* __restrict__ hiXb,
                                                         const float* __restrict__ hiZb,
                                                         const float* __restrict__ X0,
                                                         const float* __restrict__ X1,
                                                         const float* __restrict__ X2,
                                                         const float* __restrict__ Z0,
                                                         const float* __restrict__ Z1,
                                                         const float* __restrict__ Z2,
                                                         float* __restrict__ featXb,
                                                         float* __restrict__ featZb,
                                                         const float* __restrict__ G0,
                                                         const float* __restrict__ G1,
                                                         const float* __restrict__ G2) {
    int s = blockIdx.z >> 6;
    int bz = blockIdx.z & 63;
    const float* A; const float* hiF; const float* F; float* O; int N, Kpad, b;
    if (bz < 32) {
        A = attnAb + (size_t)s * ATTN_S;
        hiF = hiXb + (size_t)s * HIX_S;
        F = pick3(s, X0, X1, X2);
        O = featXb + (size_t)s * FEATX_S;
        N = NX; Kpad = KPX; b = bz;
    } else {
        if (blockIdx.x >= 2) return;
        A = attnBb + (size_t)s * ATTN_S;
        hiF = hiZb + (size_t)s * HIZ_S;
        F = pick3(s, Z0, Z1, Z2);
        O = featZb + (size_t)s * FEATZ_S;
        N = NZ; Kpad = KPZ; b = bz - 32;
    }
    const float* gamma = pick3(s, G0, G1, G2);
    extern __shared__ float csm[];
    float* sAd = csm;
    float* sBd = csm + 4 * 2560;
    int m0 = blockIdx.y * 128, n0 = blockIdx.x * 128;
    const float* Ab = A + (size_t)b * C * C;
    const float* Fb = F + (size_t)b * C * N;
    const float* Hb = hiF + (size_t)b * C * Kpad;
    int tid = threadIdx.x;
    int wid = tid >> 5, lane = tid & 31;
    int g = lane >> 2, t = lane & 3;
    int warpM = wid >> 2, warpN = wid & 3;

    uint32_t sAu = smem_u32(sAd);
    uint32_t sBu = smem_u32(sBd);
    int bcc = tid & 31;
    int bcol = n0 + bcc * 4;
    int brem = Kpad - bcol;
    int bbytes = (brem <= 0) ? 0 : ((brem >= 4) ? 16 : brem * 4);

    auto load_stage = [&](int stg, int k0) {
#pragma unroll
        for (int i = 0; i < 2; i++) {
            int q = tid + i * 256;
            int row = q >> 2, c16 = q & 3;
            cpa16(sAu + stg * 10240 + (row * 20 + c16 * 4) * 4,
                  Ab + (size_t)(m0 + row) * C + k0 + c16 * 4);
        }
#pragma unroll
        for (int i = 0; i < 2; i++) {
            int q = tid + i * 256;
            int row = q >> 5;
            const float* src = (bbytes > 0) ? Hb + (size_t)(k0 + row) * Kpad + bcol : Hb;
            cpa16z(sBu + stg * 8704 + (row * 136 + bcc * 4) * 4, src, bbytes);
        }
    };

    float acc[4][4][4];
#pragma unroll
    for (int i = 0; i < 4; i++)
#pragma unroll
        for (int j = 0; j < 4; j++)
#pragma unroll
            for (int r = 0; r < 4; r++) acc[i][j][r] = 0.f;

    const int ITERS = C / 16;   // 16
    load_stage(0, 0);
    cpa_commit();
    load_stage(1, 16);
    cpa_commit();
    load_stage(2, 32);
    cpa_commit();

    int rc = 0, rw = 3;
    for (int it = 0; it < ITERS; it++) {
        cpa_wait2();
        __syncthreads();

        const float* A0 = &sAd[rc * 2560];
        const float* B0 = &sBd[rc * 2176];
#pragma unroll
        for (int ks = 0; ks < 2; ks++) {
            int kb = ks * 8;
            uint32_t af[4][4];
#pragma unroll
            for (int mt = 0; mt < 4; mt++) {
                int m = warpM * 64 + mt * 16 + g;
                af[mt][0] = __float_as_uint(A0[m * 20 + kb + t]);
                af[mt][1] = __float_as_uint(A0[(m + 8) * 20 + kb + t]);
                af[mt][2] = __float_as_uint(A0[m * 20 + kb + t + 4]);
                af[mt][3] = __float_as_uint(A0[(m + 8) * 20 + kb + t + 4]);
            }
            uint32_t bf[4][2];
#pragma unroll
            for (int nt = 0; nt < 4; nt++) {
                int n = warpN * 32 + nt * 8 + g;
                bf[nt][0] = __float_as_uint(B0[(kb + t) * 136 + n]);
                bf[nt][1] = __float_as_uint(B0[(kb + t + 4) * 136 + n]);
            }
#pragma unroll
            for (int mt = 0; mt < 4; mt++)
#pragma unroll
                for (int nt = 0; nt < 4; nt++)
                    mma_tf32(acc[mt][nt][0], acc[mt][nt][1], acc[mt][nt][2], acc[mt][nt][3],
                             af[mt][0], af[mt][1], af[mt][2], af[mt][3],
                             bf[nt][0], bf[nt][1]);
        }

        if (it + 3 < ITERS) load_stage(rw, (it + 3) * 16);
        cpa_commit();
        rc = (rc + 1) & 3;
        rw = (rw + 1) & 3;
    }

    float gm = gamma[0];
#pragma unroll
    for (int mt = 0; mt < 4; mt++) {
        int m = m0 + warpM * 64 + mt * 16 + g;
#pragma unroll
        for (int nt = 0; nt < 4; nt++) {
            int n = n0 + warpN * 32 + nt * 8 + t * 2;
            if (n < N) {
                O[((size_t)b * C + m) * N + n] = gm * acc[mt][nt][0] + Fb[(size_t)m * N + n];
                O[((size_t)b * C + m + 8) * N + n] = gm * acc[mt][nt][2] + Fb[(size_t)(m + 8) * N + n];
                if (n + 1 < N) {
                    O[((size_t)b * C + m) * N + n + 1] = gm * acc[mt][nt][1] + Fb[(size_t)m * N + n + 1];
                    O[((size_t)b * C + m + 8) * N + n + 1] = gm * acc[mt][nt][3] + Fb[(size_t)(m + 8) * N + n + 1];
                }
            }
        }
    }
}

// ---------------------------------------------------------------------------
// merged offset conv, channel-chunked partials.  grid (8, 8, 192)
// ---------------------------------------------------------------------------
__global__ __launch_bounds__(128) void offconv_chunk_kernel(const float* __restrict__ featXb,
                                                            const float* __restrict__ featZb,
                                                            const float* __restrict__ W0,
                                                            const float* __restrict__ W1,
                                                            const float* __restrict__ W2,
                                                            float* __restrict__ off4xb,
                                                            float* __restrict__ off4zb) {
    int s = blockIdx.z >> 6;
    int bz = blockIdx.z & 63;
    const float* feat; float* off4; int H, W, b;
    if (bz < 32) {
        feat = featXb + (size_t)s * FEATX_S; off4 = off4xb + (size_t)s * OFF4X_S;
        H = 31; W = 31; b = bz;
    } else {
        if (blockIdx.x >= 2) return;
        feat = featZb + (size_t)s * FEATZ_S; off4 = off4zb + (size_t)s * OFF4Z_S;
        H = 15; W = 15; b = bz - 32;
    }
    const float* woff = pick3(s, W0, W1, W2);
    __shared__ float sw[32 * 9 * 20];
    int chunk = blockIdx.y;
    int c0 = chunk * 32;
    for (int i = threadIdx.x; i < 32 * 9 * 18; i += 128) {
        int ch = i % 18;
        int rem = i / 18;
        int tap = rem % 9, cc = rem / 9;
        sw[(cc * 9 + tap) * 20 + ch] = woff[(size_t)ch * 2304 + (c0 + cc) * 9 + tap];
    }
    __syncthreads();
    int N = H * W;
    int n = blockIdx.x * 128 + threadIdx.x;
    if (n >= N) return;
    int h = n / W, w = n % W;
    int idx[9];
#pragma unroll
    for (int tap = 0; tap < 9; tap++) {
        int y = h + tap / 3 - 1, x = w + tap % 3 - 1;
        idx[tap] = ((unsigned)y < (unsigned)H && (unsigned)x < (unsigned)W) ? y * W + x : -1;
    }
    float acc[18];
#pragma unroll
    for (int ch = 0; ch < 18; ch++) acc[ch] = 0.f;

    const float* fb = feat + ((size_t)b * C + c0) * N;
    for (int cc = 0; cc < 32; cc++) {
        const float* fc = fb + (size_t)cc * N;
        float f[9];
#pragma unroll
        for (int tap = 0; tap < 9; tap++) f[tap] = (idx[tap] >= 0) ? fc[idx[tap]] : 0.f;
        const float* wp = sw + cc * 180;
#pragma unroll
        for (int tap = 0; tap < 9; tap++) {
            const float* wt = wp + tap * 20;
            float fv = f[tap];
#pragma unroll
            for (int ch = 0; ch < 18; ch++) acc[ch] += wt[ch] * fv;
        }
    }
    float* op = off4 + (((size_t)chunk * B + b) * 18) * N + n;
#pragma unroll
    for (int ch = 0; ch < 18; ch++) op[(size_t)ch * N] = acc[ch];
}

// ---------------------------------------------------------------------------
// merged bilinear sampling -> combined im2col.  grid (8, 18, 192)
// ---------------------------------------------------------------------------
__global__ __launch_bounds__(128) void sample_kernel(const float* __restrict__ featXb,
                                                     const float* __restrict__ featZb,
                                                     const float* __restrict__ off4xb,
                                                     const float* __restrict__ off4zb,
                                                     const float* __restrict__ Bo0,
                                                     const float* __restrict__ Bo1,
                                                     const float* __restrict__ Bo2,
                                                     float* __restrict__ colb) {
    int s = blockIdx.z >> 6;
    int bz = blockIdx.z & 63;
    const float* feat; const float* off4; int H, W, b, Npad, base;
    if (bz < 32) {
        feat = featXb + (size_t)s * FEATX_S; off4 = off4xb + (size_t)s * OFF4X_S;
        H = 31; W = 31; b = bz; Npad = NPAD_X; base = ZCOLS;
    } else {
        if (blockIdx.x >= 2) return;
        feat = featZb + (size_t)s * FEATZ_S; off4 = off4zb + (size_t)s * OFF4Z_S;
        H = 15; W = 15; b = bz - 32; Npad = NPAD_Z; base = 0;
    }
    const float* boff = pick3(s, Bo0, Bo1, Bo2);
    float* col = colb + (size_t)s * COL_S;
    int N = H * W;
    int k = blockIdx.y % 9;
    int c0 = (blockIdx.y / 9) * 128;
    int n = blockIdx.x * 128 + threadIdx.x;
    if (n >= N) return;
    int h = n / W, w = n % W;
    int ky = k / 3, kx = k % 3;

    const size_t cst = (size_t)B * 18 * N;
    const float* p = off4 + ((size_t)b * 18 + 2 * k) * N + n;
    float oy = __ldg(&boff[2 * k]);
    float ox = __ldg(&boff[2 * k + 1]);
#pragma unroll
    for (int q = 0; q < 8; q++) {
        oy += p[(size_t)q * cst];
        ox += p[(size_t)q * cst + N];
    }

    float py = (float)(h + ky - 1) + oy;
    float px = (float)(w + kx - 1) + ox;
    float y0f = floorf(py), x0f = floorf(px);
    float ly = py - y0f, lx = px - x0f;
    float Hm1 = (float)(H - 1), Wm1 = (float)(W - 1);

    float vy0 = (y0f >= 0.f && y0f <= Hm1) ? (1.f - ly) : 0.f;
    float vy1 = (y0f + 1.f >= 0.f && y0f + 1.f <= Hm1) ? ly : 0.f;
    float vx0 = (x0f >= 0.f && x0f <= Wm1) ? (1.f - lx) : 0.f;
    float vx1 = (x0f + 1.f >= 0.f && x0f + 1.f <= Wm1) ? lx : 0.f;
    int y0 = (int)fminf(fmaxf(y0f, 0.f), Hm1);
    int y1 = (int)fminf(fmaxf(y0f + 1.f, 0.f), Hm1);
    int x0 = (int)fminf(fmaxf(x0f, 0.f), Wm1);
    int x1 = (int)fminf(fmaxf(x0f + 1.f, 0.f), Wm1);

    int i00 = y0 * W + x0, i01 = y0 * W + x1, i10 = y1 * W + x0, i11 = y1 * W + x1;
    float w00 = vy0 * vx0, w01 = vy0 * vx1, w10 = vy1 * vx0, w11 = vy1 * vx1;

    const float* fb = feat + ((size_t)b * C + c0) * N;
    float* cp = col + (size_t)(c0 * 9 + k) * NTOTP + base + (size_t)b * Npad + n;
    const size_t cstride = (size_t)9 * NTOTP;
    for (int c = 0; c < 128; c++) {
        const float* fc = fb + (size_t)c * N;
        float v = w00 * fc[i00] + w01 * fc[i01] + w10 * fc[i10] + w11 * fc[i11];
        cp[(size_t)c * cstride] = round_tf32(v);
    }
}

// ---------------------------------------------------------------------------
// merged wround: grid (CDIV(WR_S,256), 3)
// ---------------------------------------------------------------------------
__global__ __launch_bounds__(256) void wround_kernel(const float* __restrict__ D0,
                                                     const float* __restrict__ D1,
                                                     const float* __restrict__ D2,
                                                     float* __restrict__ outb) {
    int s = blockIdx.y;
    const float* in = pick3(s, D0, D1, D2);
    int i = blockIdx.x * 256 + threadIdx.x;
    if (i < WR_S) outb[(size_t)s * WR_S + i] = round_tf32(in[i]);
}

// ---------------------------------------------------------------------------
// merged tf32 mma GEMM: grid (2, 320, 3); BK=32, 3-stage dynamic ring
// ---------------------------------------------------------------------------
#define DA_STRIDE 36
#define DB_STRIDE 136
#define DCONV_SMEM (3 * (128 * DA_STRIDE + 32 * DB_STRIDE) * 4)   // 107520 B

__global__ __launch_bounds__(256) void dconv_mma_kernel(const float* __restrict__ Wmb,
                                                        const float* __restrict__ Bcb,
                                                        float* __restrict__ outZb,
                                                        float* __restrict__ outXb) {
    extern __shared__ float dsm[];
    float* sAd = dsm;
    float* sBd = dsm + 3 * 128 * DA_STRIDE;

    int sidx = blockIdx.z;
    const float* Wm = Wmb + (size_t)sidx * WR_S;
    const float* Bc = Bcb + (size_t)sidx * COL_S;

    int tid = threadIdx.x;
    int wid = tid >> 5, lane = tid & 31;
    int g = lane >> 2, t = lane & 3;
    int warpM = wid >> 2;
    int warpN = wid & 3;

    int m0 = blockIdx.x * 128;
    int n0 = blockIdx.y * 128;

    float* out; int bb, nl0, Nsp;
    if (n0 < ZCOLS) {
        out = outZb + (size_t)sidx * B * C * NZ;
        bb = n0 >> SH_Z; nl0 = n0 & (NPAD_Z - 1); Nsp = NZ;
    } else {
        int nx = n0 - ZCOLS;
        out = outXb + (size_t)sidx * B * C * NX;
        bb = nx >> SH_X; nl0 = nx & (NPAD_X - 1); Nsp = NX;
    }

    uint32_t sAu = smem_u32(sAd);
    uint32_t sBu = smem_u32(sBd);

    auto load_stage = [&](int stg, int k0) {
        uint32_t aBase = sAu + stg * (128 * DA_STRIDE * 4);
        uint32_t bBase = sBu + stg * (32 * DB_STRIDE * 4);
#pragma unroll
        for (int i = 0; i < 4; i++) {
            int q = tid + i * 256;
            int row = q >> 3, c16 = q & 7;
            cpa16(aBase + (row * DA_STRIDE + c16 * 4) * 4,
                  Wm + (size_t)(m0 + row) * KDIM + k0 + c16 * 4);
        }
#pragma unroll
        for (int i = 0; i < 4; i++) {
            int q = tid + i * 256;
            int row = q >> 5, c = q & 31;
            cpa16(bBase + (row * DB_STRIDE + c * 4) * 4,
                  Bc + (size_t)(k0 + row) * NTOTP + n0 + c * 4);
        }
    };

    float acc[4][4][4];
#pragma unroll
    for (int i = 0; i < 4; i++)
#pragma unroll
        for (int j = 0; j < 4; j++)
#pragma unroll
            for (int r = 0; r < 4; r++) acc[i][j][r] = 0.f;

    const int ITERS = KDIM / 32;   // 72
    load_stage(0, 0);
    cpa_commit();
    load_stage(1, 32);
    cpa_commit();

    int rc = 0, rw = 2;
    for (int it = 0; it < ITERS; ++it) {
        cpa_wait1();
        __syncthreads();

        const float* A0 = &sAd[rc * 128 * DA_STRIDE];
        const float* B0 = &sBd[rc * 32 * DB_STRIDE];
#pragma unroll
        for (int ks = 0; ks < 4; ks++) {
            int kb = ks * 8;
            uint32_t af[4][4];
#pragma unroll
            for (int mt = 0; mt < 4; mt++) {
                int m = warpM * 64 + mt * 16 + g;
                af[mt][0] = __float_as_uint(A0[m * DA_STRIDE + kb + t]);
                af[mt][1] = __float_as_uint(A0[(m + 8) * DA_STRIDE + kb + t]);
                af[mt][2] = __float_as_uint(A0[m * DA_STRIDE + kb + t + 4]);
                af[mt][3] = __float_as_uint(A0[(m + 8) * DA_STRIDE + kb + t + 4]);
            }
            uint32_t bf[4][2];
#pragma unroll
            for (int nt = 0; nt < 4; nt++) {
                int n = warpN * 32 + nt * 8 + g;
                bf[nt][0] = __float_as_uint(B0[(kb + t) * DB_STRIDE + n]);
                bf[nt][1] = __float_as_uint(B0[(kb + t + 4) * DB_STRIDE + n]);
            }
#pragma unroll
            for (int mt = 0; mt < 4; mt++)
#pragma unroll
                for (int nt = 0; nt < 4; nt++)
                    mma_tf32(acc[mt][nt][0], acc[mt][nt][1], acc[mt][nt][2], acc[mt][nt][3],
                             af[mt][0], af[mt][1], af[mt][2], af[mt][3],
                             bf[nt][0], bf[nt][1]);
        }

        if (it + 2 < ITERS) load_stage(rw, (it + 2) * 32);
        cpa_commit();
        rc = (rc == 2) ? 0 : rc + 1;
        rw = (rw == 2) ? 0 : rw + 1;
    }

#pragma unroll
    for (int mt = 0; mt < 4; mt++) {
        int m = m0 + warpM * 64 + mt * 16 + g;
        float* r0 = out + ((size_t)bb * C + m) * Nsp;
        float* r1 = out + ((size_t)bb * C + m + 8) * Nsp;
#pragma unroll
        for (int nt = 0; nt < 4; nt++) {
            int n = nl0 + warpN * 32 + nt * 8 + t * 2;
            if (n < Nsp) {
                r0[n] = acc[mt][nt][0];
                r1[n] = acc[mt][nt][2];
                if (n + 1 < Nsp) {
                    r0[n + 1] = acc[mt][nt][1];
                    r1[n + 1] = acc[mt][nt][3];
                }
            }
        }
    }
}

// ---------------------------------------------------------------------------
extern "C" void kernel_launch(void* const* d_in, const int* in_sizes, int n_in,
                              void* d_out, int out_size) {
    const float *Z[3], *X[3], *OW[3], *OB[3], *DW[3], *G[3];
    int nz = 0, nx = 0, nw = 0, nb = 0, nd = 0, ng = 0;
    for (int i = 0; i < n_in; i++) {
        switch (in_sizes[i]) {
            case 1843200: Z[nz++]  = (const float*)d_in[i]; break;
            case 7872512: X[nx++]  = (const float*)d_in[i]; break;
            case 41472:   OW[nw++] = (const float*)d_in[i]; break;
            case 18:      OB[nb++] = (const float*)d_in[i]; break;
            case 589824:  DW[nd++] = (const float*)d_in[i]; break;
            case 1:       G[ng++]  = (const float*)d_in[i]; break;
            default: break;
        }
    }

    float *attnA, *attnB, *featZ, *featX, *off4x, *off4z, *colb, *wrb;
    float *hix, *lox, *hiz, *loz;
    cudaGetSymbolAddress((void**)&attnA, g_attnA);
    cudaGetSymbolAddress((void**)&attnB, g_attnB);
    cudaGetSymbolAddress((void**)&featZ, g_featZ);
    cudaGetSymbolAddress((void**)&featX, g_featX);
    cudaGetSymbolAddress((void**)&off4x, g_off4x);
    cudaGetSymbolAddress((void**)&off4z, g_off4z);
    cudaGetSymbolAddress((void**)&colb,  g_col);
    cudaGetSymbolAddress((void**)&wrb,   g_wr);
    cudaGetSymbolAddress((void**)&hix,   g_hix);
    cudaGetSymbolAddress((void**)&lox,   g_lox);
    cudaGetSymbolAddress((void**)&hiz,   g_hiz);
    cudaGetSymbolAddress((void**)&loz,   g_loz);

    cudaFuncSetAttribute(dconv_mma_kernel,
                         cudaFuncAttributeMaxDynamicSharedMemorySize, DCONV_SMEM);
    cudaFuncSetAttribute(camuse_mma_kernel,
                         cudaFuncAttributeMaxDynamicSharedMemorySize, CAM_SMEM);

    float* outZ = (float*)d_out;
    float* outX = outZ + (size_t)3 * B * C * NZ;

    splitf_kernel<<<dim3(CDIV(KPX, 256), 2 * B * C, 3), 256>>>(
        X[0], X[1], X[2], Z[0], Z[1], Z[2], hix, lox, hiz, loz);
    gram_mma3_kernel<<<dim3(2, 2, 192), 256>>>(hix, lox, hiz, loz, attnB, attnA);
    attn_softmax_kernel<<<3 * 2 * B * C, 256>>>(attnB, attnA);
    camuse_mma_kernel<<<dim3(8, 2, 192), 256, CAM_SMEM>>>(
        attnA, attnB, hix, hiz,
        X[0], X[1], X[2], Z[0], Z[1], Z[2],
        featX, featZ, G[0], G[1], G[2]);
    wround_kernel<<<dim3(CDIV(WR_S, 256), 3), 256>>>(DW[0], DW[1], DW[2], wrb);
    offconv_chunk_kernel<<<dim3(8, 8, 192), 128>>>(featX, featZ,
                                                   OW[0], OW[1], OW[2], off4x, off4z);
    sample_kernel<<<dim3(8, 18, 192), 128>>>(featX, featZ, off4x, off4z,
                                             OB[0], OB[1], OB[2], colb);
    dconv_mma_kernel<<<dim3(2, 320, 3), 256, DCONV_SMEM>>>(wrb, colb, outZ, outX);
    (void)out_size;
}